// round 1
// baseline (speedup 1.0000x reference)
#include <cuda_runtime.h>
#include <cuda_bf16.h>

// Problem constants
#define N_SUPPORT 4096
#define N_QUERY   8192
#define IN_DIM    784
#define EMBED     512
#define N_CLASSES 64

typedef unsigned long long u64;

// ---------------- scratch (device globals; no allocation allowed) -----------
__device__ float g_semb[N_SUPPORT * EMBED];
__device__ float g_qemb[N_QUERY * EMBED];
__device__ float g_s2[N_SUPPORT];
__device__ float g_q2[N_QUERY];
__device__ int   g_cls[N_SUPPORT];

// ---------------- packed f32x2 helpers --------------------------------------
__device__ __forceinline__ void fma2(u64& d, u64 a, u64 b, u64 c) {
    asm("fma.rn.f32x2 %0, %1, %2, %3;" : "=l"(d) : "l"(a), "l"(b), "l"(c));
}
__device__ __forceinline__ u64 dup2(float x) {
    u64 r;
    asm("mov.b64 %0, {%1, %1};" : "=l"(r) : "r"(__float_as_uint(x)));
    return r;
}
__device__ __forceinline__ void unpack2(u64 v, float& lo, float& hi) {
    unsigned a, b;
    asm("mov.b64 {%0, %1}, %2;" : "=r"(a), "=r"(b) : "l"(v));
    lo = __uint_as_float(a);
    hi = __uint_as_float(b);
}

// =============================================================================
// Encoder GEMM: out[row][n] = sum_k X[row][k] * W[k][n] + b[n]
// Tile 64 rows x 256 cols, 256 threads, 8x8 per thread (4 packed col-pairs).
// which = 0 -> g_semb, 1 -> g_qemb
// =============================================================================
__global__ __launch_bounds__(256, 2)
void encode_kernel(const float* __restrict__ X,
                   const float* __restrict__ W,
                   const float* __restrict__ b,
                   int which) {
    __shared__ __align__(16) float Xs[16][66];
    __shared__ __align__(16) float Ws[16][258];

    float* out = which ? g_qemb : g_semb;

    const int tid  = threadIdx.x;
    const int rg   = tid >> 5;   // warp id: owns rows rg*8..rg*8+7
    const int lane = tid & 31;   // col pairs: 2*lane + 64*jp
    const int row0 = blockIdx.y * 64;
    const int col0 = blockIdx.x * 256;

    u64 acc[8][4];
#pragma unroll
    for (int i = 0; i < 8; i++)
#pragma unroll
        for (int jp = 0; jp < 4; jp++) acc[i][jp] = 0ull;

    const int KCHUNKS = IN_DIM / 16;  // 49
    for (int kc = 0; kc < KCHUNKS; kc++) {
        const int k0 = kc * 16;
        __syncthreads();
        // load X tile (64x16), transposed into Xs[k][row]
#pragma unroll
        for (int r = 0; r < 4; r++) {
            int idx = tid + 256 * r;
            int k = idx & 15, row = idx >> 4;
            Xs[k][row] = X[(row0 + row) * IN_DIM + k0 + k];
        }
        // load W tile (16x256) into Ws[k][n]
#pragma unroll
        for (int r = 0; r < 16; r++) {
            int idx = tid + 256 * r;
            int n = idx & 255, k = idx >> 8;
            Ws[k][n] = W[(k0 + k) * EMBED + col0 + n];
        }
        __syncthreads();

#pragma unroll
        for (int k = 0; k < 16; k++) {
            u64 qq[8];
#pragma unroll
            for (int i = 0; i < 8; i++) qq[i] = dup2(Xs[k][rg * 8 + i]);
            u64 sv[4];
#pragma unroll
            for (int jp = 0; jp < 4; jp++)
                sv[jp] = *reinterpret_cast<const u64*>(&Ws[k][2 * lane + 64 * jp]);
#pragma unroll
            for (int i = 0; i < 8; i++)
#pragma unroll
                for (int jp = 0; jp < 4; jp++)
                    fma2(acc[i][jp], qq[i], sv[jp], acc[i][jp]);
        }
    }

    // epilogue: add bias, write float2
#pragma unroll
    for (int jp = 0; jp < 4; jp++) {
        int c = col0 + 2 * lane + 64 * jp;
        float2 bv = *reinterpret_cast<const float2*>(&b[c]);
#pragma unroll
        for (int i = 0; i < 8; i++) {
            float x, y;
            unpack2(acc[i][jp], x, y);
            float2 o;
            o.x = x + bv.x;
            o.y = y + bv.y;
            *reinterpret_cast<float2*>(&out[(row0 + rg * 8 + i) * EMBED + c]) = o;
        }
    }
}

// =============================================================================
// Row squared-norms for both embedding matrices: one warp per row.
// =============================================================================
__global__ void norms_kernel() {
    int gw   = (blockIdx.x * blockDim.x + threadIdx.x) >> 5;
    int lane = threadIdx.x & 31;
    if (gw >= N_SUPPORT + N_QUERY) return;
    const float* src;
    float* dst;
    if (gw < N_SUPPORT) {
        src = g_semb + gw * EMBED;
        dst = &g_s2[gw];
    } else {
        src = g_qemb + (gw - N_SUPPORT) * EMBED;
        dst = &g_q2[gw - N_SUPPORT];
    }
    const float4* p = reinterpret_cast<const float4*>(src);
    float s = 0.f;
#pragma unroll
    for (int j = 0; j < 4; j++) {
        float4 v = p[lane + 32 * j];
        s += v.x * v.x + v.y * v.y + v.z * v.z + v.w * v.w;
    }
#pragma unroll
    for (int off = 16; off; off >>= 1) s += __shfl_xor_sync(0xffffffffu, s, off);
    if (lane == 0) *dst = s;
}

// =============================================================================
// One-hot -> class index
// =============================================================================
__global__ void cls_kernel(const float* __restrict__ labels) {
    int i = blockIdx.x * blockDim.x + threadIdx.x;
    if (i >= N_SUPPORT) return;
    int c = 0;
#pragma unroll
    for (int j = 0; j < N_CLASSES; j++)
        if (labels[i * N_CLASSES + j] > 0.5f) c = j;
    g_cls[i] = c;
}

// =============================================================================
// Fused attention kernel.
// One CTA owns 64 query rows; loops over all 4096 supports in tiles of 256.
// dist = -sqrt(max(q2 + s2 - 2 q.s, 0)); p = exp(32 + dist) (safe fixed shift);
// accumulate l[row] and sacc[row][class] (labels are one-hot); normalize.
// =============================================================================
__global__ __launch_bounds__(256, 1)
void fused_attn_kernel(float* __restrict__ out) {
    __shared__ __align__(16) float Qs[16][66];
    __shared__ __align__(16) float Ss[16][258];
    __shared__ float sacc[64][N_CLASSES];
    __shared__ float ls[64];
    __shared__ float q2s[64];

    const int tid  = threadIdx.x;
    const int rg   = tid >> 5;
    const int lane = tid & 31;
    const int row0 = blockIdx.x * 64;

    for (int idx = tid; idx < 64 * N_CLASSES; idx += 256)
        (&sacc[0][0])[idx] = 0.f;
    if (tid < 64) q2s[tid] = g_q2[row0 + tid];

    float l_part[8];
#pragma unroll
    for (int i = 0; i < 8; i++) l_part[i] = 0.f;

    __syncthreads();

    for (int st = 0; st < N_SUPPORT / 256; st++) {
        const int col0 = st * 256;

        u64 acc[8][4];
#pragma unroll
        for (int i = 0; i < 8; i++)
#pragma unroll
            for (int jp = 0; jp < 4; jp++) acc[i][jp] = 0ull;

        // per-tile support norms + class ids for this thread's 8 columns
        float2 s2p[4];
        int clsv[8];
#pragma unroll
        for (int jp = 0; jp < 4; jp++) {
            int c = col0 + 2 * lane + 64 * jp;
            s2p[jp] = *reinterpret_cast<const float2*>(&g_s2[c]);
            clsv[2 * jp]     = g_cls[c];
            clsv[2 * jp + 1] = g_cls[c + 1];
        }

        for (int kc = 0; kc < EMBED / 16; kc++) {
            const int k0 = kc * 16;
            __syncthreads();
            // Q tile 64x16 transposed
#pragma unroll
            for (int r = 0; r < 4; r++) {
                int idx = tid + 256 * r;
                int k = idx & 15, row = idx >> 4;
                Qs[k][row] = g_qemb[(row0 + row) * EMBED + k0 + k];
            }
            // S tile 256x16 transposed
#pragma unroll
            for (int r = 0; r < 16; r++) {
                int idx = tid + 256 * r;
                int k = idx & 15, n = idx >> 4;
                Ss[k][n] = g_semb[(col0 + n) * EMBED + k0 + k];
            }
            __syncthreads();

#pragma unroll
            for (int k = 0; k < 16; k++) {
                u64 qq[8];
#pragma unroll
                for (int i = 0; i < 8; i++) qq[i] = dup2(Qs[k][rg * 8 + i]);
                u64 sv[4];
#pragma unroll
                for (int jp = 0; jp < 4; jp++)
                    sv[jp] = *reinterpret_cast<const u64*>(&Ss[k][2 * lane + 64 * jp]);
#pragma unroll
                for (int i = 0; i < 8; i++)
#pragma unroll
                    for (int jp = 0; jp < 4; jp++)
                        fma2(acc[i][jp], qq[i], sv[jp], acc[i][jp]);
            }
        }
        __syncthreads();

        // epilogue for this support tile
#pragma unroll
        for (int i = 0; i < 8; i++) {
            const float q2v = q2s[rg * 8 + i];
            float lsum = 0.f;
#pragma unroll
            for (int jp = 0; jp < 4; jp++) {
                float qsx, qsy;
                unpack2(acc[i][jp], qsx, qsy);
                float d2x = fmaxf(q2v + s2p[jp].x - 2.f * qsx, 0.f);
                float d2y = fmaxf(q2v + s2p[jp].y - 2.f * qsy, 0.f);
                float dx = __fsqrt_rn(d2x);
                float dy = __fsqrt_rn(d2y);
                float px = __expf(32.0f - dx);
                float py = __expf(32.0f - dy);
                lsum += px + py;
                atomicAdd(&sacc[rg * 8 + i][clsv[2 * jp]], px);
                atomicAdd(&sacc[rg * 8 + i][clsv[2 * jp + 1]], py);
            }
            l_part[i] += lsum;
        }
    }

    // reduce l across lanes (each warp owns its 8 rows exclusively)
#pragma unroll
    for (int i = 0; i < 8; i++) {
        float v = l_part[i];
#pragma unroll
        for (int off = 16; off; off >>= 1) v += __shfl_xor_sync(0xffffffffu, v, off);
        if (lane == 0) ls[rg * 8 + i] = v;
    }
    __syncthreads();

    for (int idx = tid; idx < 64 * N_CLASSES; idx += 256) {
        int r = idx >> 6, c = idx & 63;
        out[(row0 + r) * N_CLASSES + c] = sacc[r][c] / ls[r];
    }
}

// =============================================================================
// Launch
// =============================================================================
extern "C" void kernel_launch(void* const* d_in, const int* in_sizes, int n_in,
                              void* d_out, int out_size) {
    const float* support = (const float*)d_in[0];  // (4096,1,28,28)
    const float* query   = (const float*)d_in[1];  // (8192,1,28,28)
    const float* labels  = (const float*)d_in[2];  // (4096,64) one-hot
    const float* W       = (const float*)d_in[3];  // (784,512)
    const float* b       = (const float*)d_in[4];  // (512,)
    float* out = (float*)d_out;                    // (8192,64)

    encode_kernel<<<dim3(EMBED / 256, N_SUPPORT / 64), 256>>>(support, W, b, 0);
    encode_kernel<<<dim3(EMBED / 256, N_QUERY / 64), 256>>>(query, W, b, 1);
    norms_kernel<<<(N_SUPPORT + N_QUERY) / 8, 256>>>();
    cls_kernel<<<N_SUPPORT / 256, 256>>>(labels);
    fused_attn_kernel<<<N_QUERY / 64, 256>>>(out);
}

// round 2
// speedup vs baseline: 1.0009x; 1.0009x over previous
#include <cuda_runtime.h>
#include <cuda_bf16.h>

// Problem constants
#define N_SUPPORT 4096
#define N_QUERY   8192
#define IN_DIM    784
#define EMBED     512
#define N_CLASSES 64

typedef unsigned long long u64;

// ---------------- scratch (device globals; no allocation allowed) -----------
__device__ float g_semb[N_SUPPORT * EMBED];
__device__ float g_qemb[N_QUERY * EMBED];
__device__ float g_s2[N_SUPPORT];
__device__ float g_q2[N_QUERY];
__device__ int   g_cls[N_SUPPORT];

// ---------------- packed f32x2 helpers --------------------------------------
__device__ __forceinline__ void fma2(u64& d, u64 a, u64 b, u64 c) {
    asm("fma.rn.f32x2 %0, %1, %2, %3;" : "=l"(d) : "l"(a), "l"(b), "l"(c));
}
__device__ __forceinline__ u64 dup2(float x) {
    u64 r;
    asm("mov.b64 %0, {%1, %1};" : "=l"(r) : "r"(__float_as_uint(x)));
    return r;
}
__device__ __forceinline__ void unpack2(u64 v, float& lo, float& hi) {
    unsigned a, b;
    asm("mov.b64 {%0, %1}, %2;" : "=r"(a), "=r"(b) : "l"(v));
    lo = __uint_as_float(a);
    hi = __uint_as_float(b);
}

// =============================================================================
// Encoder GEMM: out[row][n] = sum_k X[row][k] * W[k][n] + b[n]
// Tile 64 rows x 256 cols, 256 threads, 8x8 per thread (4 packed col-pairs).
// which = 0 -> g_semb, 1 -> g_qemb
// =============================================================================
__global__ __launch_bounds__(256, 2)
void encode_kernel(const float* __restrict__ X,
                   const float* __restrict__ W,
                   const float* __restrict__ b,
                   int which) {
    __shared__ __align__(16) float Xs[16][66];
    __shared__ __align__(16) float Ws[16][258];

    float* out = which ? g_qemb : g_semb;

    const int tid  = threadIdx.x;
    const int rg   = tid >> 5;   // warp id: owns rows rg*8..rg*8+7
    const int lane = tid & 31;   // col pairs: 2*lane + 64*jp
    const int row0 = blockIdx.y * 64;
    const int col0 = blockIdx.x * 256;

    u64 acc[8][4];
#pragma unroll
    for (int i = 0; i < 8; i++)
#pragma unroll
        for (int jp = 0; jp < 4; jp++) acc[i][jp] = 0ull;

    const int KCHUNKS = IN_DIM / 16;  // 49
    for (int kc = 0; kc < KCHUNKS; kc++) {
        const int k0 = kc * 16;
        __syncthreads();
        // load X tile (64x16), transposed into Xs[k][row]
#pragma unroll
        for (int r = 0; r < 4; r++) {
            int idx = tid + 256 * r;
            int k = idx & 15, row = idx >> 4;
            Xs[k][row] = X[(row0 + row) * IN_DIM + k0 + k];
        }
        // load W tile (16x256) into Ws[k][n]
#pragma unroll
        for (int r = 0; r < 16; r++) {
            int idx = tid + 256 * r;
            int n = idx & 255, k = idx >> 8;
            Ws[k][n] = W[(k0 + k) * EMBED + col0 + n];
        }
        __syncthreads();

#pragma unroll
        for (int k = 0; k < 16; k++) {
            u64 qq[8];
#pragma unroll
            for (int i = 0; i < 8; i++) qq[i] = dup2(Xs[k][rg * 8 + i]);
            u64 sv[4];
#pragma unroll
            for (int jp = 0; jp < 4; jp++)
                sv[jp] = *reinterpret_cast<const u64*>(&Ws[k][2 * lane + 64 * jp]);
#pragma unroll
            for (int i = 0; i < 8; i++)
#pragma unroll
                for (int jp = 0; jp < 4; jp++)
                    fma2(acc[i][jp], qq[i], sv[jp], acc[i][jp]);
        }
    }

    // epilogue: add bias, write float2
#pragma unroll
    for (int jp = 0; jp < 4; jp++) {
        int c = col0 + 2 * lane + 64 * jp;
        float2 bv = *reinterpret_cast<const float2*>(&b[c]);
#pragma unroll
        for (int i = 0; i < 8; i++) {
            float x, y;
            unpack2(acc[i][jp], x, y);
            float2 o;
            o.x = x + bv.x;
            o.y = y + bv.y;
            *reinterpret_cast<float2*>(&out[(row0 + rg * 8 + i) * EMBED + c]) = o;
        }
    }
}

// =============================================================================
// Row squared-norms for both embedding matrices: one warp per row.
// =============================================================================
__global__ void norms_kernel() {
    int gw   = (blockIdx.x * blockDim.x + threadIdx.x) >> 5;
    int lane = threadIdx.x & 31;
    if (gw >= N_SUPPORT + N_QUERY) return;
    const float* src;
    float* dst;
    if (gw < N_SUPPORT) {
        src = g_semb + gw * EMBED;
        dst = &g_s2[gw];
    } else {
        src = g_qemb + (gw - N_SUPPORT) * EMBED;
        dst = &g_q2[gw - N_SUPPORT];
    }
    const float4* p = reinterpret_cast<const float4*>(src);
    float s = 0.f;
#pragma unroll
    for (int j = 0; j < 4; j++) {
        float4 v = p[lane + 32 * j];
        s += v.x * v.x + v.y * v.y + v.z * v.z + v.w * v.w;
    }
#pragma unroll
    for (int off = 16; off; off >>= 1) s += __shfl_xor_sync(0xffffffffu, s, off);
    if (lane == 0) *dst = s;
}

// =============================================================================
// One-hot -> class index
// =============================================================================
__global__ void cls_kernel(const float* __restrict__ labels) {
    int i = blockIdx.x * blockDim.x + threadIdx.x;
    if (i >= N_SUPPORT) return;
    int c = 0;
#pragma unroll
    for (int j = 0; j < N_CLASSES; j++)
        if (labels[i * N_CLASSES + j] > 0.5f) c = j;
    g_cls[i] = c;
}

// =============================================================================
// Fused attention kernel.
// One CTA owns 64 query rows; loops over all 4096 supports in tiles of 256.
// dist = -sqrt(max(q2 + s2 - 2 q.s, 0)); p = exp(32 + dist) (safe fixed shift);
// accumulate l[row] and sacc[row][class] (labels are one-hot); normalize.
// =============================================================================
__global__ __launch_bounds__(256, 1)
void fused_attn_kernel(float* __restrict__ out) {
    __shared__ __align__(16) float Qs[16][66];
    __shared__ __align__(16) float Ss[16][258];
    __shared__ float sacc[64][N_CLASSES];
    __shared__ float ls[64];
    __shared__ float q2s[64];

    const int tid  = threadIdx.x;
    const int rg   = tid >> 5;
    const int lane = tid & 31;
    const int row0 = blockIdx.x * 64;

    for (int idx = tid; idx < 64 * N_CLASSES; idx += 256)
        (&sacc[0][0])[idx] = 0.f;
    if (tid < 64) q2s[tid] = g_q2[row0 + tid];

    float l_part[8];
#pragma unroll
    for (int i = 0; i < 8; i++) l_part[i] = 0.f;

    __syncthreads();

    for (int st = 0; st < N_SUPPORT / 256; st++) {
        const int col0 = st * 256;

        u64 acc[8][4];
#pragma unroll
        for (int i = 0; i < 8; i++)
#pragma unroll
            for (int jp = 0; jp < 4; jp++) acc[i][jp] = 0ull;

        // per-tile support norms + class ids for this thread's 8 columns
        float2 s2p[4];
        int clsv[8];
#pragma unroll
        for (int jp = 0; jp < 4; jp++) {
            int c = col0 + 2 * lane + 64 * jp;
            s2p[jp] = *reinterpret_cast<const float2*>(&g_s2[c]);
            clsv[2 * jp]     = g_cls[c];
            clsv[2 * jp + 1] = g_cls[c + 1];
        }

        for (int kc = 0; kc < EMBED / 16; kc++) {
            const int k0 = kc * 16;
            __syncthreads();
            // Q tile 64x16 transposed
#pragma unroll
            for (int r = 0; r < 4; r++) {
                int idx = tid + 256 * r;
                int k = idx & 15, row = idx >> 4;
                Qs[k][row] = g_qemb[(row0 + row) * EMBED + k0 + k];
            }
            // S tile 256x16 transposed
#pragma unroll
            for (int r = 0; r < 16; r++) {
                int idx = tid + 256 * r;
                int k = idx & 15, n = idx >> 4;
                Ss[k][n] = g_semb[(col0 + n) * EMBED + k0 + k];
            }
            __syncthreads();

#pragma unroll
            for (int k = 0; k < 16; k++) {
                u64 qq[8];
#pragma unroll
                for (int i = 0; i < 8; i++) qq[i] = dup2(Qs[k][rg * 8 + i]);
                u64 sv[4];
#pragma unroll
                for (int jp = 0; jp < 4; jp++)
                    sv[jp] = *reinterpret_cast<const u64*>(&Ss[k][2 * lane + 64 * jp]);
#pragma unroll
                for (int i = 0; i < 8; i++)
#pragma unroll
                    for (int jp = 0; jp < 4; jp++)
                        fma2(acc[i][jp], qq[i], sv[jp], acc[i][jp]);
            }
        }
        __syncthreads();

        // epilogue for this support tile
#pragma unroll
        for (int i = 0; i < 8; i++) {
            const float q2v = q2s[rg * 8 + i];
            float lsum = 0.f;
#pragma unroll
            for (int jp = 0; jp < 4; jp++) {
                float qsx, qsy;
                unpack2(acc[i][jp], qsx, qsy);
                float d2x = fmaxf(q2v + s2p[jp].x - 2.f * qsx, 0.f);
                float d2y = fmaxf(q2v + s2p[jp].y - 2.f * qsy, 0.f);
                float dx = __fsqrt_rn(d2x);
                float dy = __fsqrt_rn(d2y);
                float px = __expf(32.0f - dx);
                float py = __expf(32.0f - dy);
                lsum += px + py;
                atomicAdd(&sacc[rg * 8 + i][clsv[2 * jp]], px);
                atomicAdd(&sacc[rg * 8 + i][clsv[2 * jp + 1]], py);
            }
            l_part[i] += lsum;
        }
    }

    // reduce l across lanes (each warp owns its 8 rows exclusively)
#pragma unroll
    for (int i = 0; i < 8; i++) {
        float v = l_part[i];
#pragma unroll
        for (int off = 16; off; off >>= 1) v += __shfl_xor_sync(0xffffffffu, v, off);
        if (lane == 0) ls[rg * 8 + i] = v;
    }
    __syncthreads();

    for (int idx = tid; idx < 64 * N_CLASSES; idx += 256) {
        int r = idx >> 6, c = idx & 63;
        out[(row0 + r) * N_CLASSES + c] = sacc[r][c] / ls[r];
    }
}

// =============================================================================
// Launch
// =============================================================================
extern "C" void kernel_launch(void* const* d_in, const int* in_sizes, int n_in,
                              void* d_out, int out_size) {
    const float* support = (const float*)d_in[0];  // (4096,1,28,28)
    const float* query   = (const float*)d_in[1];  // (8192,1,28,28)
    const float* labels  = (const float*)d_in[2];  // (4096,64) one-hot
    const float* W       = (const float*)d_in[3];  // (784,512)
    const float* b       = (const float*)d_in[4];  // (512,)
    float* out = (float*)d_out;                    // (8192,64)

    encode_kernel<<<dim3(EMBED / 256, N_SUPPORT / 64), 256>>>(support, W, b, 0);
    encode_kernel<<<dim3(EMBED / 256, N_QUERY / 64), 256>>>(query, W, b, 1);
    norms_kernel<<<(N_SUPPORT + N_QUERY) / 8, 256>>>();
    cls_kernel<<<N_SUPPORT / 256, 256>>>(labels);
    fused_attn_kernel<<<N_QUERY / 64, 256>>>(out);
}

// round 5
// speedup vs baseline: 2.2513x; 2.2493x over previous
#include <cuda_runtime.h>
#include <cuda_fp16.h>
#include <cstdint>

#define NS 4096
#define NQ 8192
#define NR 12288
#define IND 784
#define EMB 512
#define NC 64
#define KE 2368          // 3*784 padded to 64
#define LOG2E 1.4426950408889634f

// ------------------------- device scratch -----------------------------------
__device__ __align__(128) __half g_X[(size_t)NR * KE];      // [xh|xh|xl]
__device__ __align__(128) __half g_W[(size_t)EMB * KE];     // [wh|wl|wh] (W^T rows)
__device__ __align__(128) __half g_Q[(size_t)NQ * 1024];    // [qh|ql]  (2048 B/row)
__device__ __align__(128) __half g_S[(size_t)NS * 512];     // [sh]     (1024 B/row)
__device__ float g_n2p[4 * NR];
__device__ int   g_cls[NS];
__device__ float g_pnum[2 * (size_t)NQ * NC];
__device__ float g_pden[2 * NQ];

// ------------------------- helpers ------------------------------------------
__device__ __forceinline__ uint32_t smem_u32(const void* p) {
    uint32_t a;
    asm("{ .reg .u64 t; cvta.to.shared.u64 t, %1; cvt.u32.u64 %0, t; }" : "=r"(a) : "l"(p));
    return a;
}
#define CP_COMMIT() asm volatile("cp.async.commit_group;" ::: "memory")
#define CP_WAIT2()  asm volatile("cp.async.wait_group 2;" ::: "memory")

__device__ __forceinline__ uint32_t lds32(uint32_t a) {
    uint32_t v;
    asm("ld.shared.b32 %0, [%1];" : "=r"(v) : "r"(a));
    return v;
}
__device__ __forceinline__ void mma16816(float c[4], uint32_t a0, uint32_t a1, uint32_t a2,
                                         uint32_t a3, uint32_t b0, uint32_t b1) {
    asm volatile(
        "mma.sync.aligned.m16n8k16.row.col.f32.f16.f16.f32 "
        "{%0,%1,%2,%3}, {%4,%5,%6,%7}, {%8,%9}, {%0,%1,%2,%3};"
        : "+f"(c[0]), "+f"(c[1]), "+f"(c[2]), "+f"(c[3])
        : "r"(a0), "r"(a1), "r"(a2), "r"(a3), "r"(b0), "r"(b1));
}

// 128 rows x 64 halfs (128B) global -> smem (stride 144B), via cp.async 16B
__device__ __forceinline__ void load128(uint32_t sdst, const char* g, size_t rs, int tid) {
#pragma unroll
    for (int i = 0; i < 4; i++) {
        int u = tid + (i << 8), r = u >> 3, j = u & 7;
        asm volatile("cp.async.cg.shared.global [%0], [%1], 16;"
                     :: "r"(sdst + r * 144 + j * 16), "l"(g + (size_t)r * rs + j * 16) : "memory");
    }
}

// One BK=64 chunk of the 128x128 warp-tiled MMA
__device__ __forceinline__ void compute64(uint32_t smA, uint32_t smB, int wm, int wn, int lane,
                                          float c[4][4][4]) {
    uint32_t ab = smA + (uint32_t)((wm * 64 + (lane >> 2)) * 144 + (lane & 3) * 4);
    uint32_t bb = smB + (uint32_t)((wn * 32 + (lane >> 2)) * 144 + (lane & 3) * 4);
#pragma unroll
    for (int ks = 0; ks < 4; ks++) {
        uint32_t ko = ks * 32;
        uint32_t a[4][4], b[4][2];
#pragma unroll
        for (int mi = 0; mi < 4; mi++) {
            uint32_t base = ab + mi * 2304 + ko;      // 16 rows * 144
            a[mi][0] = lds32(base);
            a[mi][1] = lds32(base + 1152);            // +8 rows
            a[mi][2] = lds32(base + 16);              // +8 k
            a[mi][3] = lds32(base + 1152 + 16);
        }
#pragma unroll
        for (int ni = 0; ni < 4; ni++) {
            uint32_t base = bb + ni * 1152 + ko;      // 8 rows * 144
            b[ni][0] = lds32(base);
            b[ni][1] = lds32(base + 16);
        }
#pragma unroll
        for (int mi = 0; mi < 4; mi++)
#pragma unroll
            for (int ni = 0; ni < 4; ni++)
                mma16816(c[mi][ni], a[mi][0], a[mi][1], a[mi][2], a[mi][3], b[ni][0], b[ni][1]);
    }
}

// ------------------------- smem layouts -------------------------------------
#define STG 36864                  // per stage: A 18432 + B 18432, 3 stages = 110592
#define E_BIAS 110592
#define E_N2   111104
#define SMEM_ENC 111616
#define D_SACC 110592              // 128*65 f32 = 33280
#define D_S2   143872              // 2*128 f32
#define D_CLS  144896              // 2*128 int
#define D_Q2   145920              // 128 f32
#define D_LS   146432              // 128 f32
#define SMEM_DIST 146944

// =============================================================================
// Prep kernels
// =============================================================================
__global__ void prep_x(const float* __restrict__ sup, const float* __restrict__ qry) {
    int rg = blockIdx.x;
    const float* src = rg < NS ? sup + (size_t)rg * IND : qry + (size_t)(rg - NS) * IND;
    __half* dst = g_X + (size_t)rg * KE;
    for (int c = threadIdx.x; c < IND; c += 128) {
        float x = src[c];
        __half h = __float2half_rn(x);
        __half l = __float2half_rn(x - __half2float(h));
        dst[c] = h; dst[IND + c] = h; dst[2 * IND + c] = l;
    }
    if (threadIdx.x < KE - 3 * IND) dst[3 * IND + threadIdx.x] = __ushort_as_half(0);
}
__global__ void prep_w(const float* __restrict__ W) {
    int n = blockIdx.x;
    __half* dst = g_W + (size_t)n * KE;
    for (int k = threadIdx.x; k < IND; k += 128) {
        float x = W[(size_t)k * EMB + n];
        __half h = __float2half_rn(x);
        __half l = __float2half_rn(x - __half2float(h));
        dst[k] = h; dst[IND + k] = l; dst[2 * IND + k] = h;
    }
    if (threadIdx.x < KE - 3 * IND) dst[3 * IND + threadIdx.x] = __ushort_as_half(0);
}
__global__ void cls_kernel(const float* __restrict__ labels) {
    int i = blockIdx.x * blockDim.x + threadIdx.x;
    if (i >= NS) return;
    int c = 0;
#pragma unroll
    for (int j = 0; j < NC; j++)
        if (labels[i * NC + j] > 0.5f) c = j;
    g_cls[i] = c;
}

// =============================================================================
// Encoder: D[128x128] = X[m0..][K] * W^T[n0..][K],  K=2368, fp16 3-term split
// =============================================================================
__global__ __launch_bounds__(256, 1) void enc_kernel(const float* __restrict__ bias) {
    extern __shared__ char sm[];
    uint32_t smb = smem_u32(sm);
    const int tid = threadIdx.x, lane = tid & 31, w = tid >> 5, wm = w >> 2, wn = w & 3;
    const int m0 = blockIdx.x * 128, n0 = blockIdx.y * 128;
    float* biasS = (float*)(sm + E_BIAS);
    float* n2s = (float*)(sm + E_N2);
    if (tid < 128) { biasS[tid] = bias[n0 + tid]; n2s[tid] = 0.f; }

    const char* A = (const char*)g_X + (size_t)m0 * (KE * 2);
    const char* B = (const char*)g_W + (size_t)n0 * (KE * 2);
    const int G = KE / 64;  // 37
    load128(smb,               A,       KE * 2, tid);
    load128(smb + 18432,       B,       KE * 2, tid); CP_COMMIT();
    load128(smb + STG,         A + 128, KE * 2, tid);
    load128(smb + STG + 18432, B + 128, KE * 2, tid); CP_COMMIT();

    float c[4][4][4];
#pragma unroll
    for (int i = 0; i < 4; i++)
#pragma unroll
        for (int j = 0; j < 4; j++)
#pragma unroll
            for (int k = 0; k < 4; k++) c[i][j][k] = 0.f;
    __syncthreads();

    for (int g = 0; g < G; g++) {
        if (g + 2 < G) {
            int s = ((g + 2) % 3) * STG;
            load128(smb + s,         A + (size_t)(g + 2) * 128, KE * 2, tid);
            load128(smb + s + 18432, B + (size_t)(g + 2) * 128, KE * 2, tid);
        }
        CP_COMMIT(); CP_WAIT2(); __syncthreads();
        int s = (g % 3) * STG;
        compute64(smb + s, smb + s + 18432, wm, wn, lane, c);
        __syncthreads();
    }

    // epilogue: bias, hi/lo fp16 split, norms
    float vsq[8];
#pragma unroll
    for (int i = 0; i < 8; i++) vsq[i] = 0.f;
#pragma unroll
    for (int mi = 0; mi < 4; mi++) {
        int r0 = wm * 64 + mi * 16 + (lane >> 2);
#pragma unroll
        for (int ni = 0; ni < 4; ni++) {
            int cn = wn * 32 + ni * 8 + (lane & 3) * 2;
            float b0 = biasS[cn], b1 = biasS[cn + 1];
            float v0 = c[mi][ni][0] + b0, v1 = c[mi][ni][1] + b1;
            float v2 = c[mi][ni][2] + b0, v3 = c[mi][ni][3] + b1;
            vsq[2 * mi] += v0 * v0 + v1 * v1;
            vsq[2 * mi + 1] += v2 * v2 + v3 * v3;
#pragma unroll
            for (int h = 0; h < 2; h++) {
                float x0 = h ? v2 : v0, x1 = h ? v3 : v1;
                int rg = m0 + r0 + h * 8, col = n0 + cn;
                __half h0 = __float2half_rn(x0), h1 = __float2half_rn(x1);
                uint32_t hp = ((uint32_t)__half_as_ushort(h1) << 16) | __half_as_ushort(h0);
                if (rg < NS) {
                    // S: single hi copy, 512 halfs (1024 B) per row
                    uint32_t* p = (uint32_t*)(g_S + (size_t)rg * 512);
                    p[col >> 1] = hp;
                } else {
                    // Q: [qh|ql], 1024 halfs (2048 B) per row
                    __half l0 = __float2half_rn(x0 - __half2float(h0));
                    __half l1 = __float2half_rn(x1 - __half2float(h1));
                    uint32_t lp = ((uint32_t)__half_as_ushort(l1) << 16) | __half_as_ushort(l0);
                    uint32_t* p = (uint32_t*)(g_Q + (size_t)(rg - NS) * 1024);
                    p[col >> 1] = hp; p[(col >> 1) + 256] = lp;
                }
            }
        }
    }
#pragma unroll
    for (int i = 0; i < 8; i++) {
        float v = vsq[i];
        v += __shfl_xor_sync(~0u, v, 1);
        v += __shfl_xor_sync(~0u, v, 2);
        if ((lane & 3) == 0)
            atomicAdd(&n2s[wm * 64 + (i >> 1) * 16 + (lane >> 2) + (i & 1) * 8], v);
    }
    __syncthreads();
    if (tid < 128) g_n2p[blockIdx.y * NR + m0 + tid] = n2s[tid];
}

__device__ __forceinline__ float pfun(float q2, float s2, float qs) {
    float d2 = fmaxf(q2 + s2 - 2.f * qs, 0.f);
    float d, p;
    asm("sqrt.approx.f32 %0, %1;" : "=f"(d) : "f"(d2));
    asm("ex2.approx.f32 %0, %1;" : "=f"(p) : "f"((32.f - d) * LOG2E));
    return p;
}

// =============================================================================
// Fused distance/softmax/aggregate. CTA: 128 queries x 2048 supports.
// 16 n-tiles x 16 K-chunks streamed through one continuous cp.async pipeline.
// A (Q) rows: 2048 B [qh|ql]; B (S) rows: 1024 B [sh], reused for kc 0-7 / 8-15.
// =============================================================================
__global__ __launch_bounds__(256, 1) void dist_kernel() {
    extern __shared__ char sm[];
    uint32_t smb = smem_u32(sm);
    const int tid = threadIdx.x, lane = tid & 31, w = tid >> 5, wm = w >> 2, wn = w & 3;
    const int m0 = blockIdx.x * 128, half = blockIdx.y, s0 = half * 2048;
    float* sacc = (float*)(sm + D_SACC);
    float* s2s  = (float*)(sm + D_S2);
    int*   clss = (int*)(sm + D_CLS);
    float* q2s  = (float*)(sm + D_Q2);
    float* lss  = (float*)(sm + D_LS);

    for (int i = tid; i < 128 * 65; i += 256) sacc[i] = 0.f;
    if (tid < 128) {
        int qr = NS + m0 + tid;
        q2s[tid] = g_n2p[qr] + g_n2p[NR + qr] + g_n2p[2 * NR + qr] + g_n2p[3 * NR + qr];
        lss[tid] = 0.f;
        int sc = s0 + tid;
        s2s[tid] = g_n2p[sc] + g_n2p[NR + sc] + g_n2p[2 * NR + sc] + g_n2p[3 * NR + sc];
        clss[tid] = g_cls[sc];
    }
    const char* A = (const char*)g_Q + (size_t)m0 * 2048;
    const char* Sb = (const char*)g_S;

#define LOADG(gg) do { \
        int _s = ((gg) % 3) * STG, _t = (gg) >> 4, _kc = (gg) & 15; \
        load128(smb + _s, A + (size_t)_kc * 128, 2048, tid); \
        load128(smb + _s + 18432, \
                Sb + (size_t)(s0 + _t * 128) * 1024 + (size_t)(_kc & 7) * 128, 1024, tid); \
    } while (0)

    LOADG(0); CP_COMMIT();
    LOADG(1); CP_COMMIT();

    float c[4][4][4];
#pragma unroll
    for (int i = 0; i < 4; i++)
#pragma unroll
        for (int j = 0; j < 4; j++)
#pragma unroll
            for (int k = 0; k < 4; k++) c[i][j][k] = 0.f;
    float lrow[8];
#pragma unroll
    for (int i = 0; i < 8; i++) lrow[i] = 0.f;
    __syncthreads();
    float q2r[8];
#pragma unroll
    for (int i = 0; i < 8; i++)
        q2r[i] = q2s[wm * 64 + (i >> 1) * 16 + (lane >> 2) + (i & 1) * 8];

    for (int g = 0; g < 256; g++) {
        if (g + 2 < 256) LOADG(g + 2);
        CP_COMMIT(); CP_WAIT2(); __syncthreads();
        int s = (g % 3) * STG;
        compute64(smb + s, smb + s + 18432, wm, wn, lane, c);
        if ((g & 15) == 15) {
            int t = g >> 4, slot = t & 1;
            const float* s2 = s2s + slot * 128;
            const int* cl = clss + slot * 128;
#pragma unroll
            for (int mi = 0; mi < 4; mi++) {
                int r0 = wm * 64 + mi * 16 + (lane >> 2);
#pragma unroll
                for (int ni = 0; ni < 4; ni++) {
                    int j0 = wn * 32 + ni * 8 + (lane & 3) * 2;
                    float s20 = s2[j0], s21 = s2[j0 + 1];
                    int c0i = cl[j0], c1i = cl[j0 + 1];
                    float p00 = pfun(q2r[2 * mi], s20, c[mi][ni][0]);
                    float p01 = pfun(q2r[2 * mi], s21, c[mi][ni][1]);
                    float p10 = pfun(q2r[2 * mi + 1], s20, c[mi][ni][2]);
                    float p11 = pfun(q2r[2 * mi + 1], s21, c[mi][ni][3]);
                    atomicAdd(&sacc[r0 * 65 + c0i], p00);
                    atomicAdd(&sacc[r0 * 65 + c1i], p01);
                    atomicAdd(&sacc[(r0 + 8) * 65 + c0i], p10);
                    atomicAdd(&sacc[(r0 + 8) * 65 + c1i], p11);
                    lrow[2 * mi] += p00 + p01;
                    lrow[2 * mi + 1] += p10 + p11;
                    c[mi][ni][0] = c[mi][ni][1] = c[mi][ni][2] = c[mi][ni][3] = 0.f;
                }
            }
            if (t + 1 < 16 && tid < 128) {
                int sc = s0 + (t + 1) * 128 + tid;
                s2s[((t + 1) & 1) * 128 + tid] =
                    g_n2p[sc] + g_n2p[NR + sc] + g_n2p[2 * NR + sc] + g_n2p[3 * NR + sc];
                clss[((t + 1) & 1) * 128 + tid] = g_cls[sc];
            }
        }
        __syncthreads();
    }
#pragma unroll
    for (int i = 0; i < 8; i++) {
        float v = lrow[i];
        v += __shfl_xor_sync(~0u, v, 1);
        v += __shfl_xor_sync(~0u, v, 2);
        if ((lane & 3) == 0)
            atomicAdd(&lss[wm * 64 + (i >> 1) * 16 + (lane >> 2) + (i & 1) * 8], v);
    }
    __syncthreads();
    for (int i = tid; i < 128 * 64; i += 256) {
        int r = i >> 6, cc = i & 63;
        g_pnum[(size_t)half * NQ * NC + (size_t)(m0 + r) * NC + cc] = sacc[r * 65 + cc];
    }
    if (tid < 128) g_pden[half * NQ + m0 + tid] = lss[tid];
#undef LOADG
}

// =============================================================================
// Finalize
// =============================================================================
__global__ void fin_kernel(float* __restrict__ out) {
    int i = blockIdx.x * blockDim.x + threadIdx.x;
    if (i >= NQ * NC) return;
    int q = i >> 6;
    out[i] = (g_pnum[i] + g_pnum[(size_t)NQ * NC + i]) / (g_pden[q] + g_pden[NQ + q]);
}

// =============================================================================
// Launch
// =============================================================================
extern "C" void kernel_launch(void* const* d_in, const int* in_sizes, int n_in,
                              void* d_out, int out_size) {
    const float* support = (const float*)d_in[0];
    const float* query   = (const float*)d_in[1];
    const float* labels  = (const float*)d_in[2];
    const float* W       = (const float*)d_in[3];
    const float* b       = (const float*)d_in[4];
    float* out = (float*)d_out;

    cudaFuncSetAttribute(enc_kernel,  cudaFuncAttributeMaxDynamicSharedMemorySize, SMEM_ENC);
    cudaFuncSetAttribute(dist_kernel, cudaFuncAttributeMaxDynamicSharedMemorySize, SMEM_DIST);

    prep_x<<<NR, 128>>>(support, query);
    prep_w<<<EMB, 128>>>(W);
    cls_kernel<<<NS / 256, 256>>>(labels);
    enc_kernel<<<dim3(NR / 128, EMB / 128), 256, SMEM_ENC>>>(b);
    dist_kernel<<<dim3(NQ / 128, 2), 256, SMEM_DIST>>>();
    fin_kernel<<<(NQ * NC + 255) / 256, 256>>>(out);
}

// round 6
// speedup vs baseline: 2.6514x; 1.1777x over previous
#include <cuda_runtime.h>
#include <cuda_fp16.h>
#include <cstdint>

#define NS 4096
#define NQ 8192
#define NR 12288
#define IND 784
#define EMB 512
#define NC 64
#define KE 2368          // 3*784 padded to 64
#define LOG2E 1.4426950408889634f

// ------------------------- device scratch -----------------------------------
__device__ __align__(128) __half g_X[(size_t)NR * KE];      // [xh|xh|xl]
__device__ __align__(128) __half g_W[(size_t)EMB * KE];     // [wh|wl|wh] (W^T rows)
__device__ __align__(128) __half g_Q[(size_t)NQ * 512];     // qh (1024 B/row)
__device__ __align__(128) __half g_S[(size_t)NS * 512];     // sh, class-sorted rows
__device__ float g_n2p[4 * NR];
__device__ int   g_cls[NS];
__device__ int   g_rank[NS];
__device__ int   g_inv[NS];
__device__ float g_s2s[NS];     // sorted support norms (full)
__device__ int   g_clsS[NS];    // sorted classes
__device__ float g_q2f[NQ];     // full query norms
__device__ float g_pnum[2 * (size_t)NQ * NC];
__device__ float g_pden[2 * NQ];

// ------------------------- helpers ------------------------------------------
__device__ __forceinline__ uint32_t smem_u32(const void* p) {
    uint32_t a;
    asm("{ .reg .u64 t; cvta.to.shared.u64 t, %1; cvt.u32.u64 %0, t; }" : "=r"(a) : "l"(p));
    return a;
}
#define CP_COMMIT() asm volatile("cp.async.commit_group;" ::: "memory")
#define CP_WAIT2()  asm volatile("cp.async.wait_group 2;" ::: "memory")

__device__ __forceinline__ void ldm4(uint32_t r[4], uint32_t addr) {
    asm volatile("ldmatrix.sync.aligned.m8n8.x4.shared.b16 {%0,%1,%2,%3}, [%4];"
                 : "=r"(r[0]), "=r"(r[1]), "=r"(r[2]), "=r"(r[3]) : "r"(addr));
}
__device__ __forceinline__ void mma16816(float c[4], uint32_t a0, uint32_t a1, uint32_t a2,
                                         uint32_t a3, uint32_t b0, uint32_t b1) {
    asm volatile(
        "mma.sync.aligned.m16n8k16.row.col.f32.f16.f16.f32 "
        "{%0,%1,%2,%3}, {%4,%5,%6,%7}, {%8,%9}, {%0,%1,%2,%3};"
        : "+f"(c[0]), "+f"(c[1]), "+f"(c[2]), "+f"(c[3])
        : "r"(a0), "r"(a1), "r"(a2), "r"(a3), "r"(b0), "r"(b1));
}

// 128 rows x 64 halfs (128B) global -> smem (stride 144B), via cp.async 16B
__device__ __forceinline__ void load128(uint32_t sdst, const char* g, size_t rs, int tid) {
#pragma unroll
    for (int i = 0; i < 4; i++) {
        int u = tid + (i << 8), r = u >> 3, j = u & 7;
        asm volatile("cp.async.cg.shared.global [%0], [%1], 16;"
                     :: "r"(sdst + r * 144 + j * 16), "l"(g + (size_t)r * rs + j * 16) : "memory");
    }
}

// One BK=64 chunk of the 128x128 warp-tiled MMA. ldmatrix + frag double buffer.
__device__ __forceinline__ void compute64(uint32_t smA, uint32_t smB, int wm, int wn, int lane,
                                          float c[4][4][4]) {
    // A: lanes 0-7 rows 0-7 k0, 8-15 rows 8-15 k0, 16-23 rows 0-7 k8, 24-31 rows 8-15 k8
    uint32_t aRow = smA + (uint32_t)((wm * 64 + (lane & 15)) * 144 + (lane >> 4) * 16);
    // B: lanes 0-7 n0-7 k0, 8-15 n0-7 k8, 16-23 n8-15 k0, 24-31 n8-15 k8
    uint32_t bRow = smB + (uint32_t)((wn * 32 + (lane >> 4) * 8 + (lane & 7)) * 144
                                     + ((lane >> 3) & 1) * 16);
    uint32_t af[2][4][4], bf[2][2][4];
#pragma unroll
    for (int mi = 0; mi < 4; mi++) ldm4(af[0][mi], aRow + mi * 2304);
#pragma unroll
    for (int q = 0; q < 2; q++) ldm4(bf[0][q], bRow + q * 2304);
#pragma unroll
    for (int ks = 0; ks < 4; ks++) {
        int cur = ks & 1, nxt = cur ^ 1;
        if (ks < 3) {
            uint32_t ko = (uint32_t)(ks + 1) * 32;
#pragma unroll
            for (int mi = 0; mi < 4; mi++) ldm4(af[nxt][mi], aRow + mi * 2304 + ko);
#pragma unroll
            for (int q = 0; q < 2; q++) ldm4(bf[nxt][q], bRow + q * 2304 + ko);
        }
#pragma unroll
        for (int mi = 0; mi < 4; mi++)
#pragma unroll
            for (int ni = 0; ni < 4; ni++)
                mma16816(c[mi][ni], af[cur][mi][0], af[cur][mi][1], af[cur][mi][2],
                         af[cur][mi][3], bf[cur][ni >> 1][(ni & 1) * 2],
                         bf[cur][ni >> 1][(ni & 1) * 2 + 1]);
    }
}

// ------------------------- smem layouts -------------------------------------
#define STG 36864                  // per stage: A 18432 + B 18432, 3 stages = 110592
#define E_BIAS 110592
#define E_N2   111104
#define SMEM_ENC 111616
#define D_SACC 110592              // 128*65 f32 = 33280
#define D_S2   143872              // 2*128 f32
#define D_CLS  144896              // 2*128 int
#define D_Q2   145920              // 128 f32
#define D_LS   146432              // 128 f32
#define SMEM_DIST 146944

// =============================================================================
// Prep kernels
// =============================================================================
__global__ void prep_x(const float* __restrict__ sup, const float* __restrict__ qry) {
    int rg = blockIdx.x;
    const float* src = rg < NS ? sup + (size_t)rg * IND : qry + (size_t)(rg - NS) * IND;
    __half* dst = g_X + (size_t)rg * KE;
    for (int c = threadIdx.x; c < IND; c += 128) {
        float x = src[c];
        __half h = __float2half_rn(x);
        __half l = __float2half_rn(x - __half2float(h));
        dst[c] = h; dst[IND + c] = h; dst[2 * IND + c] = l;
    }
    if (threadIdx.x < KE - 3 * IND) dst[3 * IND + threadIdx.x] = __ushort_as_half(0);
}
__global__ void prep_w(const float* __restrict__ W) {
    int n = blockIdx.x;
    __half* dst = g_W + (size_t)n * KE;
    for (int k = threadIdx.x; k < IND; k += 128) {
        float x = W[(size_t)k * EMB + n];
        __half h = __float2half_rn(x);
        __half l = __float2half_rn(x - __half2float(h));
        dst[k] = h; dst[IND + k] = l; dst[2 * IND + k] = h;
    }
    if (threadIdx.x < KE - 3 * IND) dst[3 * IND + threadIdx.x] = __ushort_as_half(0);
}
__global__ void cls_kernel(const float* __restrict__ labels) {
    int i = blockIdx.x * blockDim.x + threadIdx.x;
    if (i >= NS) return;
    int c = 0;
#pragma unroll
    for (int j = 0; j < NC; j++)
        if (labels[i * NC + j] > 0.5f) c = j;
    g_cls[i] = c;
}
// Deterministic counting-sort rank: rank[i] = #{j : cls_j<cls_i or (== and j<i)}
__global__ void rank_kernel() {
    __shared__ int cl[NS];
    for (int i = threadIdx.x; i < NS; i += 128) cl[i] = g_cls[i];
    __syncthreads();
    int i = blockIdx.x * 128 + threadIdx.x;
    int c = cl[i], r = 0;
    for (int j = 0; j < NS; j++) {
        int cj = cl[j];
        r += (cj < c) || (cj == c && j < i);
    }
    g_rank[i] = r;
    g_inv[r] = i;
}
// Sorted-order metadata + full norms
__global__ void meta_kernel() {
    int i = blockIdx.x * 256 + threadIdx.x;
    if (i < NS) {
        int o = g_inv[i];
        g_s2s[i] = g_n2p[o] + g_n2p[NR + o] + g_n2p[2 * NR + o] + g_n2p[3 * NR + o];
        g_clsS[i] = g_cls[o];
    } else if (i < NS + NQ) {
        int o = i;  // NS + q
        g_q2f[i - NS] = g_n2p[o] + g_n2p[NR + o] + g_n2p[2 * NR + o] + g_n2p[3 * NR + o];
    }
}

// =============================================================================
// Encoder: D[128x128] = X[m0..][K] * W^T[n0..][K],  K=2368, fp16 3-term split
// =============================================================================
__global__ __launch_bounds__(256, 1) void enc_kernel(const float* __restrict__ bias) {
    extern __shared__ char sm[];
    uint32_t smb = smem_u32(sm);
    const int tid = threadIdx.x, lane = tid & 31, w = tid >> 5, wm = w >> 2, wn = w & 3;
    const int m0 = blockIdx.x * 128, n0 = blockIdx.y * 128;
    float* biasS = (float*)(sm + E_BIAS);
    float* n2s = (float*)(sm + E_N2);
    if (tid < 128) { biasS[tid] = bias[n0 + tid]; n2s[tid] = 0.f; }

    const char* A = (const char*)g_X + (size_t)m0 * (KE * 2);
    const char* B = (const char*)g_W + (size_t)n0 * (KE * 2);
    const int G = KE / 64;  // 37
    load128(smb,               A,       KE * 2, tid);
    load128(smb + 18432,       B,       KE * 2, tid); CP_COMMIT();
    load128(smb + STG,         A + 128, KE * 2, tid);
    load128(smb + STG + 18432, B + 128, KE * 2, tid); CP_COMMIT();

    float c[4][4][4];
#pragma unroll
    for (int i = 0; i < 4; i++)
#pragma unroll
        for (int j = 0; j < 4; j++)
#pragma unroll
            for (int k = 0; k < 4; k++) c[i][j][k] = 0.f;
    __syncthreads();

    for (int g = 0; g < G; g++) {
        if (g + 2 < G) {
            int s = ((g + 2) % 3) * STG;
            load128(smb + s,         A + (size_t)(g + 2) * 128, KE * 2, tid);
            load128(smb + s + 18432, B + (size_t)(g + 2) * 128, KE * 2, tid);
        }
        CP_COMMIT(); CP_WAIT2(); __syncthreads();
        int s = (g % 3) * STG;
        compute64(smb + s, smb + s + 18432, wm, wn, lane, c);
        __syncthreads();
    }

    // epilogue: bias, fp16 store (S rows class-sorted via g_rank), norms
    float vsq[8];
#pragma unroll
    for (int i = 0; i < 8; i++) vsq[i] = 0.f;
#pragma unroll
    for (int mi = 0; mi < 4; mi++) {
        int r0 = wm * 64 + mi * 16 + (lane >> 2);
#pragma unroll
        for (int ni = 0; ni < 4; ni++) {
            int cn = wn * 32 + ni * 8 + (lane & 3) * 2;
            float b0 = biasS[cn], b1 = biasS[cn + 1];
            float v0 = c[mi][ni][0] + b0, v1 = c[mi][ni][1] + b1;
            float v2 = c[mi][ni][2] + b0, v3 = c[mi][ni][3] + b1;
            vsq[2 * mi] += v0 * v0 + v1 * v1;
            vsq[2 * mi + 1] += v2 * v2 + v3 * v3;
#pragma unroll
            for (int h = 0; h < 2; h++) {
                float x0 = h ? v2 : v0, x1 = h ? v3 : v1;
                int rg = m0 + r0 + h * 8, col = n0 + cn;
                __half h0 = __float2half_rn(x0), h1 = __float2half_rn(x1);
                uint32_t hp = ((uint32_t)__half_as_ushort(h1) << 16) | __half_as_ushort(h0);
                if (rg < NS) {
                    int sr = g_rank[rg];
                    ((uint32_t*)(g_S + (size_t)sr * 512))[col >> 1] = hp;
                } else {
                    ((uint32_t*)(g_Q + (size_t)(rg - NS) * 512))[col >> 1] = hp;
                }
            }
        }
    }
#pragma unroll
    for (int i = 0; i < 8; i++) {
        float v = vsq[i];
        v += __shfl_xor_sync(~0u, v, 1);
        v += __shfl_xor_sync(~0u, v, 2);
        if ((lane & 3) == 0)
            atomicAdd(&n2s[wm * 64 + (i >> 1) * 16 + (lane >> 2) + (i & 1) * 8], v);
    }
    __syncthreads();
    if (tid < 128) g_n2p[blockIdx.y * NR + m0 + tid] = n2s[tid];
}

__device__ __forceinline__ float pfun(float q2, float s2, float qs) {
    float d2 = fmaxf(q2 + s2 - 2.f * qs, 0.f);
    float d, p;
    asm("sqrt.approx.f32 %0, %1;" : "=f"(d) : "f"(d2));
    asm("ex2.approx.f32 %0, %1;" : "=f"(p) : "f"((32.f - d) * LOG2E));
    return p;
}

// =============================================================================
// Fused distance/softmax/aggregate. CTA: 128 queries x 2048 supports (sorted).
// K=512 (qh.sh only). 16 n-tiles x 8 K-chunks, 3-stage cp.async pipeline.
// Epilogue: class-run merge (sorted classes) -> few smem atomics.
// =============================================================================
__global__ __launch_bounds__(256, 1) void dist_kernel() {
    extern __shared__ char sm[];
    uint32_t smb = smem_u32(sm);
    const int tid = threadIdx.x, lane = tid & 31, w = tid >> 5, wm = w >> 2, wn = w & 3;
    const int m0 = blockIdx.x * 128, half = blockIdx.y, s0 = half * 2048;
    float* sacc = (float*)(sm + D_SACC);
    float* s2s  = (float*)(sm + D_S2);
    int*   clss = (int*)(sm + D_CLS);
    float* q2s  = (float*)(sm + D_Q2);
    float* lss  = (float*)(sm + D_LS);

    for (int i = tid; i < 128 * 65; i += 256) sacc[i] = 0.f;
    if (tid < 128) {
        q2s[tid] = g_q2f[m0 + tid];
        lss[tid] = 0.f;
        s2s[tid] = g_s2s[s0 + tid];
        clss[tid] = g_clsS[s0 + tid];
    }
    const char* A  = (const char*)g_Q + (size_t)m0 * 1024;
    const char* Sb = (const char*)g_S;

#define LOADG(gg) do { \
        int _s = ((gg) % 3) * STG, _t = (gg) >> 3, _kc = (gg) & 7; \
        load128(smb + _s, A + (size_t)_kc * 128, 1024, tid); \
        load128(smb + _s + 18432, \
                Sb + (size_t)(s0 + _t * 128) * 1024 + (size_t)_kc * 128, 1024, tid); \
    } while (0)

    LOADG(0); CP_COMMIT();
    LOADG(1); CP_COMMIT();

    float c[4][4][4];
#pragma unroll
    for (int i = 0; i < 4; i++)
#pragma unroll
        for (int j = 0; j < 4; j++)
#pragma unroll
            for (int k = 0; k < 4; k++) c[i][j][k] = 0.f;
    float lrow[8];
#pragma unroll
    for (int i = 0; i < 8; i++) lrow[i] = 0.f;
    __syncthreads();
    float q2r[8];
#pragma unroll
    for (int i = 0; i < 8; i++)
        q2r[i] = q2s[wm * 64 + (i >> 1) * 16 + (lane >> 2) + (i & 1) * 8];

    for (int g = 0; g < 128; g++) {
        if (g + 2 < 128) LOADG(g + 2);
        CP_COMMIT(); CP_WAIT2(); __syncthreads();
        int s = (g % 3) * STG;
        compute64(smb + s, smb + s + 18432, wm, wn, lane, c);
        if ((g & 7) == 7) {
            int t = g >> 3, slot = t & 1;
            const float* s2 = s2s + slot * 128;
            const int* cl = clss + slot * 128;
#pragma unroll
            for (int mi = 0; mi < 4; mi++) {
#pragma unroll
                for (int h = 0; h < 2; h++) {
                    int r = wm * 64 + mi * 16 + (lane >> 2) + h * 8;
                    float acc = 0.f, lr = 0.f;
                    int cc = -1;
#pragma unroll
                    for (int ni = 0; ni < 4; ni++) {
#pragma unroll
                        for (int e = 0; e < 2; e++) {
                            int j = wn * 32 + ni * 8 + (lane & 3) * 2 + e;
                            float p = pfun(q2r[2 * mi + h], s2[j], c[mi][ni][2 * h + e]);
                            lr += p;
                            int cj = cl[j];
                            if (cj == cc) {
                                acc += p;
                            } else {
                                if (cc >= 0) atomicAdd(&sacc[r * 65 + cc], acc);
                                cc = cj; acc = p;
                            }
                        }
                    }
                    atomicAdd(&sacc[r * 65 + cc], acc);
                    lrow[2 * mi + h] += lr;
                }
#pragma unroll
                for (int ni = 0; ni < 4; ni++)
                    c[mi][ni][0] = c[mi][ni][1] = c[mi][ni][2] = c[mi][ni][3] = 0.f;
            }
            if (t + 1 < 16 && tid < 128) {
                int sc = s0 + (t + 1) * 128 + tid;
                s2s[((t + 1) & 1) * 128 + tid] = g_s2s[sc];
                clss[((t + 1) & 1) * 128 + tid] = g_clsS[sc];
            }
        }
        __syncthreads();
    }
#pragma unroll
    for (int i = 0; i < 8; i++) {
        float v = lrow[i];
        v += __shfl_xor_sync(~0u, v, 1);
        v += __shfl_xor_sync(~0u, v, 2);
        if ((lane & 3) == 0)
            atomicAdd(&lss[wm * 64 + (i >> 1) * 16 + (lane >> 2) + (i & 1) * 8], v);
    }
    __syncthreads();
    for (int i = tid; i < 128 * 64; i += 256) {
        int r = i >> 6, cc = i & 63;
        g_pnum[(size_t)half * NQ * NC + (size_t)(m0 + r) * NC + cc] = sacc[r * 65 + cc];
    }
    if (tid < 128) g_pden[half * NQ + m0 + tid] = lss[tid];
#undef LOADG
}

// =============================================================================
// Finalize
// =============================================================================
__global__ void fin_kernel(float* __restrict__ out) {
    int i = blockIdx.x * blockDim.x + threadIdx.x;
    if (i >= NQ * NC) return;
    int q = i >> 6;
    out[i] = (g_pnum[i] + g_pnum[(size_t)NQ * NC + i]) / (g_pden[q] + g_pden[NQ + q]);
}

// =============================================================================
// Launch
// =============================================================================
extern "C" void kernel_launch(void* const* d_in, const int* in_sizes, int n_in,
                              void* d_out, int out_size) {
    const float* support = (const float*)d_in[0];
    const float* query   = (const float*)d_in[1];
    const float* labels  = (const float*)d_in[2];
    const float* W       = (const float*)d_in[3];
    const float* b       = (const float*)d_in[4];
    float* out = (float*)d_out;

    cudaFuncSetAttribute(enc_kernel,  cudaFuncAttributeMaxDynamicSharedMemorySize, SMEM_ENC);
    cudaFuncSetAttribute(dist_kernel, cudaFuncAttributeMaxDynamicSharedMemorySize, SMEM_DIST);

    prep_x<<<NR, 128>>>(support, query);
    prep_w<<<EMB, 128>>>(W);
    cls_kernel<<<NS / 256, 256>>>(labels);
    rank_kernel<<<NS / 128, 128>>>();
    enc_kernel<<<dim3(NR / 128, EMB / 128), 256, SMEM_ENC>>>(b);
    meta_kernel<<<(NS + NQ) / 256, 256>>>();
    dist_kernel<<<dim3(NQ / 128, 2), 256, SMEM_DIST>>>();
    fin_kernel<<<(NQ * NC + 255) / 256, 256>>>(out);
}

// round 7
// speedup vs baseline: 2.7094x; 1.0219x over previous
#include <cuda_runtime.h>
#include <cuda_fp16.h>
#include <cstdint>

#define NS 4096
#define NQ 8192
#define NR 12288
#define IND 784
#define EMB 512
#define NC 64
#define KE 1600          // 2*784 = 1568 padded to 64
#define LOG2E 1.4426950408889634f

// ------------------------- device scratch -----------------------------------
__device__ __align__(128) __half g_X[(size_t)NR * KE];      // [xh|xl]
__device__ __align__(128) __half g_W[(size_t)EMB * KE];     // [wh|wh] (W^T rows)
__device__ __align__(128) __half g_Q[(size_t)NQ * 512];     // qh (1024 B/row)
__device__ __align__(128) __half g_S[(size_t)NS * 512];     // sh, class-sorted rows
__device__ float g_n2p[4 * NR];
__device__ int   g_rank[NS];     // original idx -> sorted pos
__device__ int   g_inv[NS];      // sorted pos -> original idx
__device__ int   g_clsS[NS];     // class at sorted pos
__device__ float g_pnum[2 * (size_t)NQ * NC];
__device__ float g_pden[2 * NQ];

// ------------------------- helpers ------------------------------------------
__device__ __forceinline__ uint32_t smem_u32(const void* p) {
    uint32_t a;
    asm("{ .reg .u64 t; cvta.to.shared.u64 t, %1; cvt.u32.u64 %0, t; }" : "=r"(a) : "l"(p));
    return a;
}
#define CP_COMMIT() asm volatile("cp.async.commit_group;" ::: "memory")
#define CP_WAIT2()  asm volatile("cp.async.wait_group 2;" ::: "memory")

__device__ __forceinline__ void ldm4(uint32_t r[4], uint32_t addr) {
    asm volatile("ldmatrix.sync.aligned.m8n8.x4.shared.b16 {%0,%1,%2,%3}, [%4];"
                 : "=r"(r[0]), "=r"(r[1]), "=r"(r[2]), "=r"(r[3]) : "r"(addr));
}
__device__ __forceinline__ void mma16816(float c[4], uint32_t a0, uint32_t a1, uint32_t a2,
                                         uint32_t a3, uint32_t b0, uint32_t b1) {
    asm volatile(
        "mma.sync.aligned.m16n8k16.row.col.f32.f16.f16.f32 "
        "{%0,%1,%2,%3}, {%4,%5,%6,%7}, {%8,%9}, {%0,%1,%2,%3};"
        : "+f"(c[0]), "+f"(c[1]), "+f"(c[2]), "+f"(c[3])
        : "r"(a0), "r"(a1), "r"(a2), "r"(a3), "r"(b0), "r"(b1));
}

// 64 rows x 64 halfs (128B) global -> smem (stride 144B)
__device__ __forceinline__ void load64(uint32_t sdst, const char* g, size_t rs, int tid) {
#pragma unroll
    for (int i = 0; i < 2; i++) {
        int u = tid + (i << 8), r = u >> 3, j = u & 7;
        asm volatile("cp.async.cg.shared.global [%0], [%1], 16;"
                     :: "r"(sdst + r * 144 + j * 16), "l"(g + (size_t)r * rs + j * 16) : "memory");
    }
}
// 128 rows x 64 halfs
__device__ __forceinline__ void load128(uint32_t sdst, const char* g, size_t rs, int tid) {
#pragma unroll
    for (int i = 0; i < 4; i++) {
        int u = tid + (i << 8), r = u >> 3, j = u & 7;
        asm volatile("cp.async.cg.shared.global [%0], [%1], 16;"
                     :: "r"(sdst + r * 144 + j * 16), "l"(g + (size_t)r * rs + j * 16) : "memory");
    }
}

// One BK=64 chunk: Cwarp[32x32] over A tile 64 rows, B tile 128 rows.
// ldmatrix x4 + register double buffer. c[2][4][4].
__device__ __forceinline__ void compute64(uint32_t smA, uint32_t smB, int wm, int wn, int lane,
                                          float c[2][4][4]) {
    uint32_t aRow = smA + (uint32_t)((wm * 32 + (lane & 15)) * 144 + (lane >> 4) * 16);
    uint32_t bRow = smB + (uint32_t)((wn * 32 + (lane >> 4) * 8 + (lane & 7)) * 144
                                     + ((lane >> 3) & 1) * 16);
    uint32_t af[2][2][4], bf[2][2][4];
#pragma unroll
    for (int mi = 0; mi < 2; mi++) ldm4(af[0][mi], aRow + mi * 2304);
#pragma unroll
    for (int q = 0; q < 2; q++) ldm4(bf[0][q], bRow + q * 2304);
#pragma unroll
    for (int ks = 0; ks < 4; ks++) {
        int cur = ks & 1, nxt = cur ^ 1;
        if (ks < 3) {
            uint32_t ko = (uint32_t)(ks + 1) * 32;
#pragma unroll
            for (int mi = 0; mi < 2; mi++) ldm4(af[nxt][mi], aRow + mi * 2304 + ko);
#pragma unroll
            for (int q = 0; q < 2; q++) ldm4(bf[nxt][q], bRow + q * 2304 + ko);
        }
#pragma unroll
        for (int mi = 0; mi < 2; mi++)
#pragma unroll
            for (int ni = 0; ni < 4; ni++)
                mma16816(c[mi][ni], af[cur][mi][0], af[cur][mi][1], af[cur][mi][2],
                         af[cur][mi][3], bf[cur][ni >> 1][(ni & 1) * 2],
                         bf[cur][ni >> 1][(ni & 1) * 2 + 1]);
    }
}

// ------------------------- smem layouts -------------------------------------
#define STG 27648                  // A 9216 + B 18432; 3 stages = 82944
#define E_BIAS 82944
#define E_N2   83456
#define SMEM_ENC 83712
#define D_SACC 82944               // 64*65 f32 = 16640
#define D_S2   99584               // 2*128 f32
#define D_CLS  100608              // 2*128 int
#define D_Q2   101632              // 64 f32
#define D_LS   101888              // 64 f32
#define SMEM_DIST 102144

// =============================================================================
// Prep: hi/lo split of X (NR rows) and W^T (EMB rows)
// =============================================================================
__global__ void prep_kernel(const float* __restrict__ sup, const float* __restrict__ qry,
                            const float* __restrict__ W) {
    int bid = blockIdx.x;
    if (bid < NR) {
        const float* src = bid < NS ? sup + (size_t)bid * IND : qry + (size_t)(bid - NS) * IND;
        __half* dst = g_X + (size_t)bid * KE;
        for (int c = threadIdx.x; c < IND; c += 128) {
            float x = src[c];
            __half h = __float2half_rn(x);
            dst[c] = h;
            dst[IND + c] = __float2half_rn(x - __half2float(h));
        }
        if (threadIdx.x < KE - 2 * IND) dst[2 * IND + threadIdx.x] = __ushort_as_half(0);
    } else {
        int n = bid - NR;
        __half* dst = g_W + (size_t)n * KE;
        for (int k = threadIdx.x; k < IND; k += 128) {
            __half h = __float2half_rn(W[(size_t)k * EMB + n]);
            dst[k] = h;
            dst[IND + k] = h;
        }
        if (threadIdx.x < KE - 2 * IND) dst[2 * IND + threadIdx.x] = __ushort_as_half(0);
    }
}

// =============================================================================
// Class extraction + deterministic stable counting sort.
// Block b handles class b: rank[j] = #{cls<b} + #{j'<j : cls_j'==b}.
// =============================================================================
__global__ __launch_bounds__(256) void clsrank_kernel(const float* __restrict__ labels) {
    __shared__ int cl[NS];
    __shared__ int eqs[256], lts[256];
    const int b = blockIdx.x, tid = threadIdx.x;
    for (int idx = tid; idx < NS * NC; idx += 256)
        if (labels[idx] > 0.5f) cl[idx >> 6] = idx & 63;
    __syncthreads();
    int e0 = 0, l0 = 0;
    const int j0 = tid * 16;
#pragma unroll
    for (int e = 0; e < 16; e++) {
        int c = cl[j0 + e];
        e0 += (c == b);
        l0 += (c < b);
    }
    eqs[tid] = e0; lts[tid] = l0;
    __syncthreads();
    for (int off = 1; off < 256; off <<= 1) {
        int ve = (tid >= off) ? eqs[tid - off] : 0;
        int vl = (tid >= off) ? lts[tid - off] : 0;
        __syncthreads();
        eqs[tid] += ve; lts[tid] += vl;
        __syncthreads();
    }
    int r = lts[255] + eqs[tid] - e0;   // base + exclusive prefix
    for (int e = 0; e < 16; e++) {
        int j = j0 + e;
        if (cl[j] == b) {
            g_rank[j] = r;
            g_inv[r] = j;
            g_clsS[r] = b;
            r++;
        }
    }
}

// =============================================================================
// Encoder: D[64x128] = X[m0..][K] * W^T[n0..][K],  K=1600, fp16 2-term split
// =============================================================================
__global__ __launch_bounds__(256, 2) void enc_kernel(const float* __restrict__ bias) {
    extern __shared__ char sm[];
    uint32_t smb = smem_u32(sm);
    const int tid = threadIdx.x, lane = tid & 31, w = tid >> 5, wm = w >> 2, wn = w & 3;
    const int m0 = blockIdx.x * 64, n0 = blockIdx.y * 128;
    float* biasS = (float*)(sm + E_BIAS);
    float* n2s = (float*)(sm + E_N2);
    if (tid < 128) biasS[tid] = bias[n0 + tid];
    if (tid < 64) n2s[tid] = 0.f;

    const char* A = (const char*)g_X + (size_t)m0 * (KE * 2);
    const char* B = (const char*)g_W + (size_t)n0 * (KE * 2);
    const int G = KE / 64;  // 25
    load64(smb, A, KE * 2, tid);
    load128(smb + 9216, B, KE * 2, tid); CP_COMMIT();
    load64(smb + STG, A + 128, KE * 2, tid);
    load128(smb + STG + 9216, B + 128, KE * 2, tid); CP_COMMIT();

    float c[2][4][4];
#pragma unroll
    for (int i = 0; i < 2; i++)
#pragma unroll
        for (int j = 0; j < 4; j++)
#pragma unroll
            for (int k = 0; k < 4; k++) c[i][j][k] = 0.f;
    __syncthreads();

    for (int g = 0; g < G; g++) {
        if (g + 2 < G) {
            int s = ((g + 2) % 3) * STG;
            load64(smb + s, A + (size_t)(g + 2) * 128, KE * 2, tid);
            load128(smb + s + 9216, B + (size_t)(g + 2) * 128, KE * 2, tid);
        }
        CP_COMMIT(); CP_WAIT2(); __syncthreads();
        int s = (g % 3) * STG;
        compute64(smb + s, smb + s + 9216, wm, wn, lane, c);
        __syncthreads();
    }

    float vsq[4];
#pragma unroll
    for (int i = 0; i < 4; i++) vsq[i] = 0.f;
#pragma unroll
    for (int mi = 0; mi < 2; mi++) {
        int r0 = wm * 32 + mi * 16 + (lane >> 2);
#pragma unroll
        for (int ni = 0; ni < 4; ni++) {
            int cn = wn * 32 + ni * 8 + (lane & 3) * 2;
            float b0 = biasS[cn], b1 = biasS[cn + 1];
            float v0 = c[mi][ni][0] + b0, v1 = c[mi][ni][1] + b1;
            float v2 = c[mi][ni][2] + b0, v3 = c[mi][ni][3] + b1;
            vsq[2 * mi] += v0 * v0 + v1 * v1;
            vsq[2 * mi + 1] += v2 * v2 + v3 * v3;
#pragma unroll
            for (int h = 0; h < 2; h++) {
                float x0 = h ? v2 : v0, x1 = h ? v3 : v1;
                int rg = m0 + r0 + h * 8, col = n0 + cn;
                __half h0 = __float2half_rn(x0), h1 = __float2half_rn(x1);
                uint32_t hp = ((uint32_t)__half_as_ushort(h1) << 16) | __half_as_ushort(h0);
                if (rg < NS) {
                    int sr = g_rank[rg];
                    ((uint32_t*)(g_S + (size_t)sr * 512))[col >> 1] = hp;
                } else {
                    ((uint32_t*)(g_Q + (size_t)(rg - NS) * 512))[col >> 1] = hp;
                }
            }
        }
    }
#pragma unroll
    for (int i = 0; i < 4; i++) {
        float v = vsq[i];
        v += __shfl_xor_sync(~0u, v, 1);
        v += __shfl_xor_sync(~0u, v, 2);
        if ((lane & 3) == 0)
            atomicAdd(&n2s[wm * 32 + (i >> 1) * 16 + (lane >> 2) + (i & 1) * 8], v);
    }
    __syncthreads();
    if (tid < 64) g_n2p[blockIdx.y * NR + m0 + tid] = n2s[tid];
}

__device__ __forceinline__ float pfun(float q2, float s2, float qs) {
    float d2 = fmaxf(q2 + s2 - 2.f * qs, 0.f);
    float d, p;
    asm("sqrt.approx.f32 %0, %1;" : "=f"(d) : "f"(d2));
    asm("ex2.approx.f32 %0, %1;" : "=f"(p) : "f"((32.f - d) * LOG2E));
    return p;
}

// =============================================================================
// Fused distance/softmax/aggregate. CTA: 64 queries x 2048 supports (sorted).
// K=512. 16 n-tiles x 8 K-chunks, 3-stage cp.async pipeline, 2 CTAs/SM.
// =============================================================================
__global__ __launch_bounds__(256, 2) void dist_kernel() {
    extern __shared__ char sm[];
    uint32_t smb = smem_u32(sm);
    const int tid = threadIdx.x, lane = tid & 31, w = tid >> 5, wm = w >> 2, wn = w & 3;
    const int m0 = blockIdx.x * 64, half = blockIdx.y, s0 = half * 2048;
    float* sacc  = (float*)(sm + D_SACC);
    float* s2s   = (float*)(sm + D_S2);
    int*   clss  = (int*)(sm + D_CLS);
    float* q2s   = (float*)(sm + D_Q2);
    float* lsums = (float*)(sm + D_LS);

    for (int i = tid; i < 64 * 65; i += 256) sacc[i] = 0.f;
    if (tid < 64) {
        int qr = NS + m0 + tid;
        q2s[tid] = g_n2p[qr] + g_n2p[NR + qr] + g_n2p[2 * NR + qr] + g_n2p[3 * NR + qr];
        lsums[tid] = 0.f;
    }
    if (tid < 128) {
        int sc = s0 + tid, o = g_inv[sc];
        s2s[tid] = g_n2p[o] + g_n2p[NR + o] + g_n2p[2 * NR + o] + g_n2p[3 * NR + o];
        clss[tid] = g_clsS[sc];
    }
    const char* A  = (const char*)g_Q + (size_t)m0 * 1024;
    const char* Sb = (const char*)g_S;

#define LOADG(gg) do { \
        int _s = ((gg) % 3) * STG, _t = (gg) >> 3, _kc = (gg) & 7; \
        load64(smb + _s, A + (size_t)_kc * 128, 1024, tid); \
        load128(smb + _s + 9216, \
                Sb + (size_t)(s0 + _t * 128) * 1024 + (size_t)_kc * 128, 1024, tid); \
    } while (0)

    LOADG(0); CP_COMMIT();
    LOADG(1); CP_COMMIT();

    float c[2][4][4];
#pragma unroll
    for (int i = 0; i < 2; i++)
#pragma unroll
        for (int j = 0; j < 4; j++)
#pragma unroll
            for (int k = 0; k < 4; k++) c[i][j][k] = 0.f;
    float lrow[4];
#pragma unroll
    for (int i = 0; i < 4; i++) lrow[i] = 0.f;
    __syncthreads();
    float q2r[4];
#pragma unroll
    for (int i = 0; i < 4; i++)
        q2r[i] = q2s[wm * 32 + (i >> 1) * 16 + (lane >> 2) + (i & 1) * 8];

    for (int g = 0; g < 128; g++) {
        if (g + 2 < 128) LOADG(g + 2);
        CP_COMMIT(); CP_WAIT2(); __syncthreads();
        int s = (g % 3) * STG;
        compute64(smb + s, smb + s + 9216, wm, wn, lane, c);
        if ((g & 7) == 7) {
            int t = g >> 3, slot = t & 1;
            const float* s2 = s2s + slot * 128;
            const int* cl = clss + slot * 128;
#pragma unroll
            for (int mi = 0; mi < 2; mi++) {
#pragma unroll
                for (int h = 0; h < 2; h++) {
                    int r = wm * 32 + mi * 16 + (lane >> 2) + h * 8;
                    float acc = 0.f, lr = 0.f;
                    int cc = -1;
#pragma unroll
                    for (int ni = 0; ni < 4; ni++) {
#pragma unroll
                        for (int e = 0; e < 2; e++) {
                            int j = wn * 32 + ni * 8 + (lane & 3) * 2 + e;
                            float p = pfun(q2r[2 * mi + h], s2[j], c[mi][ni][2 * h + e]);
                            lr += p;
                            int cj = cl[j];
                            if (cj == cc) {
                                acc += p;
                            } else {
                                if (cc >= 0) atomicAdd(&sacc[r * 65 + cc], acc);
                                cc = cj; acc = p;
                            }
                        }
                    }
                    atomicAdd(&sacc[r * 65 + cc], acc);
                    lrow[2 * mi + h] += lr;
                }
#pragma unroll
                for (int ni = 0; ni < 4; ni++)
                    c[mi][ni][0] = c[mi][ni][1] = c[mi][ni][2] = c[mi][ni][3] = 0.f;
            }
            if (t + 1 < 16 && tid < 128) {
                int sc = s0 + (t + 1) * 128 + tid, o = g_inv[sc];
                s2s[((t + 1) & 1) * 128 + tid] =
                    g_n2p[o] + g_n2p[NR + o] + g_n2p[2 * NR + o] + g_n2p[3 * NR + o];
                clss[((t + 1) & 1) * 128 + tid] = g_clsS[sc];
            }
        }
        __syncthreads();
    }
#pragma unroll
    for (int i = 0; i < 4; i++) {
        float v = lrow[i];
        v += __shfl_xor_sync(~0u, v, 1);
        v += __shfl_xor_sync(~0u, v, 2);
        if ((lane & 3) == 0)
            atomicAdd(&lsums[wm * 32 + (i >> 1) * 16 + (lane >> 2) + (i & 1) * 8], v);
    }
    __syncthreads();
    for (int i = tid; i < 64 * 64; i += 256) {
        int r = i >> 6, cc = i & 63;
        g_pnum[(size_t)half * NQ * NC + (size_t)(m0 + r) * NC + cc] = sacc[r * 65 + cc];
    }
    if (tid < 64) g_pden[half * NQ + m0 + tid] = lsums[tid];
#undef LOADG
}

// =============================================================================
// Finalize
// =============================================================================
__global__ void fin_kernel(float* __restrict__ out) {
    int i = blockIdx.x * blockDim.x + threadIdx.x;
    if (i >= NQ * NC) return;
    int q = i >> 6;
    out[i] = (g_pnum[i] + g_pnum[(size_t)NQ * NC + i]) / (g_pden[q] + g_pden[NQ + q]);
}

// =============================================================================
// Launch: prep(0), clsrank(1), enc(2), dist(3), fin(4)
// =============================================================================
extern "C" void kernel_launch(void* const* d_in, const int* in_sizes, int n_in,
                              void* d_out, int out_size) {
    const float* support = (const float*)d_in[0];
    const float* query   = (const float*)d_in[1];
    const float* labels  = (const float*)d_in[2];
    const float* W       = (const float*)d_in[3];
    const float* b       = (const float*)d_in[4];
    float* out = (float*)d_out;

    cudaFuncSetAttribute(enc_kernel,  cudaFuncAttributeMaxDynamicSharedMemorySize, SMEM_ENC);
    cudaFuncSetAttribute(dist_kernel, cudaFuncAttributeMaxDynamicSharedMemorySize, SMEM_DIST);

    prep_kernel<<<NR + EMB, 128>>>(support, query, W);
    clsrank_kernel<<<NC, 256>>>(labels);
    enc_kernel<<<dim3(NR / 64, EMB / 128), 256, SMEM_ENC>>>(b);
    dist_kernel<<<dim3(NQ / 64, 2), 256, SMEM_DIST>>>();
    fin_kernel<<<(NQ * NC + 255) / 256, 256>>>(out);
}

// round 8
// speedup vs baseline: 3.0121x; 1.1117x over previous
#include <cuda_runtime.h>
#include <cuda_fp16.h>
#include <cstdint>

#define NS 4096
#define NQ 8192
#define NR 12288
#define IND 784
#define EMB 512
#define NC 64
#define KE 1600          // 2*784 = 1568 padded to 64
#define LOG2E 1.4426950408889634f

// ------------------------- device scratch -----------------------------------
__device__ __align__(128) __half g_X[(size_t)NR * KE];      // [xh|xl]
__device__ __align__(128) __half g_W[(size_t)EMB * KE];     // [wh|wh] (W^T rows)
__device__ __align__(128) __half g_Q[(size_t)NQ * 512];     // qh (1024 B/row)
__device__ __align__(128) __half g_S[(size_t)NS * 512];     // sh, class-sorted rows
__device__ float g_n2p[4 * NR];
__device__ int   g_rank[NS];     // original idx -> sorted pos
__device__ int   g_inv[NS];      // sorted pos -> original idx
__device__ int   g_clsS[NS];     // class at sorted pos
__device__ float g_pnum[2 * (size_t)NQ * NC];
__device__ float g_pden[2 * NQ];

// ------------------------- helpers ------------------------------------------
__device__ __forceinline__ uint32_t smem_u32(const void* p) {
    uint32_t a;
    asm("{ .reg .u64 t; cvta.to.shared.u64 t, %1; cvt.u32.u64 %0, t; }" : "=r"(a) : "l"(p));
    return a;
}
#define CP_COMMIT() asm volatile("cp.async.commit_group;" ::: "memory")
#define CP_WAIT1()  asm volatile("cp.async.wait_group 1;" ::: "memory")

__device__ __forceinline__ void ldm4(uint32_t r[4], uint32_t addr) {
    asm volatile("ldmatrix.sync.aligned.m8n8.x4.shared.b16 {%0,%1,%2,%3}, [%4];"
                 : "=r"(r[0]), "=r"(r[1]), "=r"(r[2]), "=r"(r[3]) : "r"(addr));
}
__device__ __forceinline__ void mma16816(float c[4], uint32_t a0, uint32_t a1, uint32_t a2,
                                         uint32_t a3, uint32_t b0, uint32_t b1) {
    asm volatile(
        "mma.sync.aligned.m16n8k16.row.col.f32.f16.f16.f32 "
        "{%0,%1,%2,%3}, {%4,%5,%6,%7}, {%8,%9}, {%0,%1,%2,%3};"
        : "+f"(c[0]), "+f"(c[1]), "+f"(c[2]), "+f"(c[3])
        : "r"(a0), "r"(a1), "r"(a2), "r"(a3), "r"(b0), "r"(b1));
}

// 64 rows x 64 halfs (128B) global -> smem (stride 144B), 32-bit offsets
__device__ __forceinline__ void load64(uint32_t sdst, const char* gbase, uint32_t goff,
                                       uint32_t rs, int tid) {
#pragma unroll
    for (int i = 0; i < 2; i++) {
        int u = tid + (i << 8), r = u >> 3, j = u & 7;
        asm volatile("cp.async.cg.shared.global [%0], [%1], 16;"
                     :: "r"(sdst + r * 144 + j * 16),
                        "l"(gbase + goff + (uint32_t)r * rs + j * 16) : "memory");
    }
}
__device__ __forceinline__ void load128(uint32_t sdst, const char* gbase, uint32_t goff,
                                        uint32_t rs, int tid) {
#pragma unroll
    for (int i = 0; i < 4; i++) {
        int u = tid + (i << 8), r = u >> 3, j = u & 7;
        asm volatile("cp.async.cg.shared.global [%0], [%1], 16;"
                     :: "r"(sdst + r * 144 + j * 16),
                        "l"(gbase + goff + (uint32_t)r * rs + j * 16) : "memory");
    }
}

// One BK=64 chunk: Cwarp[32x32] over A tile 64 rows, B tile 128 rows.
__device__ __forceinline__ void compute64(uint32_t smA, uint32_t smB, int wm, int wn, int lane,
                                          float c[2][4][4]) {
    uint32_t aRow = smA + (uint32_t)((wm * 32 + (lane & 15)) * 144 + (lane >> 4) * 16);
    uint32_t bRow = smB + (uint32_t)((wn * 32 + (lane >> 4) * 8 + (lane & 7)) * 144
                                     + ((lane >> 3) & 1) * 16);
    uint32_t af[2][2][4], bf[2][2][4];
#pragma unroll
    for (int mi = 0; mi < 2; mi++) ldm4(af[0][mi], aRow + mi * 2304);
#pragma unroll
    for (int q = 0; q < 2; q++) ldm4(bf[0][q], bRow + q * 2304);
#pragma unroll
    for (int ks = 0; ks < 4; ks++) {
        int cur = ks & 1, nxt = cur ^ 1;
        if (ks < 3) {
            uint32_t ko = (uint32_t)(ks + 1) * 32;
#pragma unroll
            for (int mi = 0; mi < 2; mi++) ldm4(af[nxt][mi], aRow + mi * 2304 + ko);
#pragma unroll
            for (int q = 0; q < 2; q++) ldm4(bf[nxt][q], bRow + q * 2304 + ko);
        }
#pragma unroll
        for (int mi = 0; mi < 2; mi++)
#pragma unroll
            for (int ni = 0; ni < 4; ni++)
                mma16816(c[mi][ni], af[cur][mi][0], af[cur][mi][1], af[cur][mi][2],
                         af[cur][mi][3], bf[cur][ni >> 1][(ni & 1) * 2],
                         bf[cur][ni >> 1][(ni & 1) * 2 + 1]);
    }
}

// ------------------------- smem layouts -------------------------------------
#define STG 27648                  // A 9216 + B 18432; 3 stages = 82944
#define E_BIAS 82944
#define E_N2   83456
#define SMEM_ENC 83712
#define D_SACC 82944               // 64*65 f32 = 16640
#define D_S2   99584               // 2*128 f32
#define D_CLS  100608              // 2*128 int
#define D_Q2   101632              // 64 f32
#define D_LS   101888              // 64 f32
#define SMEM_DIST 102144

// =============================================================================
// Prep: hi/lo split of X (NR rows) and W^T (EMB rows)
// =============================================================================
__global__ void prep_kernel(const float* __restrict__ sup, const float* __restrict__ qry,
                            const float* __restrict__ W) {
    int bid = blockIdx.x;
    if (bid < NR) {
        const float* src = bid < NS ? sup + (size_t)bid * IND : qry + (size_t)(bid - NS) * IND;
        __half* dst = g_X + (size_t)bid * KE;
        for (int c = threadIdx.x; c < IND; c += 128) {
            float x = src[c];
            __half h = __float2half_rn(x);
            dst[c] = h;
            dst[IND + c] = __float2half_rn(x - __half2float(h));
        }
        if (threadIdx.x < KE - 2 * IND) dst[2 * IND + threadIdx.x] = __ushort_as_half(0);
    } else {
        int n = bid - NR;
        __half* dst = g_W + (size_t)n * KE;
        for (int k = threadIdx.x; k < IND; k += 128) {
            __half h = __float2half_rn(W[(size_t)k * EMB + n]);
            dst[k] = h;
            dst[IND + k] = h;
        }
        if (threadIdx.x < KE - 2 * IND) dst[2 * IND + threadIdx.x] = __ushort_as_half(0);
    }
}

// =============================================================================
// Class extraction + deterministic stable counting sort (block b = class b).
// =============================================================================
__global__ __launch_bounds__(256) void clsrank_kernel(const float* __restrict__ labels) {
    __shared__ int cl[NS];
    __shared__ int eqs[256], lts[256];
    const int b = blockIdx.x, tid = threadIdx.x;
    for (int idx = tid; idx < NS * NC; idx += 256)
        if (labels[idx] > 0.5f) cl[idx >> 6] = idx & 63;
    __syncthreads();
    int e0 = 0, l0 = 0;
    const int j0 = tid * 16;
#pragma unroll
    for (int e = 0; e < 16; e++) {
        int c = cl[j0 + e];
        e0 += (c == b);
        l0 += (c < b);
    }
    eqs[tid] = e0; lts[tid] = l0;
    __syncthreads();
    for (int off = 1; off < 256; off <<= 1) {
        int ve = (tid >= off) ? eqs[tid - off] : 0;
        int vl = (tid >= off) ? lts[tid - off] : 0;
        __syncthreads();
        eqs[tid] += ve; lts[tid] += vl;
        __syncthreads();
    }
    int r = lts[255] + eqs[tid] - e0;
    for (int e = 0; e < 16; e++) {
        int j = j0 + e;
        if (cl[j] == b) {
            g_rank[j] = r;
            g_inv[r] = j;
            g_clsS[r] = b;
            r++;
        }
    }
}

// =============================================================================
// Encoder: D[64x128] = X[m0..][K] * W^T[n0..][K],  K=1600, fp16 2-term split
// Single-barrier mainloop.
// =============================================================================
__global__ __launch_bounds__(256, 2) void enc_kernel(const float* __restrict__ bias) {
    extern __shared__ char sm[];
    uint32_t smb = smem_u32(sm);
    const int tid = threadIdx.x, lane = tid & 31, w = tid >> 5, wm = w >> 2, wn = w & 3;
    const int m0 = blockIdx.x * 64, n0 = blockIdx.y * 128;
    float* biasS = (float*)(sm + E_BIAS);
    float* n2s = (float*)(sm + E_N2);
    if (tid < 128) biasS[tid] = bias[n0 + tid];
    if (tid < 64) n2s[tid] = 0.f;

    const char* A = (const char*)g_X + (size_t)m0 * (KE * 2);
    const char* B = (const char*)g_W + (size_t)n0 * (KE * 2);
    const int G = KE / 64;  // 25
    load64(smb, A, 0, KE * 2, tid);
    load128(smb + 9216, B, 0, KE * 2, tid); CP_COMMIT();
    load64(smb + STG, A, 128, KE * 2, tid);
    load128(smb + STG + 9216, B, 128, KE * 2, tid); CP_COMMIT();

    float c[2][4][4];
#pragma unroll
    for (int i = 0; i < 2; i++)
#pragma unroll
        for (int j = 0; j < 4; j++)
#pragma unroll
            for (int k = 0; k < 4; k++) c[i][j][k] = 0.f;

    for (int g = 0; g < G; g++) {
        CP_WAIT1(); __syncthreads();
        int s = (g % 3) * STG;
        compute64(smb + s, smb + s + 9216, wm, wn, lane, c);
        if (g + 2 < G) {
            int s2 = ((g + 2) % 3) * STG;
            load64(smb + s2, A, (uint32_t)(g + 2) * 128, KE * 2, tid);
            load128(smb + s2 + 9216, B, (uint32_t)(g + 2) * 128, KE * 2, tid);
        }
        CP_COMMIT();
    }

    float vsq[4];
#pragma unroll
    for (int i = 0; i < 4; i++) vsq[i] = 0.f;
#pragma unroll
    for (int mi = 0; mi < 2; mi++) {
        int r0 = wm * 32 + mi * 16 + (lane >> 2);
#pragma unroll
        for (int ni = 0; ni < 4; ni++) {
            int cn = wn * 32 + ni * 8 + (lane & 3) * 2;
            float b0 = biasS[cn], b1 = biasS[cn + 1];
            float v0 = c[mi][ni][0] + b0, v1 = c[mi][ni][1] + b1;
            float v2 = c[mi][ni][2] + b0, v3 = c[mi][ni][3] + b1;
            vsq[2 * mi] += v0 * v0 + v1 * v1;
            vsq[2 * mi + 1] += v2 * v2 + v3 * v3;
#pragma unroll
            for (int h = 0; h < 2; h++) {
                float x0 = h ? v2 : v0, x1 = h ? v3 : v1;
                int rg = m0 + r0 + h * 8, col = n0 + cn;
                __half h0 = __float2half_rn(x0), h1 = __float2half_rn(x1);
                uint32_t hp = ((uint32_t)__half_as_ushort(h1) << 16) | __half_as_ushort(h0);
                if (rg < NS) {
                    int sr = g_rank[rg];
                    ((uint32_t*)(g_S + (size_t)sr * 512))[col >> 1] = hp;
                } else {
                    ((uint32_t*)(g_Q + (size_t)(rg - NS) * 512))[col >> 1] = hp;
                }
            }
        }
    }
#pragma unroll
    for (int i = 0; i < 4; i++) {
        float v = vsq[i];
        v += __shfl_xor_sync(~0u, v, 1);
        v += __shfl_xor_sync(~0u, v, 2);
        if ((lane & 3) == 0)
            atomicAdd(&n2s[wm * 32 + (i >> 1) * 16 + (lane >> 2) + (i & 1) * 8], v);
    }
    __syncthreads();
    if (tid < 64) g_n2p[blockIdx.y * NR + m0 + tid] = n2s[tid];
}

__device__ __forceinline__ float pfun(float q2, float s2, float qs) {
    float d2 = fmaxf(q2 + s2 - 2.f * qs, 0.f);
    float d, p;
    asm("sqrt.approx.f32 %0, %1;" : "=f"(d) : "f"(d2));
    asm("ex2.approx.f32 %0, %1;" : "=f"(p) : "f"((32.f - d) * LOG2E));
    return p;
}

// =============================================================================
// Fused distance/softmax/aggregate. CTA: 64 queries x 2048 supports (sorted).
// K=512. 16 n-tiles x 8 K-chunks. Single-barrier 3-stage pipeline, 2 CTAs/SM.
// Epilogue fast path: whole thread-slice in one class -> 1 atomic.
// =============================================================================
__global__ __launch_bounds__(256, 2) void dist_kernel() {
    extern __shared__ char sm[];
    uint32_t smb = smem_u32(sm);
    const int tid = threadIdx.x, lane = tid & 31, w = tid >> 5, wm = w >> 2, wn = w & 3;
    const int m0 = blockIdx.x * 64, half = blockIdx.y, s0 = half * 2048;
    float* sacc  = (float*)(sm + D_SACC);
    float* s2s   = (float*)(sm + D_S2);
    int*   clss  = (int*)(sm + D_CLS);
    float* q2s   = (float*)(sm + D_Q2);
    float* lsums = (float*)(sm + D_LS);

    for (int i = tid; i < 64 * 65; i += 256) sacc[i] = 0.f;
    if (tid < 64) {
        int qr = NS + m0 + tid;
        q2s[tid] = g_n2p[qr] + g_n2p[NR + qr] + g_n2p[2 * NR + qr] + g_n2p[3 * NR + qr];
        lsums[tid] = 0.f;
    }
    if (tid < 128) {
        int sc = s0 + tid, o = g_inv[sc];
        s2s[tid] = g_n2p[o] + g_n2p[NR + o] + g_n2p[2 * NR + o] + g_n2p[3 * NR + o];
        clss[tid] = g_clsS[sc];
    }
    const char* A  = (const char*)g_Q + (size_t)m0 * 1024;
    const char* Sb = (const char*)g_S + (size_t)s0 * 1024;

#define LOADG(gg) do { \
        int _s = ((gg) % 3) * STG; \
        uint32_t _t = (uint32_t)(gg) >> 3, _kc = (uint32_t)(gg) & 7; \
        load64(smb + _s, A, _kc * 128, 1024, tid); \
        load128(smb + _s + 9216, Sb, _t * 131072 + _kc * 128, 1024, tid); \
    } while (0)

    LOADG(0); CP_COMMIT();
    LOADG(1); CP_COMMIT();

    float c[2][4][4];
#pragma unroll
    for (int i = 0; i < 2; i++)
#pragma unroll
        for (int j = 0; j < 4; j++)
#pragma unroll
            for (int k = 0; k < 4; k++) c[i][j][k] = 0.f;
    float lrow[4];
#pragma unroll
    for (int i = 0; i < 4; i++) lrow[i] = 0.f;
    __syncthreads();
    float q2r[4];
#pragma unroll
    for (int i = 0; i < 4; i++)
        q2r[i] = q2s[wm * 32 + (i >> 1) * 16 + (lane >> 2) + (i & 1) * 8];

    const int jb = wn * 32 + (lane & 3) * 2;

    for (int g = 0; g < 128; g++) {
        CP_WAIT1(); __syncthreads();
        int s = (g % 3) * STG;
        compute64(smb + s, smb + s + 9216, wm, wn, lane, c);
        if (g + 2 < 128) LOADG(g + 2);
        CP_COMMIT();
        if ((g & 7) == 7) {
            int t = g >> 3, slot = t & 1;
            const float* s2 = s2s + slot * 128;
            const int* cl = clss + slot * 128;
            const int c0 = cl[jb], c25 = cl[jb + 25];
            const bool fast = (c0 == c25);
#pragma unroll
            for (int mi = 0; mi < 2; mi++) {
#pragma unroll
                for (int h = 0; h < 2; h++) {
                    int r = wm * 32 + mi * 16 + (lane >> 2) + h * 8;
                    float p[8];
                    float lr = 0.f;
#pragma unroll
                    for (int ni = 0; ni < 4; ni++) {
#pragma unroll
                        for (int e = 0; e < 2; e++) {
                            int j = jb + ni * 8 + e;
                            p[ni * 2 + e] = pfun(q2r[2 * mi + h], s2[j], c[mi][ni][2 * h + e]);
                            lr += p[ni * 2 + e];
                        }
                    }
                    lrow[2 * mi + h] += lr;
                    if (fast) {
                        atomicAdd(&sacc[r * 65 + c0], lr);
                    } else {
                        float acc = 0.f;
                        int cc = -1;
#pragma unroll
                        for (int ni = 0; ni < 4; ni++) {
#pragma unroll
                            for (int e = 0; e < 2; e++) {
                                int cj = cl[jb + ni * 8 + e];
                                if (cj == cc) {
                                    acc += p[ni * 2 + e];
                                } else {
                                    if (cc >= 0) atomicAdd(&sacc[r * 65 + cc], acc);
                                    cc = cj; acc = p[ni * 2 + e];
                                }
                            }
                        }
                        atomicAdd(&sacc[r * 65 + cc], acc);
                    }
                }
#pragma unroll
                for (int ni = 0; ni < 4; ni++)
                    c[mi][ni][0] = c[mi][ni][1] = c[mi][ni][2] = c[mi][ni][3] = 0.f;
            }
            if (t + 1 < 16 && tid < 128) {
                int sc = s0 + (t + 1) * 128 + tid, o = g_inv[sc];
                s2s[((t + 1) & 1) * 128 + tid] =
                    g_n2p[o] + g_n2p[NR + o] + g_n2p[2 * NR + o] + g_n2p[3 * NR + o];
                clss[((t + 1) & 1) * 128 + tid] = g_clsS[sc];
            }
        }
    }
#pragma unroll
    for (int i = 0; i < 4; i++) {
        float v = lrow[i];
        v += __shfl_xor_sync(~0u, v, 1);
        v += __shfl_xor_sync(~0u, v, 2);
        if ((lane & 3) == 0)
            atomicAdd(&lsums[wm * 32 + (i >> 1) * 16 + (lane >> 2) + (i & 1) * 8], v);
    }
    __syncthreads();
    for (int i = tid; i < 64 * 64; i += 256) {
        int r = i >> 6, cc = i & 63;
        g_pnum[(size_t)half * NQ * NC + (size_t)(m0 + r) * NC + cc] = sacc[r * 65 + cc];
    }
    if (tid < 64) g_pden[half * NQ + m0 + tid] = lsums[tid];
#undef LOADG
}

// =============================================================================
// Finalize
// =============================================================================
__global__ void fin_kernel(float* __restrict__ out) {
    int i = blockIdx.x * blockDim.x + threadIdx.x;
    if (i >= NQ * NC) return;
    int q = i >> 6;
    out[i] = (g_pnum[i] + g_pnum[(size_t)NQ * NC + i]) / (g_pden[q] + g_pden[NQ + q]);
}

// =============================================================================
// Launch: prep(0), clsrank(1), enc(2), dist(3), fin(4)
// =============================================================================
extern "C" void kernel_launch(void* const* d_in, const int* in_sizes, int n_in,
                              void* d_out, int out_size) {
    const float* support = (const float*)d_in[0];
    const float* query   = (const float*)d_in[1];
    const float* labels  = (const float*)d_in[2];
    const float* W       = (const float*)d_in[3];
    const float* b       = (const float*)d_in[4];
    float* out = (float*)d_out;

    cudaFuncSetAttribute(enc_kernel,  cudaFuncAttributeMaxDynamicSharedMemorySize, SMEM_ENC);
    cudaFuncSetAttribute(dist_kernel, cudaFuncAttributeMaxDynamicSharedMemorySize, SMEM_DIST);

    prep_kernel<<<NR + EMB, 128>>>(support, query, W);
    clsrank_kernel<<<NC, 256>>>(labels);
    enc_kernel<<<dim3(NR / 64, EMB / 128), 256, SMEM_ENC>>>(b);
    dist_kernel<<<dim3(NQ / 64, 2), 256, SMEM_DIST>>>();
    fin_kernel<<<(NQ * NC + 255) / 256, 256>>>(out);
}

// round 9
// speedup vs baseline: 3.0525x; 1.0134x over previous
#include <cuda_runtime.h>
#include <cuda_fp16.h>
#include <cstdint>

#define NS 4096
#define NQ 8192
#define NR 12288
#define IND 784
#define EMB 512
#define NC 64
#define KE 1600          // 2*784 = 1568 padded to 64
#define LOG2E 1.4426950408889634f

// ------------------------- device scratch -----------------------------------
__device__ __align__(128) __half g_X[(size_t)NR * KE];      // [xh|xl]
__device__ __align__(128) __half g_W[(size_t)EMB * KE];     // [wh|wh] (W^T rows)
__device__ __align__(128) __half g_Q[(size_t)NQ * 512];     // qh (1024 B/row)
__device__ __align__(128) __half g_S[(size_t)NS * 512];     // sh, class-sorted rows
__device__ float g_n2p[4 * NR];
__device__ int   g_rank[NS];
__device__ int   g_inv[NS];
__device__ int   g_clsS[NS];
__device__ float g_pnum[2 * (size_t)NQ * NC];
__device__ float g_pden[2 * NQ];

// ------------------------- helpers ------------------------------------------
__device__ __forceinline__ uint32_t smem_u32(const void* p) {
    uint32_t a;
    asm("{ .reg .u64 t; cvta.to.shared.u64 t, %1; cvt.u32.u64 %0, t; }" : "=r"(a) : "l"(p));
    return a;
}
#define CP_COMMIT() asm volatile("cp.async.commit_group;" ::: "memory")
#define CP_WAIT1()  asm volatile("cp.async.wait_group 1;" ::: "memory")

__device__ __forceinline__ void ldm4(uint32_t r[4], uint32_t addr) {
    asm volatile("ldmatrix.sync.aligned.m8n8.x4.shared.b16 {%0,%1,%2,%3}, [%4];"
                 : "=r"(r[0]), "=r"(r[1]), "=r"(r[2]), "=r"(r[3]) : "r"(addr));
}
__device__ __forceinline__ void mma16816(float c[4], uint32_t a0, uint32_t a1, uint32_t a2,
                                         uint32_t a3, uint32_t b0, uint32_t b1) {
    asm volatile(
        "mma.sync.aligned.m16n8k16.row.col.f32.f16.f16.f32 "
        "{%0,%1,%2,%3}, {%4,%5,%6,%7}, {%8,%9}, {%0,%1,%2,%3};"
        : "+f"(c[0]), "+f"(c[1]), "+f"(c[2]), "+f"(c[3])
        : "r"(a0), "r"(a1), "r"(a2), "r"(a3), "r"(b0), "r"(b1));
}

// N rows x 64 halfs (128B) global -> smem (stride 144B)
template <int ROWS>
__device__ __forceinline__ void loadT(uint32_t sdst, const char* gbase, uint32_t goff,
                                      uint32_t rs, int tid) {
#pragma unroll
    for (int i = 0; i < ROWS / 32; i++) {
        int u = tid + (i << 8), r = u >> 3, j = u & 7;
        asm volatile("cp.async.cg.shared.global [%0], [%1], 16;"
                     :: "r"(sdst + r * 144 + j * 16),
                        "l"(gbase + goff + (uint32_t)r * rs + j * 16) : "memory");
    }
}

// BK=64 chunk, warp tile 64x64 (dist): A tile 128 rows, B tile 256 rows.
__device__ __forceinline__ void compute_d(uint32_t smA, uint32_t smB, int wm, int wn, int lane,
                                          float c[4][8][4]) {
    uint32_t aRow = smA + (uint32_t)((wm * 64 + (lane & 15)) * 144 + (lane >> 4) * 16);
    uint32_t bRow = smB + (uint32_t)((wn * 64 + (lane >> 4) * 8 + (lane & 7)) * 144
                                     + ((lane >> 3) & 1) * 16);
#pragma unroll
    for (int ks = 0; ks < 4; ks++) {
        uint32_t ko = (uint32_t)ks * 32;
        uint32_t a[4][4], b[4][4];
#pragma unroll
        for (int mi = 0; mi < 4; mi++) ldm4(a[mi], aRow + mi * 2304 + ko);
#pragma unroll
        for (int q = 0; q < 4; q++) ldm4(b[q], bRow + q * 2304 + ko);
#pragma unroll
        for (int mi = 0; mi < 4; mi++)
#pragma unroll
            for (int ni = 0; ni < 8; ni++)
                mma16816(c[mi][ni], a[mi][0], a[mi][1], a[mi][2], a[mi][3],
                         b[ni >> 1][(ni & 1) * 2], b[ni >> 1][(ni & 1) * 2 + 1]);
    }
}

// BK=64 chunk, warp tile 64x32 (enc): A tile 128 rows, B tile 128 rows.
__device__ __forceinline__ void compute_e(uint32_t smA, uint32_t smB, int wm, int wn, int lane,
                                          float c[4][4][4]) {
    uint32_t aRow = smA + (uint32_t)((wm * 64 + (lane & 15)) * 144 + (lane >> 4) * 16);
    uint32_t bRow = smB + (uint32_t)((wn * 32 + (lane >> 4) * 8 + (lane & 7)) * 144
                                     + ((lane >> 3) & 1) * 16);
#pragma unroll
    for (int ks = 0; ks < 4; ks++) {
        uint32_t ko = (uint32_t)ks * 32;
        uint32_t a[4][4], b[2][4];
#pragma unroll
        for (int mi = 0; mi < 4; mi++) ldm4(a[mi], aRow + mi * 2304 + ko);
#pragma unroll
        for (int q = 0; q < 2; q++) ldm4(b[q], bRow + q * 2304 + ko);
#pragma unroll
        for (int mi = 0; mi < 4; mi++)
#pragma unroll
            for (int ni = 0; ni < 4; ni++)
                mma16816(c[mi][ni], a[mi][0], a[mi][1], a[mi][2], a[mi][3],
                         b[ni >> 1][(ni & 1) * 2], b[ni >> 1][(ni & 1) * 2 + 1]);
    }
}

// ------------------------- smem layouts -------------------------------------
// enc: stage = A(128x144) + B(128x144) = 36864; 3 stages
#define ESTG 36864
#define E_BIAS 110592
#define E_N2   111104
#define SMEM_ENC 111616
// dist: stage = A(128x144=18432) + B(256x144=36864) = 55296; 3 stages
#define DSTG 55296
#define D_SACC 165888              // 128*65 f32 = 33280
#define D_S2   199168              // 2*256 f32
#define D_CLS  201216              // 2*256 int
#define D_Q2   203264              // 128 f32
#define D_LS   203776              // 128 f32
#define SMEM_DIST 204288

// =============================================================================
// Prep: hi/lo split of X (NR rows) and W^T (EMB rows)
// =============================================================================
__global__ void prep_kernel(const float* __restrict__ sup, const float* __restrict__ qry,
                            const float* __restrict__ W) {
    int bid = blockIdx.x;
    if (bid < NR) {
        const float* src = bid < NS ? sup + (size_t)bid * IND : qry + (size_t)(bid - NS) * IND;
        __half* dst = g_X + (size_t)bid * KE;
        for (int c = threadIdx.x; c < IND; c += 128) {
            float x = src[c];
            __half h = __float2half_rn(x);
            dst[c] = h;
            dst[IND + c] = __float2half_rn(x - __half2float(h));
        }
        if (threadIdx.x < KE - 2 * IND) dst[2 * IND + threadIdx.x] = __ushort_as_half(0);
    } else {
        int n = bid - NR;
        __half* dst = g_W + (size_t)n * KE;
        for (int k = threadIdx.x; k < IND; k += 128) {
            __half h = __float2half_rn(W[(size_t)k * EMB + n]);
            dst[k] = h;
            dst[IND + k] = h;
        }
        if (threadIdx.x < KE - 2 * IND) dst[2 * IND + threadIdx.x] = __ushort_as_half(0);
    }
}

// =============================================================================
// Class extraction + deterministic stable counting sort (block b = class b).
// =============================================================================
__global__ __launch_bounds__(256) void clsrank_kernel(const float* __restrict__ labels) {
    __shared__ int cl[NS];
    __shared__ int eqs[256], lts[256];
    const int b = blockIdx.x, tid = threadIdx.x;
    for (int idx = tid; idx < NS * NC; idx += 256)
        if (labels[idx] > 0.5f) cl[idx >> 6] = idx & 63;
    __syncthreads();
    int e0 = 0, l0 = 0;
    const int j0 = tid * 16;
#pragma unroll
    for (int e = 0; e < 16; e++) {
        int c = cl[j0 + e];
        e0 += (c == b);
        l0 += (c < b);
    }
    eqs[tid] = e0; lts[tid] = l0;
    __syncthreads();
    for (int off = 1; off < 256; off <<= 1) {
        int ve = (tid >= off) ? eqs[tid - off] : 0;
        int vl = (tid >= off) ? lts[tid - off] : 0;
        __syncthreads();
        eqs[tid] += ve; lts[tid] += vl;
        __syncthreads();
    }
    int r = lts[255] + eqs[tid] - e0;
    for (int e = 0; e < 16; e++) {
        int j = j0 + e;
        if (cl[j] == b) {
            g_rank[j] = r;
            g_inv[r] = j;
            g_clsS[r] = b;
            r++;
        }
    }
}

// =============================================================================
// Encoder: D[128x128] = X * W^T, K=1600, fp16 2-term split.
// 8 warps (2x4), warp tile 64x32, single-barrier 3-stage pipeline, 1 CTA/SM.
// =============================================================================
__global__ __launch_bounds__(256, 1) void enc_kernel(const float* __restrict__ bias) {
    extern __shared__ char sm[];
    uint32_t smb = smem_u32(sm);
    const int tid = threadIdx.x, lane = tid & 31, w = tid >> 5, wm = w >> 2, wn = w & 3;
    const int m0 = blockIdx.x * 128, n0 = blockIdx.y * 128;
    float* biasS = (float*)(sm + E_BIAS);
    float* n2s = (float*)(sm + E_N2);
    if (tid < 128) { biasS[tid] = bias[n0 + tid]; n2s[tid] = 0.f; }

    const char* A = (const char*)g_X + (size_t)m0 * (KE * 2);
    const char* B = (const char*)g_W + (size_t)n0 * (KE * 2);
    const int G = KE / 64;  // 25
    loadT<128>(smb, A, 0, KE * 2, tid);
    loadT<128>(smb + 18432, B, 0, KE * 2, tid); CP_COMMIT();
    loadT<128>(smb + ESTG, A, 128, KE * 2, tid);
    loadT<128>(smb + ESTG + 18432, B, 128, KE * 2, tid); CP_COMMIT();

    float c[4][4][4];
#pragma unroll
    for (int i = 0; i < 4; i++)
#pragma unroll
        for (int j = 0; j < 4; j++)
#pragma unroll
            for (int k = 0; k < 4; k++) c[i][j][k] = 0.f;

    for (int g = 0; g < G; g++) {
        CP_WAIT1(); __syncthreads();
        int s = (g % 3) * ESTG;
        compute_e(smb + s, smb + s + 18432, wm, wn, lane, c);
        if (g + 2 < G) {
            int s2 = ((g + 2) % 3) * ESTG;
            loadT<128>(smb + s2, A, (uint32_t)(g + 2) * 128, KE * 2, tid);
            loadT<128>(smb + s2 + 18432, B, (uint32_t)(g + 2) * 128, KE * 2, tid);
        }
        CP_COMMIT();
    }

    float vsq[8];
#pragma unroll
    for (int i = 0; i < 8; i++) vsq[i] = 0.f;
#pragma unroll
    for (int mi = 0; mi < 4; mi++) {
        int r0 = wm * 64 + mi * 16 + (lane >> 2);
#pragma unroll
        for (int ni = 0; ni < 4; ni++) {
            int cn = wn * 32 + ni * 8 + (lane & 3) * 2;
            float b0 = biasS[cn], b1 = biasS[cn + 1];
            float v0 = c[mi][ni][0] + b0, v1 = c[mi][ni][1] + b1;
            float v2 = c[mi][ni][2] + b0, v3 = c[mi][ni][3] + b1;
            vsq[2 * mi] += v0 * v0 + v1 * v1;
            vsq[2 * mi + 1] += v2 * v2 + v3 * v3;
#pragma unroll
            for (int h = 0; h < 2; h++) {
                float x0 = h ? v2 : v0, x1 = h ? v3 : v1;
                int rg = m0 + r0 + h * 8, col = n0 + cn;
                __half h0 = __float2half_rn(x0), h1 = __float2half_rn(x1);
                uint32_t hp = ((uint32_t)__half_as_ushort(h1) << 16) | __half_as_ushort(h0);
                if (rg < NS) {
                    int sr = g_rank[rg];
                    ((uint32_t*)(g_S + (size_t)sr * 512))[col >> 1] = hp;
                } else {
                    ((uint32_t*)(g_Q + (size_t)(rg - NS) * 512))[col >> 1] = hp;
                }
            }
        }
    }
#pragma unroll
    for (int i = 0; i < 8; i++) {
        float v = vsq[i];
        v += __shfl_xor_sync(~0u, v, 1);
        v += __shfl_xor_sync(~0u, v, 2);
        if ((lane & 3) == 0)
            atomicAdd(&n2s[wm * 64 + (i >> 1) * 16 + (lane >> 2) + (i & 1) * 8], v);
    }
    __syncthreads();
    if (tid < 128) g_n2p[blockIdx.y * NR + m0 + tid] = n2s[tid];
}

__device__ __forceinline__ float pfun(float q2, float s2, float qs) {
    float d2 = fmaxf(q2 + s2 - 2.f * qs, 0.f);
    float d, p;
    asm("sqrt.approx.f32 %0, %1;" : "=f"(d) : "f"(d2));
    asm("ex2.approx.f32 %0, %1;" : "=f"(p) : "f"((32.f - d) * LOG2E));
    return p;
}

// =============================================================================
// Fused distance/softmax/aggregate. CTA: 128 queries x 2048 supports (sorted).
// 8 tiles of 256 supports x 8 K-chunks = 64 iterations. Warp tile 64x64.
// =============================================================================
__global__ __launch_bounds__(256, 1) void dist_kernel() {
    extern __shared__ char sm[];
    uint32_t smb = smem_u32(sm);
    const int tid = threadIdx.x, lane = tid & 31, w = tid >> 5, wm = w >> 2, wn = w & 3;
    const int m0 = blockIdx.x * 128, half = blockIdx.y, s0 = half * 2048;
    float* sacc  = (float*)(sm + D_SACC);
    float* s2s   = (float*)(sm + D_S2);
    int*   clss  = (int*)(sm + D_CLS);
    float* q2s   = (float*)(sm + D_Q2);
    float* lsums = (float*)(sm + D_LS);

    for (int i = tid; i < 128 * 65; i += 256) sacc[i] = 0.f;
    if (tid < 128) {
        int qr = NS + m0 + tid;
        q2s[tid] = g_n2p[qr] + g_n2p[NR + qr] + g_n2p[2 * NR + qr] + g_n2p[3 * NR + qr];
        lsums[tid] = 0.f;
    }
    {
        int sc = s0 + tid, o = g_inv[sc];
        s2s[tid] = g_n2p[o] + g_n2p[NR + o] + g_n2p[2 * NR + o] + g_n2p[3 * NR + o];
        clss[tid] = g_clsS[sc];
    }
    const char* A  = (const char*)g_Q + (size_t)m0 * 1024;
    const char* Sb = (const char*)g_S + (size_t)s0 * 1024;

#define LOADG(gg) do { \
        int _s = ((gg) % 3) * DSTG; \
        uint32_t _t = (uint32_t)(gg) >> 3, _kc = (uint32_t)(gg) & 7; \
        loadT<128>(smb + _s, A, _kc * 128, 1024, tid); \
        loadT<256>(smb + _s + 18432, Sb, _t * 262144 + _kc * 128, 1024, tid); \
    } while (0)

    LOADG(0); CP_COMMIT();
    LOADG(1); CP_COMMIT();

    float c[4][8][4];
#pragma unroll
    for (int i = 0; i < 4; i++)
#pragma unroll
        for (int j = 0; j < 8; j++)
#pragma unroll
            for (int k = 0; k < 4; k++) c[i][j][k] = 0.f;
    float lrow[8];
#pragma unroll
    for (int i = 0; i < 8; i++) lrow[i] = 0.f;
    __syncthreads();
    float q2r[8];
#pragma unroll
    for (int i = 0; i < 8; i++)
        q2r[i] = q2s[wm * 64 + (i >> 1) * 16 + (lane >> 2) + (i & 1) * 8];

    const int jb = wn * 64 + (lane & 3) * 2;

    for (int g = 0; g < 64; g++) {
        CP_WAIT1(); __syncthreads();
        int s = (g % 3) * DSTG;
        compute_d(smb + s, smb + s + 18432, wm, wn, lane, c);
        if (g + 2 < 64) LOADG(g + 2);
        CP_COMMIT();
        if ((g & 7) == 7) {
            int t = g >> 3, slot = t & 1;
            const float* s2 = s2s + slot * 256;
            const int* cl = clss + slot * 256;
            const bool fast = (cl[jb] == cl[jb + 57]);
            const int c0 = cl[jb];
#pragma unroll
            for (int mi = 0; mi < 4; mi++) {
#pragma unroll
                for (int h = 0; h < 2; h++) {
                    int r = wm * 64 + mi * 16 + (lane >> 2) + h * 8;
                    float p[16];
                    float lr = 0.f;
#pragma unroll
                    for (int ni = 0; ni < 8; ni++) {
#pragma unroll
                        for (int e = 0; e < 2; e++) {
                            int j = jb + ni * 8 + e;
                            p[ni * 2 + e] = pfun(q2r[2 * mi + h], s2[j], c[mi][ni][2 * h + e]);
                            lr += p[ni * 2 + e];
                        }
                    }
                    lrow[2 * mi + h] += lr;
                    if (fast) {
                        atomicAdd(&sacc[r * 65 + c0], lr);
                    } else {
                        float acc = 0.f;
                        int cc = -1;
#pragma unroll
                        for (int ni = 0; ni < 8; ni++) {
#pragma unroll
                            for (int e = 0; e < 2; e++) {
                                int cj = cl[jb + ni * 8 + e];
                                if (cj == cc) {
                                    acc += p[ni * 2 + e];
                                } else {
                                    if (cc >= 0) atomicAdd(&sacc[r * 65 + cc], acc);
                                    cc = cj; acc = p[ni * 2 + e];
                                }
                            }
                        }
                        atomicAdd(&sacc[r * 65 + cc], acc);
                    }
                }
#pragma unroll
                for (int ni = 0; ni < 8; ni++)
#pragma unroll
                    for (int k = 0; k < 4; k++) c[mi][ni][k] = 0.f;
            }
            if (t + 1 < 8) {
                int sc = s0 + (t + 1) * 256 + tid, o = g_inv[sc];
                s2s[((t + 1) & 1) * 256 + tid] =
                    g_n2p[o] + g_n2p[NR + o] + g_n2p[2 * NR + o] + g_n2p[3 * NR + o];
                clss[((t + 1) & 1) * 256 + tid] = g_clsS[sc];
            }
        }
    }
#pragma unroll
    for (int i = 0; i < 8; i++) {
        float v = lrow[i];
        v += __shfl_xor_sync(~0u, v, 1);
        v += __shfl_xor_sync(~0u, v, 2);
        if ((lane & 3) == 0)
            atomicAdd(&lsums[wm * 64 + (i >> 1) * 16 + (lane >> 2) + (i & 1) * 8], v);
    }
    __syncthreads();
    for (int i = tid; i < 128 * 64; i += 256) {
        int r = i >> 6, cc = i & 63;
        g_pnum[(size_t)half * NQ * NC + (size_t)(m0 + r) * NC + cc] = sacc[r * 65 + cc];
    }
    if (tid < 128) g_pden[half * NQ + m0 + tid] = lsums[tid];
#undef LOADG
}

// =============================================================================
// Finalize
// =============================================================================
__global__ void fin_kernel(float* __restrict__ out) {
    int i = blockIdx.x * blockDim.x + threadIdx.x;
    if (i >= NQ * NC) return;
    int q = i >> 6;
    out[i] = (g_pnum[i] + g_pnum[(size_t)NQ * NC + i]) / (g_pden[q] + g_pden[NQ + q]);
}

// =============================================================================
// Launch: prep(0), clsrank(1), enc(2), dist(3), fin(4)
// =============================================================================
extern "C" void kernel_launch(void* const* d_in, const int* in_sizes, int n_in,
                              void* d_out, int out_size) {
    const float* support = (const float*)d_in[0];
    const float* query   = (const float*)d_in[1];
    const float* labels  = (const float*)d_in[2];
    const float* W       = (const float*)d_in[3];
    const float* b       = (const float*)d_in[4];
    float* out = (float*)d_out;

    cudaFuncSetAttribute(enc_kernel,  cudaFuncAttributeMaxDynamicSharedMemorySize, SMEM_ENC);
    cudaFuncSetAttribute(dist_kernel, cudaFuncAttributeMaxDynamicSharedMemorySize, SMEM_DIST);

    prep_kernel<<<NR + EMB, 128>>>(support, query, W);
    clsrank_kernel<<<NC, 256>>>(labels);
    enc_kernel<<<dim3(NR / 128, EMB / 128), 256, SMEM_ENC>>>(b);
    dist_kernel<<<dim3(NQ / 128, 2), 256, SMEM_DIST>>>();
    fin_kernel<<<(NQ * NC + 255) / 256, 256>>>(out);
}

// round 10
// speedup vs baseline: 3.4867x; 1.1423x over previous
#include <cuda_runtime.h>
#include <cuda_fp16.h>
#include <cstdint>

#define NS 4096
#define NQ 8192
#define NR 12288
#define IND 784
#define EMB 512
#define NC 64
#define KE 832           // 784 padded to 64-multiple (1-term fp16 encoder)
#define LOG2E 1.4426950408889634f

// ------------------------- device scratch -----------------------------------
__device__ __align__(128) __half g_X[(size_t)NR * KE];      // xh
__device__ __align__(128) __half g_W[(size_t)EMB * KE];     // wh (W^T rows)
__device__ __align__(128) __half g_Q[(size_t)NQ * 512];     // qh (1024 B/row)
__device__ __align__(128) __half g_S[(size_t)NS * 512];     // sh, class-sorted rows
__device__ float g_n2p[4 * NR];
__device__ int   g_rank[NS];
__device__ int   g_inv[NS];
__device__ int   g_clsS[NS];
__device__ float g_pnum[2 * (size_t)NQ * NC];
__device__ float g_pden[2 * NQ];

// ------------------------- helpers ------------------------------------------
__device__ __forceinline__ uint32_t smem_u32(const void* p) {
    uint32_t a;
    asm("{ .reg .u64 t; cvta.to.shared.u64 t, %1; cvt.u32.u64 %0, t; }" : "=r"(a) : "l"(p));
    return a;
}
#define CP_COMMIT() asm volatile("cp.async.commit_group;" ::: "memory")
#define CP_WAIT1()  asm volatile("cp.async.wait_group 1;" ::: "memory")

__device__ __forceinline__ void ldm4(uint32_t r[4], uint32_t addr) {
    asm volatile("ldmatrix.sync.aligned.m8n8.x4.shared.b16 {%0,%1,%2,%3}, [%4];"
                 : "=r"(r[0]), "=r"(r[1]), "=r"(r[2]), "=r"(r[3]) : "r"(addr));
}
__device__ __forceinline__ void mma16816(float c[4], uint32_t a0, uint32_t a1, uint32_t a2,
                                         uint32_t a3, uint32_t b0, uint32_t b1) {
    asm volatile(
        "mma.sync.aligned.m16n8k16.row.col.f32.f16.f16.f32 "
        "{%0,%1,%2,%3}, {%4,%5,%6,%7}, {%8,%9}, {%0,%1,%2,%3};"
        : "+f"(c[0]), "+f"(c[1]), "+f"(c[2]), "+f"(c[3])
        : "r"(a0), "r"(a1), "r"(a2), "r"(a3), "r"(b0), "r"(b1));
}

// N rows x 64 halfs (128B) global -> smem (stride 144B)
template <int ROWS>
__device__ __forceinline__ void loadT(uint32_t sdst, const char* gbase, uint32_t goff,
                                      uint32_t rs, int tid) {
#pragma unroll
    for (int i = 0; i < ROWS / 32; i++) {
        int u = tid + (i << 8), r = u >> 3, j = u & 7;
        asm volatile("cp.async.cg.shared.global [%0], [%1], 16;"
                     :: "r"(sdst + r * 144 + j * 16),
                        "l"(gbase + goff + (uint32_t)r * rs + j * 16) : "memory");
    }
}

// BK=64 chunk, warp tile 64x64 (dist): A tile 128 rows, B tile 256 rows.
__device__ __forceinline__ void compute_d(uint32_t smA, uint32_t smB, int wm, int wn, int lane,
                                          float c[4][8][4]) {
    uint32_t aRow = smA + (uint32_t)((wm * 64 + (lane & 15)) * 144 + (lane >> 4) * 16);
    uint32_t bRow = smB + (uint32_t)((wn * 64 + (lane >> 4) * 8 + (lane & 7)) * 144
                                     + ((lane >> 3) & 1) * 16);
#pragma unroll
    for (int ks = 0; ks < 4; ks++) {
        uint32_t ko = (uint32_t)ks * 32;
        uint32_t a[4][4], b[4][4];
#pragma unroll
        for (int mi = 0; mi < 4; mi++) ldm4(a[mi], aRow + mi * 2304 + ko);
#pragma unroll
        for (int q = 0; q < 4; q++) ldm4(b[q], bRow + q * 2304 + ko);
#pragma unroll
        for (int mi = 0; mi < 4; mi++)
#pragma unroll
            for (int ni = 0; ni < 8; ni++)
                mma16816(c[mi][ni], a[mi][0], a[mi][1], a[mi][2], a[mi][3],
                         b[ni >> 1][(ni & 1) * 2], b[ni >> 1][(ni & 1) * 2 + 1]);
    }
}

// BK=64 chunk, warp tile 64x32 (enc): A tile 128 rows, B tile 128 rows.
__device__ __forceinline__ void compute_e(uint32_t smA, uint32_t smB, int wm, int wn, int lane,
                                          float c[4][4][4]) {
    uint32_t aRow = smA + (uint32_t)((wm * 64 + (lane & 15)) * 144 + (lane >> 4) * 16);
    uint32_t bRow = smB + (uint32_t)((wn * 32 + (lane >> 4) * 8 + (lane & 7)) * 144
                                     + ((lane >> 3) & 1) * 16);
#pragma unroll
    for (int ks = 0; ks < 4; ks++) {
        uint32_t ko = (uint32_t)ks * 32;
        uint32_t a[4][4], b[2][4];
#pragma unroll
        for (int mi = 0; mi < 4; mi++) ldm4(a[mi], aRow + mi * 2304 + ko);
#pragma unroll
        for (int q = 0; q < 2; q++) ldm4(b[q], bRow + q * 2304 + ko);
#pragma unroll
        for (int mi = 0; mi < 4; mi++)
#pragma unroll
            for (int ni = 0; ni < 4; ni++)
                mma16816(c[mi][ni], a[mi][0], a[mi][1], a[mi][2], a[mi][3],
                         b[ni >> 1][(ni & 1) * 2], b[ni >> 1][(ni & 1) * 2 + 1]);
    }
}

// ------------------------- smem layouts -------------------------------------
// enc: stage = A(128x144) + B(128x144) = 36864; 3 stages
#define ESTG 36864
#define E_BIAS 110592
#define E_N2   111104
#define SMEM_ENC 111616
// dist: stage = A(128x144=18432) + B(256x144=36864) = 55296; 3 stages
#define DSTG 55296
#define D_SACC 165888              // 128*65 f32 = 33280
#define D_S2   199168              // 2*256 f32
#define D_CLS  201216              // 2*256 int
#define D_Q2   203264              // 128 f32
#define D_LS   203776              // 128 f32
#define SMEM_DIST 204288

// =============================================================================
// Prep: fp16 rounding of X (NR rows) and W^T (EMB rows), zero-padded to KE
// =============================================================================
__global__ void prep_kernel(const float* __restrict__ sup, const float* __restrict__ qry,
                            const float* __restrict__ W) {
    int bid = blockIdx.x;
    if (bid < NR) {
        const float* src = bid < NS ? sup + (size_t)bid * IND : qry + (size_t)(bid - NS) * IND;
        __half* dst = g_X + (size_t)bid * KE;
        for (int c = threadIdx.x; c < IND; c += 128)
            dst[c] = __float2half_rn(src[c]);
        if (threadIdx.x < KE - IND) dst[IND + threadIdx.x] = __ushort_as_half(0);
    } else {
        int n = bid - NR;
        __half* dst = g_W + (size_t)n * KE;
        for (int k = threadIdx.x; k < IND; k += 128)
            dst[k] = __float2half_rn(W[(size_t)k * EMB + n]);
        if (threadIdx.x < KE - IND) dst[IND + threadIdx.x] = __ushort_as_half(0);
    }
}

// =============================================================================
// Class extraction + deterministic stable counting sort (block b = class b).
// =============================================================================
__global__ __launch_bounds__(256) void clsrank_kernel(const float* __restrict__ labels) {
    __shared__ int cl[NS];
    __shared__ int eqs[256], lts[256];
    const int b = blockIdx.x, tid = threadIdx.x;
    for (int idx = tid; idx < NS * NC; idx += 256)
        if (labels[idx] > 0.5f) cl[idx >> 6] = idx & 63;
    __syncthreads();
    int e0 = 0, l0 = 0;
    const int j0 = tid * 16;
#pragma unroll
    for (int e = 0; e < 16; e++) {
        int c = cl[j0 + e];
        e0 += (c == b);
        l0 += (c < b);
    }
    eqs[tid] = e0; lts[tid] = l0;
    __syncthreads();
    for (int off = 1; off < 256; off <<= 1) {
        int ve = (tid >= off) ? eqs[tid - off] : 0;
        int vl = (tid >= off) ? lts[tid - off] : 0;
        __syncthreads();
        eqs[tid] += ve; lts[tid] += vl;
        __syncthreads();
    }
    int r = lts[255] + eqs[tid] - e0;
    for (int e = 0; e < 16; e++) {
        int j = j0 + e;
        if (cl[j] == b) {
            g_rank[j] = r;
            g_inv[r] = j;
            g_clsS[r] = b;
            r++;
        }
    }
}

// =============================================================================
// Encoder: D[128x128] = X * W^T, K=832 (pure fp16).
// 8 warps (2x4), warp tile 64x32, single-barrier 3-stage pipeline, 1 CTA/SM.
// =============================================================================
__global__ __launch_bounds__(256, 1) void enc_kernel(const float* __restrict__ bias) {
    extern __shared__ char sm[];
    uint32_t smb = smem_u32(sm);
    const int tid = threadIdx.x, lane = tid & 31, w = tid >> 5, wm = w >> 2, wn = w & 3;
    const int m0 = blockIdx.x * 128, n0 = blockIdx.y * 128;
    float* biasS = (float*)(sm + E_BIAS);
    float* n2s = (float*)(sm + E_N2);
    if (tid < 128) { biasS[tid] = bias[n0 + tid]; n2s[tid] = 0.f; }

    const char* A = (const char*)g_X + (size_t)m0 * (KE * 2);
    const char* B = (const char*)g_W + (size_t)n0 * (KE * 2);
    const int G = KE / 64;  // 13
    loadT<128>(smb, A, 0, KE * 2, tid);
    loadT<128>(smb + 18432, B, 0, KE * 2, tid); CP_COMMIT();
    loadT<128>(smb + ESTG, A, 128, KE * 2, tid);
    loadT<128>(smb + ESTG + 18432, B, 128, KE * 2, tid); CP_COMMIT();

    float c[4][4][4];
#pragma unroll
    for (int i = 0; i < 4; i++)
#pragma unroll
        for (int j = 0; j < 4; j++)
#pragma unroll
            for (int k = 0; k < 4; k++) c[i][j][k] = 0.f;

    for (int g = 0; g < G; g++) {
        CP_WAIT1(); __syncthreads();
        int s = (g % 3) * ESTG;
        compute_e(smb + s, smb + s + 18432, wm, wn, lane, c);
        if (g + 2 < G) {
            int s2 = ((g + 2) % 3) * ESTG;
            loadT<128>(smb + s2, A, (uint32_t)(g + 2) * 128, KE * 2, tid);
            loadT<128>(smb + s2 + 18432, B, (uint32_t)(g + 2) * 128, KE * 2, tid);
        }
        CP_COMMIT();
    }

    float vsq[8];
#pragma unroll
    for (int i = 0; i < 8; i++) vsq[i] = 0.f;
#pragma unroll
    for (int mi = 0; mi < 4; mi++) {
        int r0 = wm * 64 + mi * 16 + (lane >> 2);
#pragma unroll
        for (int ni = 0; ni < 4; ni++) {
            int cn = wn * 32 + ni * 8 + (lane & 3) * 2;
            float b0 = biasS[cn], b1 = biasS[cn + 1];
            float v0 = c[mi][ni][0] + b0, v1 = c[mi][ni][1] + b1;
            float v2 = c[mi][ni][2] + b0, v3 = c[mi][ni][3] + b1;
            vsq[2 * mi] += v0 * v0 + v1 * v1;
            vsq[2 * mi + 1] += v2 * v2 + v3 * v3;
#pragma unroll
            for (int h = 0; h < 2; h++) {
                float x0 = h ? v2 : v0, x1 = h ? v3 : v1;
                int rg = m0 + r0 + h * 8, col = n0 + cn;
                __half h0 = __float2half_rn(x0), h1 = __float2half_rn(x1);
                uint32_t hp = ((uint32_t)__half_as_ushort(h1) << 16) | __half_as_ushort(h0);
                if (rg < NS) {
                    int sr = g_rank[rg];
                    ((uint32_t*)(g_S + (size_t)sr * 512))[col >> 1] = hp;
                } else {
                    ((uint32_t*)(g_Q + (size_t)(rg - NS) * 512))[col >> 1] = hp;
                }
            }
        }
    }
#pragma unroll
    for (int i = 0; i < 8; i++) {
        float v = vsq[i];
        v += __shfl_xor_sync(~0u, v, 1);
        v += __shfl_xor_sync(~0u, v, 2);
        if ((lane & 3) == 0)
            atomicAdd(&n2s[wm * 64 + (i >> 1) * 16 + (lane >> 2) + (i & 1) * 8], v);
    }
    __syncthreads();
    if (tid < 128) g_n2p[blockIdx.y * NR + m0 + tid] = n2s[tid];
}

__device__ __forceinline__ float pfun(float q2, float s2, float qs) {
    float d2 = fmaxf(q2 + s2 - 2.f * qs, 0.f);
    float d, p;
    asm("sqrt.approx.f32 %0, %1;" : "=f"(d) : "f"(d2));
    asm("ex2.approx.f32 %0, %1;" : "=f"(p) : "f"((32.f - d) * LOG2E));
    return p;
}

// =============================================================================
// Fused distance/softmax/aggregate. CTA: 128 queries x 2048 supports (sorted).
// 8 tiles of 256 supports x 8 K-chunks = 64 iterations. Warp tile 64x64.
// =============================================================================
__global__ __launch_bounds__(256, 1) void dist_kernel() {
    extern __shared__ char sm[];
    uint32_t smb = smem_u32(sm);
    const int tid = threadIdx.x, lane = tid & 31, w = tid >> 5, wm = w >> 2, wn = w & 3;
    const int m0 = blockIdx.x * 128, half = blockIdx.y, s0 = half * 2048;
    float* sacc  = (float*)(sm + D_SACC);
    float* s2s   = (float*)(sm + D_S2);
    int*   clss  = (int*)(sm + D_CLS);
    float* q2s   = (float*)(sm + D_Q2);
    float* lsums = (float*)(sm + D_LS);

    for (int i = tid; i < 128 * 65; i += 256) sacc[i] = 0.f;
    if (tid < 128) {
        int qr = NS + m0 + tid;
        q2s[tid] = g_n2p[qr] + g_n2p[NR + qr] + g_n2p[2 * NR + qr] + g_n2p[3 * NR + qr];
        lsums[tid] = 0.f;
    }
    {
        int sc = s0 + tid, o = g_inv[sc];
        s2s[tid] = g_n2p[o] + g_n2p[NR + o] + g_n2p[2 * NR + o] + g_n2p[3 * NR + o];
        clss[tid] = g_clsS[sc];
    }
    const char* A  = (const char*)g_Q + (size_t)m0 * 1024;
    const char* Sb = (const char*)g_S + (size_t)s0 * 1024;

#define LOADG(gg) do { \
        int _s = ((gg) % 3) * DSTG; \
        uint32_t _t = (uint32_t)(gg) >> 3, _kc = (uint32_t)(gg) & 7; \
        loadT<128>(smb + _s, A, _kc * 128, 1024, tid); \
        loadT<256>(smb + _s + 18432, Sb, _t * 262144 + _kc * 128, 1024, tid); \
    } while (0)

    LOADG(0); CP_COMMIT();
    LOADG(1); CP_COMMIT();

    float c[4][8][4];
#pragma unroll
    for (int i = 0; i < 4; i++)
#pragma unroll
        for (int j = 0; j < 8; j++)
#pragma unroll
            for (int k = 0; k < 4; k++) c[i][j][k] = 0.f;
    float lrow[8];
#pragma unroll
    for (int i = 0; i < 8; i++) lrow[i] = 0.f;
    __syncthreads();
    float q2r[8];
#pragma unroll
    for (int i = 0; i < 8; i++)
        q2r[i] = q2s[wm * 64 + (i >> 1) * 16 + (lane >> 2) + (i & 1) * 8];

    const int jb = wn * 64 + (lane & 3) * 2;

    for (int g = 0; g < 64; g++) {
        CP_WAIT1(); __syncthreads();
        int s = (g % 3) * DSTG;
        compute_d(smb + s, smb + s + 18432, wm, wn, lane, c);
        if (g + 2 < 64) LOADG(g + 2);
        CP_COMMIT();
        if ((g & 7) == 7) {
            int t = g >> 3, slot = t & 1;
            const float* s2 = s2s + slot * 256;
            const int* cl = clss + slot * 256;
            const bool fast = (cl[jb] == cl[jb + 57]);
            const int c0 = cl[jb];
#pragma unroll
            for (int mi = 0; mi < 4; mi++) {
#pragma unroll
                for (int h = 0; h < 2; h++) {
                    int r = wm * 64 + mi * 16 + (lane >> 2) + h * 8;
                    float p[16];
                    float lr = 0.f;
#pragma unroll
                    for (int ni = 0; ni < 8; ni++) {
#pragma unroll
                        for (int e = 0; e < 2; e++) {
                            int j = jb + ni * 8 + e;
                            p[ni * 2 + e] = pfun(q2r[2 * mi + h], s2[j], c[mi][ni][2 * h + e]);
                            lr += p[ni * 2 + e];
                        }
                    }
                    lrow[2 * mi + h] += lr;
                    if (fast) {
                        atomicAdd(&sacc[r * 65 + c0], lr);
                    } else {
                        float acc = 0.f;
                        int cc = -1;
#pragma unroll
                        for (int ni = 0; ni < 8; ni++) {
#pragma unroll
                            for (int e = 0; e < 2; e++) {
                                int cj = cl[jb + ni * 8 + e];
                                if (cj == cc) {
                                    acc += p[ni * 2 + e];
                                } else {
                                    if (cc >= 0) atomicAdd(&sacc[r * 65 + cc], acc);
                                    cc = cj; acc = p[ni * 2 + e];
                                }
                            }
                        }
                        atomicAdd(&sacc[r * 65 + cc], acc);
                    }
                }
#pragma unroll
                for (int ni = 0; ni < 8; ni++)
#pragma unroll
                    for (int k = 0; k < 4; k++) c[mi][ni][k] = 0.f;
            }
            if (t + 1 < 8) {
                int sc = s0 + (t + 1) * 256 + tid, o = g_inv[sc];
                s2s[((t + 1) & 1) * 256 + tid] =
                    g_n2p[o] + g_n2p[NR + o] + g_n2p[2 * NR + o] + g_n2p[3 * NR + o];
                clss[((t + 1) & 1) * 256 + tid] = g_clsS[sc];
            }
        }
    }
#pragma unroll
    for (int i = 0; i < 8; i++) {
        float v = lrow[i];
        v += __shfl_xor_sync(~0u, v, 1);
        v += __shfl_xor_sync(~0u, v, 2);
        if ((lane & 3) == 0)
            atomicAdd(&lsums[wm * 64 + (i >> 1) * 16 + (lane >> 2) + (i & 1) * 8], v);
    }
    __syncthreads();
    for (int i = tid; i < 128 * 64; i += 256) {
        int r = i >> 6, cc = i & 63;
        g_pnum[(size_t)half * NQ * NC + (size_t)(m0 + r) * NC + cc] = sacc[r * 65 + cc];
    }
    if (tid < 128) g_pden[half * NQ + m0 + tid] = lsums[tid];
#undef LOADG
}

// =============================================================================
// Finalize
// =============================================================================
__global__ void fin_kernel(float* __restrict__ out) {
    int i = blockIdx.x * blockDim.x + threadIdx.x;
    if (i >= NQ * NC) return;
    int q = i >> 6;
    out[i] = (g_pnum[i] + g_pnum[(size_t)NQ * NC + i]) / (g_pden[q] + g_pden[NQ + q]);
}

// =============================================================================
// Launch: prep(0), clsrank(1), enc(2), dist(3), fin(4)
// =============================================================================
extern "C" void kernel_launch(void* const* d_in, const int* in_sizes, int n_in,
                              void* d_out, int out_size) {
    const float* support = (const float*)d_in[0];
    const float* query   = (const float*)d_in[1];
    const float* labels  = (const float*)d_in[2];
    const float* W       = (const float*)d_in[3];
    const float* b       = (const float*)d_in[4];
    float* out = (float*)d_out;

    cudaFuncSetAttribute(enc_kernel,  cudaFuncAttributeMaxDynamicSharedMemorySize, SMEM_ENC);
    cudaFuncSetAttribute(dist_kernel, cudaFuncAttributeMaxDynamicSharedMemorySize, SMEM_DIST);

    prep_kernel<<<NR + EMB, 128>>>(support, query, W);
    clsrank_kernel<<<NC, 256>>>(labels);
    enc_kernel<<<dim3(NR / 128, EMB / 128), 256, SMEM_ENC>>>(b);
    dist_kernel<<<dim3(NQ / 128, 2), 256, SMEM_DIST>>>();
    fin_kernel<<<(NQ * NC + 255) / 256, 256>>>(out);
}

// round 11
// speedup vs baseline: 3.6206x; 1.0384x over previous
#include <cuda_runtime.h>
#include <cuda_fp16.h>
#include <cstdint>

#define NS 4096
#define NQ 8192
#define NR 12288
#define IND 784
#define EMB 512
#define NC 64
#define KE 832           // 784 padded to 64-multiple (1-term fp16 encoder)
#define LOG2E 1.4426950408889634f

// ------------------------- device scratch -----------------------------------
__device__ __align__(128) __half g_X[(size_t)NR * KE];      // xh
__device__ __align__(128) __half g_W[(size_t)EMB * KE];     // wh (W^T rows)
__device__ __align__(128) __half g_Q[(size_t)NQ * 512];     // qh (1024 B/row)
__device__ __align__(128) __half g_S[(size_t)NS * 512];     // sh, class-sorted rows
__device__ float g_n2p[4 * NR];
__device__ int   g_rank[NS];
__device__ int   g_inv[NS];
__device__ int   g_clsS[NS];
__device__ float g_pnum[2 * (size_t)NQ * NC];
__device__ float g_pden[2 * NQ];

// ------------------------- helpers ------------------------------------------
__device__ __forceinline__ uint32_t smem_u32(const void* p) {
    uint32_t a;
    asm("{ .reg .u64 t; cvta.to.shared.u64 t, %1; cvt.u32.u64 %0, t; }" : "=r"(a) : "l"(p));
    return a;
}
#define CP_COMMIT() asm volatile("cp.async.commit_group;" ::: "memory")
#define CP_WAIT1()  asm volatile("cp.async.wait_group 1;" ::: "memory")

__device__ __forceinline__ void ldm4(uint32_t r[4], uint32_t addr) {
    asm volatile("ldmatrix.sync.aligned.m8n8.x4.shared.b16 {%0,%1,%2,%3}, [%4];"
                 : "=r"(r[0]), "=r"(r[1]), "=r"(r[2]), "=r"(r[3]) : "r"(addr));
}
__device__ __forceinline__ void mma16816(float c[4], uint32_t a0, uint32_t a1, uint32_t a2,
                                         uint32_t a3, uint32_t b0, uint32_t b1) {
    asm volatile(
        "mma.sync.aligned.m16n8k16.row.col.f32.f16.f16.f32 "
        "{%0,%1,%2,%3}, {%4,%5,%6,%7}, {%8,%9}, {%0,%1,%2,%3};"
        : "+f"(c[0]), "+f"(c[1]), "+f"(c[2]), "+f"(c[3])
        : "r"(a0), "r"(a1), "r"(a2), "r"(a3), "r"(b0), "r"(b1));
}

// N rows x 64 halfs (128B) global -> smem (stride 144B); 512-thread CTA
template <int ROWS>
__device__ __forceinline__ void loadT(uint32_t sdst, const char* gbase, uint32_t goff,
                                      uint32_t rs, int tid) {
#pragma unroll
    for (int i = 0; i < ROWS / 64; i++) {
        int u = tid + (i << 9), r = u >> 3, j = u & 7;
        asm volatile("cp.async.cg.shared.global [%0], [%1], 16;"
                     :: "r"(sdst + r * 144 + j * 16),
                        "l"(gbase + goff + (uint32_t)r * rs + j * 16) : "memory");
    }
}

// BK=64 chunk, warp tile 32x64 (dist): A tile 128 rows, B tile 256 rows. 16 warps (4x4).
__device__ __forceinline__ void compute_d(uint32_t smA, uint32_t smB, int wm, int wn, int lane,
                                          float c[2][8][4]) {
    uint32_t aRow = smA + (uint32_t)((wm * 32 + (lane & 15)) * 144 + (lane >> 4) * 16);
    uint32_t bRow = smB + (uint32_t)((wn * 64 + (lane >> 4) * 8 + (lane & 7)) * 144
                                     + ((lane >> 3) & 1) * 16);
#pragma unroll
    for (int ks = 0; ks < 4; ks++) {
        uint32_t ko = (uint32_t)ks * 32;
        uint32_t a[2][4], b[4][4];
#pragma unroll
        for (int mi = 0; mi < 2; mi++) ldm4(a[mi], aRow + mi * 2304 + ko);
#pragma unroll
        for (int q = 0; q < 4; q++) ldm4(b[q], bRow + q * 2304 + ko);
#pragma unroll
        for (int mi = 0; mi < 2; mi++)
#pragma unroll
            for (int ni = 0; ni < 8; ni++)
                mma16816(c[mi][ni], a[mi][0], a[mi][1], a[mi][2], a[mi][3],
                         b[ni >> 1][(ni & 1) * 2], b[ni >> 1][(ni & 1) * 2 + 1]);
    }
}

// BK=64 chunk, warp tile 32x32 (enc): A tile 128 rows, B tile 128 rows. 16 warps (4x4).
__device__ __forceinline__ void compute_e(uint32_t smA, uint32_t smB, int wm, int wn, int lane,
                                          float c[2][4][4]) {
    uint32_t aRow = smA + (uint32_t)((wm * 32 + (lane & 15)) * 144 + (lane >> 4) * 16);
    uint32_t bRow = smB + (uint32_t)((wn * 32 + (lane >> 4) * 8 + (lane & 7)) * 144
                                     + ((lane >> 3) & 1) * 16);
#pragma unroll
    for (int ks = 0; ks < 4; ks++) {
        uint32_t ko = (uint32_t)ks * 32;
        uint32_t a[2][4], b[2][4];
#pragma unroll
        for (int mi = 0; mi < 2; mi++) ldm4(a[mi], aRow + mi * 2304 + ko);
#pragma unroll
        for (int q = 0; q < 2; q++) ldm4(b[q], bRow + q * 2304 + ko);
#pragma unroll
        for (int mi = 0; mi < 2; mi++)
#pragma unroll
            for (int ni = 0; ni < 4; ni++)
                mma16816(c[mi][ni], a[mi][0], a[mi][1], a[mi][2], a[mi][3],
                         b[ni >> 1][(ni & 1) * 2], b[ni >> 1][(ni & 1) * 2 + 1]);
    }
}

// ------------------------- smem layouts -------------------------------------
// enc: stage = A(128x144) + B(128x144) = 36864; 3 stages
#define ESTG 36864
#define E_BIAS 110592
#define E_N2   111104
#define SMEM_ENC 111616
// dist: stage = A(128x144=18432) + B(256x144=36864) = 55296; 3 stages
#define DSTG 55296
#define D_SACC 165888              // 128*65 f32 = 33280
#define D_S2   199168              // 2*256 f32
#define D_CLS  201216              // 2*256 int
#define D_Q2   203264              // 128 f32
#define D_LS   203776              // 128 f32
#define SMEM_DIST 204288

// =============================================================================
// Prep: fp16 rounding of X (NR rows) and W^T (EMB rows), zero-padded to KE
// =============================================================================
__global__ void prep_kernel(const float* __restrict__ sup, const float* __restrict__ qry,
                            const float* __restrict__ W) {
    int bid = blockIdx.x;
    if (bid < NR) {
        const float* src = bid < NS ? sup + (size_t)bid * IND : qry + (size_t)(bid - NS) * IND;
        __half* dst = g_X + (size_t)bid * KE;
        for (int c = threadIdx.x; c < IND; c += 128)
            dst[c] = __float2half_rn(src[c]);
        if (threadIdx.x < KE - IND) dst[IND + threadIdx.x] = __ushort_as_half(0);
    } else {
        int n = bid - NR;
        __half* dst = g_W + (size_t)n * KE;
        for (int k = threadIdx.x; k < IND; k += 128)
            dst[k] = __float2half_rn(W[(size_t)k * EMB + n]);
        if (threadIdx.x < KE - IND) dst[IND + threadIdx.x] = __ushort_as_half(0);
    }
}

// =============================================================================
// Class extraction + deterministic stable counting sort (block b = class b).
// =============================================================================
__global__ __launch_bounds__(256) void clsrank_kernel(const float* __restrict__ labels) {
    __shared__ int cl[NS];
    __shared__ int eqs[256], lts[256];
    const int b = blockIdx.x, tid = threadIdx.x;
    for (int idx = tid; idx < NS * NC; idx += 256)
        if (labels[idx] > 0.5f) cl[idx >> 6] = idx & 63;
    __syncthreads();
    int e0 = 0, l0 = 0;
    const int j0 = tid * 16;
#pragma unroll
    for (int e = 0; e < 16; e++) {
        int c = cl[j0 + e];
        e0 += (c == b);
        l0 += (c < b);
    }
    eqs[tid] = e0; lts[tid] = l0;
    __syncthreads();
    for (int off = 1; off < 256; off <<= 1) {
        int ve = (tid >= off) ? eqs[tid - off] : 0;
        int vl = (tid >= off) ? lts[tid - off] : 0;
        __syncthreads();
        eqs[tid] += ve; lts[tid] += vl;
        __syncthreads();
    }
    int r = lts[255] + eqs[tid] - e0;
    for (int e = 0; e < 16; e++) {
        int j = j0 + e;
        if (cl[j] == b) {
            g_rank[j] = r;
            g_inv[r] = j;
            g_clsS[r] = b;
            r++;
        }
    }
}

// =============================================================================
// Encoder: D[128x128] = X * W^T, K=832 (pure fp16).
// 16 warps (4x4), warp tile 32x32, single-barrier 3-stage pipeline, 1 CTA/SM.
// =============================================================================
__global__ __launch_bounds__(512, 1) void enc_kernel(const float* __restrict__ bias) {
    extern __shared__ char sm[];
    uint32_t smb = smem_u32(sm);
    const int tid = threadIdx.x, lane = tid & 31, w = tid >> 5, wm = w >> 2, wn = w & 3;
    const int m0 = blockIdx.x * 128, n0 = blockIdx.y * 128;
    float* biasS = (float*)(sm + E_BIAS);
    float* n2s = (float*)(sm + E_N2);
    if (tid < 128) { biasS[tid] = bias[n0 + tid]; n2s[tid] = 0.f; }

    const char* A = (const char*)g_X + (size_t)m0 * (KE * 2);
    const char* B = (const char*)g_W + (size_t)n0 * (KE * 2);
    const int G = KE / 64;  // 13
    loadT<128>(smb, A, 0, KE * 2, tid);
    loadT<128>(smb + 18432, B, 0, KE * 2, tid); CP_COMMIT();
    loadT<128>(smb + ESTG, A, 128, KE * 2, tid);
    loadT<128>(smb + ESTG + 18432, B, 128, KE * 2, tid); CP_COMMIT();

    float c[2][4][4];
#pragma unroll
    for (int i = 0; i < 2; i++)
#pragma unroll
        for (int j = 0; j < 4; j++)
#pragma unroll
            for (int k = 0; k < 4; k++) c[i][j][k] = 0.f;

    for (int g = 0; g < G; g++) {
        CP_WAIT1(); __syncthreads();
        int s = (g % 3) * ESTG;
        compute_e(smb + s, smb + s + 18432, wm, wn, lane, c);
        if (g + 2 < G) {
            int s2 = ((g + 2) % 3) * ESTG;
            loadT<128>(smb + s2, A, (uint32_t)(g + 2) * 128, KE * 2, tid);
            loadT<128>(smb + s2 + 18432, B, (uint32_t)(g + 2) * 128, KE * 2, tid);
        }
        CP_COMMIT();
    }

    float vsq[4];
#pragma unroll
    for (int i = 0; i < 4; i++) vsq[i] = 0.f;
#pragma unroll
    for (int mi = 0; mi < 2; mi++) {
        int r0 = wm * 32 + mi * 16 + (lane >> 2);
#pragma unroll
        for (int ni = 0; ni < 4; ni++) {
            int cn = wn * 32 + ni * 8 + (lane & 3) * 2;
            float b0 = biasS[cn], b1 = biasS[cn + 1];
            float v0 = c[mi][ni][0] + b0, v1 = c[mi][ni][1] + b1;
            float v2 = c[mi][ni][2] + b0, v3 = c[mi][ni][3] + b1;
            vsq[2 * mi] += v0 * v0 + v1 * v1;
            vsq[2 * mi + 1] += v2 * v2 + v3 * v3;
#pragma unroll
            for (int h = 0; h < 2; h++) {
                float x0 = h ? v2 : v0, x1 = h ? v3 : v1;
                int rg = m0 + r0 + h * 8, col = n0 + cn;
                __half h0 = __float2half_rn(x0), h1 = __float2half_rn(x1);
                uint32_t hp = ((uint32_t)__half_as_ushort(h1) << 16) | __half_as_ushort(h0);
                if (rg < NS) {
                    int sr = g_rank[rg];
                    ((uint32_t*)(g_S + (size_t)sr * 512))[col >> 1] = hp;
                } else {
                    ((uint32_t*)(g_Q + (size_t)(rg - NS) * 512))[col >> 1] = hp;
                }
            }
        }
    }
#pragma unroll
    for (int i = 0; i < 4; i++) {
        float v = vsq[i];
        v += __shfl_xor_sync(~0u, v, 1);
        v += __shfl_xor_sync(~0u, v, 2);
        if ((lane & 3) == 0)
            atomicAdd(&n2s[wm * 32 + (i >> 1) * 16 + (lane >> 2) + (i & 1) * 8], v);
    }
    __syncthreads();
    if (tid < 128) g_n2p[blockIdx.y * NR + m0 + tid] = n2s[tid];
}

__device__ __forceinline__ float pfun(float q2, float s2, float qs) {
    float d2 = fmaxf(q2 + s2 - 2.f * qs, 0.f);
    float d, p;
    asm("sqrt.approx.f32 %0, %1;" : "=f"(d) : "f"(d2));
    asm("ex2.approx.f32 %0, %1;" : "=f"(p) : "f"((32.f - d) * LOG2E));
    return p;
}

// =============================================================================
// Fused distance/softmax/aggregate. CTA: 128 queries x 2048 supports (sorted).
// 8 tiles of 256 supports x 8 K-chunks = 64 iterations. 16 warps, tile 32x64.
// =============================================================================
__global__ __launch_bounds__(512, 1) void dist_kernel() {
    extern __shared__ char sm[];
    uint32_t smb = smem_u32(sm);
    const int tid = threadIdx.x, lane = tid & 31, w = tid >> 5, wm = w >> 2, wn = w & 3;
    const int m0 = blockIdx.x * 128, half = blockIdx.y, s0 = half * 2048;
    float* sacc  = (float*)(sm + D_SACC);
    float* s2s   = (float*)(sm + D_S2);
    int*   clss  = (int*)(sm + D_CLS);
    float* q2s   = (float*)(sm + D_Q2);
    float* lsums = (float*)(sm + D_LS);

    for (int i = tid; i < 128 * 65; i += 512) sacc[i] = 0.f;
    if (tid < 128) {
        int qr = NS + m0 + tid;
        q2s[tid] = g_n2p[qr] + g_n2p[NR + qr] + g_n2p[2 * NR + qr] + g_n2p[3 * NR + qr];
        lsums[tid] = 0.f;
    }
    if (tid < 256) {
        int sc = s0 + tid, o = g_inv[sc];
        s2s[tid] = g_n2p[o] + g_n2p[NR + o] + g_n2p[2 * NR + o] + g_n2p[3 * NR + o];
        clss[tid] = g_clsS[sc];
    }
    const char* A  = (const char*)g_Q + (size_t)m0 * 1024;
    const char* Sb = (const char*)g_S + (size_t)s0 * 1024;

#define LOADG(gg) do { \
        int _s = ((gg) % 3) * DSTG; \
        uint32_t _t = (uint32_t)(gg) >> 3, _kc = (uint32_t)(gg) & 7; \
        loadT<128>(smb + _s, A, _kc * 128, 1024, tid); \
        loadT<256>(smb + _s + 18432, Sb, _t * 262144 + _kc * 128, 1024, tid); \
    } while (0)

    LOADG(0); CP_COMMIT();
    LOADG(1); CP_COMMIT();

    float c[2][8][4];
#pragma unroll
    for (int i = 0; i < 2; i++)
#pragma unroll
        for (int j = 0; j < 8; j++)
#pragma unroll
            for (int k = 0; k < 4; k++) c[i][j][k] = 0.f;
    float lrow[4];
#pragma unroll
    for (int i = 0; i < 4; i++) lrow[i] = 0.f;
    __syncthreads();
    float q2r[4];
#pragma unroll
    for (int i = 0; i < 4; i++)
        q2r[i] = q2s[wm * 32 + (i >> 1) * 16 + (lane >> 2) + (i & 1) * 8];

    const int jb = wn * 64 + (lane & 3) * 2;

    for (int g = 0; g < 64; g++) {
        CP_WAIT1(); __syncthreads();
        int s = (g % 3) * DSTG;
        compute_d(smb + s, smb + s + 18432, wm, wn, lane, c);
        if (g + 2 < 64) LOADG(g + 2);
        CP_COMMIT();
        if ((g & 7) == 7) {
            int t = g >> 3, slot = t & 1;
            const float* s2 = s2s + slot * 256;
            const int* cl = clss + slot * 256;
            const bool fast = (cl[jb] == cl[jb + 57]);
            const int c0 = cl[jb];
#pragma unroll
            for (int mi = 0; mi < 2; mi++) {
#pragma unroll
                for (int h = 0; h < 2; h++) {
                    int r = wm * 32 + mi * 16 + (lane >> 2) + h * 8;
                    if (fast) {
                        float lr = 0.f;
#pragma unroll
                        for (int ni = 0; ni < 8; ni++) {
#pragma unroll
                            for (int e = 0; e < 2; e++) {
                                int j = jb + ni * 8 + e;
                                lr += pfun(q2r[2 * mi + h], s2[j], c[mi][ni][2 * h + e]);
                            }
                        }
                        lrow[2 * mi + h] += lr;
                        atomicAdd(&sacc[r * 65 + c0], lr);
                    } else {
                        float lr = 0.f, acc = 0.f;
                        int cc = -1;
#pragma unroll
                        for (int ni = 0; ni < 8; ni++) {
#pragma unroll
                            for (int e = 0; e < 2; e++) {
                                int j = jb + ni * 8 + e;
                                float pv = pfun(q2r[2 * mi + h], s2[j], c[mi][ni][2 * h + e]);
                                lr += pv;
                                int cj = cl[j];
                                if (cj == cc) {
                                    acc += pv;
                                } else {
                                    if (cc >= 0) atomicAdd(&sacc[r * 65 + cc], acc);
                                    cc = cj; acc = pv;
                                }
                            }
                        }
                        atomicAdd(&sacc[r * 65 + cc], acc);
                        lrow[2 * mi + h] += lr;
                    }
                }
#pragma unroll
                for (int ni = 0; ni < 8; ni++)
#pragma unroll
                    for (int k = 0; k < 4; k++) c[mi][ni][k] = 0.f;
            }
            if (t + 1 < 8 && tid < 256) {
                int sc = s0 + (t + 1) * 256 + tid, o = g_inv[sc];
                s2s[((t + 1) & 1) * 256 + tid] =
                    g_n2p[o] + g_n2p[NR + o] + g_n2p[2 * NR + o] + g_n2p[3 * NR + o];
                clss[((t + 1) & 1) * 256 + tid] = g_clsS[sc];
            }
        }
    }
#pragma unroll
    for (int i = 0; i < 4; i++) {
        float v = lrow[i];
        v += __shfl_xor_sync(~0u, v, 1);
        v += __shfl_xor_sync(~0u, v, 2);
        if ((lane & 3) == 0)
            atomicAdd(&lsums[wm * 32 + (i >> 1) * 16 + (lane >> 2) + (i & 1) * 8], v);
    }
    __syncthreads();
    for (int i = tid; i < 128 * 64; i += 512) {
        int r = i >> 6, cc = i & 63;
        g_pnum[(size_t)half * NQ * NC + (size_t)(m0 + r) * NC + cc] = sacc[r * 65 + cc];
    }
    if (tid < 128) g_pden[half * NQ + m0 + tid] = lsums[tid];
#undef LOADG
}

// =============================================================================
// Finalize
// =============================================================================
__global__ void fin_kernel(float* __restrict__ out) {
    int i = blockIdx.x * blockDim.x + threadIdx.x;
    if (i >= NQ * NC) return;
    int q = i >> 6;
    out[i] = (g_pnum[i] + g_pnum[(size_t)NQ * NC + i]) / (g_pden[q] + g_pden[NQ + q]);
}

// =============================================================================
// Launch: prep(0), clsrank(1), enc(2), dist(3), fin(4)
// =============================================================================
extern "C" void kernel_launch(void* const* d_in, const int* in_sizes, int n_in,
                              void* d_out, int out_size) {
    const float* support = (const float*)d_in[0];
    const float* query   = (const float*)d_in[1];
    const float* labels  = (const float*)d_in[2];
    const float* W       = (const float*)d_in[3];
    const float* b       = (const float*)d_in[4];
    float* out = (float*)d_out;

    cudaFuncSetAttribute(enc_kernel,  cudaFuncAttributeMaxDynamicSharedMemorySize, SMEM_ENC);
    cudaFuncSetAttribute(dist_kernel, cudaFuncAttributeMaxDynamicSharedMemorySize, SMEM_DIST);

    prep_kernel<<<NR + EMB, 128>>>(support, query, W);
    clsrank_kernel<<<NC, 256>>>(labels);
    enc_kernel<<<dim3(NR / 128, EMB / 128), 512, SMEM_ENC>>>(b);
    dist_kernel<<<dim3(NQ / 128, 2), 512, SMEM_DIST>>>();
    fin_kernel<<<(NQ * NC + 255) / 256, 256>>>(out);
}

// round 12
// speedup vs baseline: 3.7778x; 1.0434x over previous
#include <cuda_runtime.h>
#include <cuda_fp16.h>
#include <cstdint>

#define NS 4096
#define NQ 8192
#define NR 12288
#define IND 784
#define EMB 512
#define NC 64
#define KE 832           // 784 padded to 64-multiple (1-term fp16 encoder)
#define LOG2E 1.4426950408889634f

// ------------------------- device scratch -----------------------------------
__device__ __align__(128) __half g_X[(size_t)NR * KE];      // xh
__device__ __align__(128) __half g_W[(size_t)EMB * KE];     // wh (W^T rows)
__device__ __align__(128) __half g_Q[(size_t)NQ * 512];     // qh (1024 B/row)
__device__ __align__(128) __half g_S[(size_t)NS * 512];     // sh, class-sorted rows
__device__ float g_n2p[4 * NR];
__device__ int   g_rank[NS];
__device__ int   g_inv[NS];
__device__ int   g_clsS[NS];
__device__ float g_pnum[2 * (size_t)NQ * NC];
__device__ float g_pden[2 * NQ];

// ------------------------- helpers ------------------------------------------
__device__ __forceinline__ uint32_t smem_u32(const void* p) {
    uint32_t a;
    asm("{ .reg .u64 t; cvta.to.shared.u64 t, %1; cvt.u32.u64 %0, t; }" : "=r"(a) : "l"(p));
    return a;
}
#define CP_COMMIT() asm volatile("cp.async.commit_group;" ::: "memory")
#define CP_WAIT1()  asm volatile("cp.async.wait_group 1;" ::: "memory")

__device__ __forceinline__ void ldm4(uint32_t r[4], uint32_t addr) {
    asm volatile("ldmatrix.sync.aligned.m8n8.x4.shared.b16 {%0,%1,%2,%3}, [%4];"
                 : "=r"(r[0]), "=r"(r[1]), "=r"(r[2]), "=r"(r[3]) : "r"(addr));
}
__device__ __forceinline__ void mma16816(float c[4], uint32_t a0, uint32_t a1, uint32_t a2,
                                         uint32_t a3, uint32_t b0, uint32_t b1) {
    asm volatile(
        "mma.sync.aligned.m16n8k16.row.col.f32.f16.f16.f32 "
        "{%0,%1,%2,%3}, {%4,%5,%6,%7}, {%8,%9}, {%0,%1,%2,%3};"
        : "+f"(c[0]), "+f"(c[1]), "+f"(c[2]), "+f"(c[3])
        : "r"(a0), "r"(a1), "r"(a2), "r"(a3), "r"(b0), "r"(b1));
}

// ROWS x 64 halfs (128B) global -> smem (stride 144B); THREADS-thread CTA
template <int ROWS, int THREADS>
__device__ __forceinline__ void loadT(uint32_t sdst, const char* gbase, uint32_t goff,
                                      uint32_t rs, int tid) {
#pragma unroll
    for (int i = 0; i < ROWS * 8 / THREADS; i++) {
        int u = tid + i * THREADS, r = u >> 3, j = u & 7;
        asm volatile("cp.async.cg.shared.global [%0], [%1], 16;"
                     :: "r"(sdst + r * 144 + j * 16),
                        "l"(gbase + goff + (uint32_t)r * rs + j * 16) : "memory");
    }
}

// BK=64 chunk, warp tile 32x64 (dist): A tile 128 rows, B tile 256 rows. 16 warps (4x4).
__device__ __forceinline__ void compute_d(uint32_t smA, uint32_t smB, int wm, int wn, int lane,
                                          float c[2][8][4]) {
    uint32_t aRow = smA + (uint32_t)((wm * 32 + (lane & 15)) * 144 + (lane >> 4) * 16);
    uint32_t bRow = smB + (uint32_t)((wn * 64 + (lane >> 4) * 8 + (lane & 7)) * 144
                                     + ((lane >> 3) & 1) * 16);
#pragma unroll
    for (int ks = 0; ks < 4; ks++) {
        uint32_t ko = (uint32_t)ks * 32;
        uint32_t a[2][4], b[4][4];
#pragma unroll
        for (int mi = 0; mi < 2; mi++) ldm4(a[mi], aRow + mi * 2304 + ko);
#pragma unroll
        for (int q = 0; q < 4; q++) ldm4(b[q], bRow + q * 2304 + ko);
#pragma unroll
        for (int mi = 0; mi < 2; mi++)
#pragma unroll
            for (int ni = 0; ni < 8; ni++)
                mma16816(c[mi][ni], a[mi][0], a[mi][1], a[mi][2], a[mi][3],
                         b[ni >> 1][(ni & 1) * 2], b[ni >> 1][(ni & 1) * 2 + 1]);
    }
}

// BK=64 chunk, warp tile 64x32 (enc): A tile 128 rows, B tile 128 rows. 8 warps (2x4).
__device__ __forceinline__ void compute_e(uint32_t smA, uint32_t smB, int wm, int wn, int lane,
                                          float c[4][4][4]) {
    uint32_t aRow = smA + (uint32_t)((wm * 64 + (lane & 15)) * 144 + (lane >> 4) * 16);
    uint32_t bRow = smB + (uint32_t)((wn * 32 + (lane >> 4) * 8 + (lane & 7)) * 144
                                     + ((lane >> 3) & 1) * 16);
#pragma unroll
    for (int ks = 0; ks < 4; ks++) {
        uint32_t ko = (uint32_t)ks * 32;
        uint32_t a[4][4], b[2][4];
#pragma unroll
        for (int mi = 0; mi < 4; mi++) ldm4(a[mi], aRow + mi * 2304 + ko);
#pragma unroll
        for (int q = 0; q < 2; q++) ldm4(b[q], bRow + q * 2304 + ko);
#pragma unroll
        for (int mi = 0; mi < 4; mi++)
#pragma unroll
            for (int ni = 0; ni < 4; ni++)
                mma16816(c[mi][ni], a[mi][0], a[mi][1], a[mi][2], a[mi][3],
                         b[ni >> 1][(ni & 1) * 2], b[ni >> 1][(ni & 1) * 2 + 1]);
    }
}

// ------------------------- smem layouts -------------------------------------
// enc: stage = A(128x144) + B(128x144) = 36864; 3 stages; 2 CTAs/SM
#define ESTG 36864
#define E_BIAS 110592
#define E_N2   111104
#define SMEM_ENC 111616
// dist: stage = A(128x144=18432) + B(256x144=36864) = 55296; 3 stages
#define DSTG 55296
#define D_SACC 165888              // 128*65 f32 = 33280
#define D_S2   199168              // 2*256 f32
#define D_CLS  201216              // 2*256 int
#define D_Q2   203264              // 128 f32
#define D_LS   203776              // 128 f32
#define SMEM_DIST 204288

// =============================================================================
// Prep: fp16 rounding of X (NR rows) and W^T (EMB rows), zero-padded to KE
// =============================================================================
__global__ void prep_kernel(const float* __restrict__ sup, const float* __restrict__ qry,
                            const float* __restrict__ W) {
    int bid = blockIdx.x;
    if (bid < NR) {
        const float* src = bid < NS ? sup + (size_t)bid * IND : qry + (size_t)(bid - NS) * IND;
        __half* dst = g_X + (size_t)bid * KE;
        for (int c = threadIdx.x; c < IND; c += 128)
            dst[c] = __float2half_rn(src[c]);
        if (threadIdx.x < KE - IND) dst[IND + threadIdx.x] = __ushort_as_half(0);
    } else {
        int n = bid - NR;
        __half* dst = g_W + (size_t)n * KE;
        for (int k = threadIdx.x; k < IND; k += 128)
            dst[k] = __float2half_rn(W[(size_t)k * EMB + n]);
        if (threadIdx.x < KE - IND) dst[IND + threadIdx.x] = __ushort_as_half(0);
    }
}

// =============================================================================
// Class extraction + deterministic stable counting sort (block b = class b).
// =============================================================================
__global__ __launch_bounds__(256) void clsrank_kernel(const float* __restrict__ labels) {
    __shared__ int cl[NS];
    __shared__ int eqs[256], lts[256];
    const int b = blockIdx.x, tid = threadIdx.x;
    for (int idx = tid; idx < NS * NC; idx += 256)
        if (labels[idx] > 0.5f) cl[idx >> 6] = idx & 63;
    __syncthreads();
    int e0 = 0, l0 = 0;
    const int j0 = tid * 16;
#pragma unroll
    for (int e = 0; e < 16; e++) {
        int c = cl[j0 + e];
        e0 += (c == b);
        l0 += (c < b);
    }
    eqs[tid] = e0; lts[tid] = l0;
    __syncthreads();
    for (int off = 1; off < 256; off <<= 1) {
        int ve = (tid >= off) ? eqs[tid - off] : 0;
        int vl = (tid >= off) ? lts[tid - off] : 0;
        __syncthreads();
        eqs[tid] += ve; lts[tid] += vl;
        __syncthreads();
    }
    int r = lts[255] + eqs[tid] - e0;
    for (int e = 0; e < 16; e++) {
        int j = j0 + e;
        if (cl[j] == b) {
            g_rank[j] = r;
            g_inv[r] = j;
            g_clsS[r] = b;
            r++;
        }
    }
}

// =============================================================================
// Encoder: D[128x128] = X * W^T, K=832 (pure fp16).
// 8 warps (2x4), warp tile 64x32, single-barrier 3-stage pipeline, 2 CTAs/SM.
// =============================================================================
__global__ __launch_bounds__(256, 2) void enc_kernel(const float* __restrict__ bias) {
    extern __shared__ char sm[];
    uint32_t smb = smem_u32(sm);
    const int tid = threadIdx.x, lane = tid & 31, w = tid >> 5, wm = w >> 2, wn = w & 3;
    const int m0 = blockIdx.x * 128, n0 = blockIdx.y * 128;
    float* biasS = (float*)(sm + E_BIAS);
    float* n2s = (float*)(sm + E_N2);
    if (tid < 128) { biasS[tid] = bias[n0 + tid]; n2s[tid] = 0.f; }

    const char* A = (const char*)g_X + (size_t)m0 * (KE * 2);
    const char* B = (const char*)g_W + (size_t)n0 * (KE * 2);
    const int G = KE / 64;  // 13
    loadT<128, 256>(smb, A, 0, KE * 2, tid);
    loadT<128, 256>(smb + 18432, B, 0, KE * 2, tid); CP_COMMIT();
    loadT<128, 256>(smb + ESTG, A, 128, KE * 2, tid);
    loadT<128, 256>(smb + ESTG + 18432, B, 128, KE * 2, tid); CP_COMMIT();

    float c[4][4][4];
#pragma unroll
    for (int i = 0; i < 4; i++)
#pragma unroll
        for (int j = 0; j < 4; j++)
#pragma unroll
            for (int k = 0; k < 4; k++) c[i][j][k] = 0.f;

    for (int g = 0; g < G; g++) {
        CP_WAIT1(); __syncthreads();
        int s = (g % 3) * ESTG;
        compute_e(smb + s, smb + s + 18432, wm, wn, lane, c);
        if (g + 2 < G) {
            int s2 = ((g + 2) % 3) * ESTG;
            loadT<128, 256>(smb + s2, A, (uint32_t)(g + 2) * 128, KE * 2, tid);
            loadT<128, 256>(smb + s2 + 18432, B, (uint32_t)(g + 2) * 128, KE * 2, tid);
        }
        CP_COMMIT();
    }

    float vsq[8];
#pragma unroll
    for (int i = 0; i < 8; i++) vsq[i] = 0.f;
#pragma unroll
    for (int mi = 0; mi < 4; mi++) {
        int r0 = wm * 64 + mi * 16 + (lane >> 2);
#pragma unroll
        for (int ni = 0; ni < 4; ni++) {
            int cn = wn * 32 + ni * 8 + (lane & 3) * 2;
            float b0 = biasS[cn], b1 = biasS[cn + 1];
            float v0 = c[mi][ni][0] + b0, v1 = c[mi][ni][1] + b1;
            float v2 = c[mi][ni][2] + b0, v3 = c[mi][ni][3] + b1;
            vsq[2 * mi] += v0 * v0 + v1 * v1;
            vsq[2 * mi + 1] += v2 * v2 + v3 * v3;
#pragma unroll
            for (int h = 0; h < 2; h++) {
                float x0 = h ? v2 : v0, x1 = h ? v3 : v1;
                int rg = m0 + r0 + h * 8, col = n0 + cn;
                __half h0 = __float2half_rn(x0), h1 = __float2half_rn(x1);
                uint32_t hp = ((uint32_t)__half_as_ushort(h1) << 16) | __half_as_ushort(h0);
                if (rg < NS) {
                    int sr = g_rank[rg];
                    ((uint32_t*)(g_S + (size_t)sr * 512))[col >> 1] = hp;
                } else {
                    ((uint32_t*)(g_Q + (size_t)(rg - NS) * 512))[col >> 1] = hp;
                }
            }
        }
    }
#pragma unroll
    for (int i = 0; i < 8; i++) {
        float v = vsq[i];
        v += __shfl_xor_sync(~0u, v, 1);
        v += __shfl_xor_sync(~0u, v, 2);
        if ((lane & 3) == 0)
            atomicAdd(&n2s[wm * 64 + (i >> 1) * 16 + (lane >> 2) + (i & 1) * 8], v);
    }
    __syncthreads();
    if (tid < 128) g_n2p[blockIdx.y * NR + m0 + tid] = n2s[tid];
}

__device__ __forceinline__ float pfun(float q2, float s2, float qs) {
    float d2 = fmaxf(q2 + s2 - 2.f * qs, 0.f);
    float d, p;
    asm("sqrt.approx.f32 %0, %1;" : "=f"(d) : "f"(d2));
    asm("ex2.approx.f32 %0, %1;" : "=f"(p) : "f"((32.f - d) * LOG2E));
    return p;
}

// =============================================================================
// Fused distance/softmax/aggregate. CTA: 128 queries x 2048 supports (sorted).
// 8 tiles of 256 supports x 8 K-chunks = 64 iterations. 16 warps, tile 32x64.
// =============================================================================
__global__ __launch_bounds__(512, 1) void dist_kernel() {
    extern __shared__ char sm[];
    uint32_t smb = smem_u32(sm);
    const int tid = threadIdx.x, lane = tid & 31, w = tid >> 5, wm = w >> 2, wn = w & 3;
    const int m0 = blockIdx.x * 128, half = blockIdx.y, s0 = half * 2048;
    float* sacc  = (float*)(sm + D_SACC);
    float* s2s   = (float*)(sm + D_S2);
    int*   clss  = (int*)(sm + D_CLS);
    float* q2s   = (float*)(sm + D_Q2);
    float* lsums = (float*)(sm + D_LS);

    for (int i = tid; i < 128 * 65; i += 512) sacc[i] = 0.f;
    if (tid < 128) {
        int qr = NS + m0 + tid;
        q2s[tid] = g_n2p[qr] + g_n2p[NR + qr] + g_n2p[2 * NR + qr] + g_n2p[3 * NR + qr];
        lsums[tid] = 0.f;
    }
    if (tid < 256) {
        int sc = s0 + tid, o = g_inv[sc];
        s2s[tid] = g_n2p[o] + g_n2p[NR + o] + g_n2p[2 * NR + o] + g_n2p[3 * NR + o];
        clss[tid] = g_clsS[sc];
    }
    const char* A  = (const char*)g_Q + (size_t)m0 * 1024;
    const char* Sb = (const char*)g_S + (size_t)s0 * 1024;

#define LOADG(gg) do { \
        int _s = ((gg) % 3) * DSTG; \
        uint32_t _t = (uint32_t)(gg) >> 3, _kc = (uint32_t)(gg) & 7; \
        loadT<128, 512>(smb + _s, A, _kc * 128, 1024, tid); \
        loadT<256, 512>(smb + _s + 18432, Sb, _t * 262144 + _kc * 128, 1024, tid); \
    } while (0)

    LOADG(0); CP_COMMIT();
    LOADG(1); CP_COMMIT();

    float c[2][8][4];
#pragma unroll
    for (int i = 0; i < 2; i++)
#pragma unroll
        for (int j = 0; j < 8; j++)
#pragma unroll
            for (int k = 0; k < 4; k++) c[i][j][k] = 0.f;
    float lrow[4];
#pragma unroll
    for (int i = 0; i < 4; i++) lrow[i] = 0.f;
    __syncthreads();
    float q2r[4];
#pragma unroll
    for (int i = 0; i < 4; i++)
        q2r[i] = q2s[wm * 32 + (i >> 1) * 16 + (lane >> 2) + (i & 1) * 8];

    const int jb = wn * 64 + (lane & 3) * 2;

    for (int g = 0; g < 64; g++) {
        CP_WAIT1(); __syncthreads();
        int s = (g % 3) * DSTG;
        compute_d(smb + s, smb + s + 18432, wm, wn, lane, c);
        if (g + 2 < 64) LOADG(g + 2);
        CP_COMMIT();
        if ((g & 7) == 7) {
            int t = g >> 3, slot = t & 1;
            const float* s2 = s2s + slot * 256;
            const int* cl = clss + slot * 256;
            const bool fast = (cl[jb] == cl[jb + 57]);
            const int c0 = cl[jb];
#pragma unroll
            for (int mi = 0; mi < 2; mi++) {
#pragma unroll
                for (int h = 0; h < 2; h++) {
                    int r = wm * 32 + mi * 16 + (lane >> 2) + h * 8;
                    if (fast) {
                        float lr = 0.f;
#pragma unroll
                        for (int ni = 0; ni < 8; ni++) {
#pragma unroll
                            for (int e = 0; e < 2; e++) {
                                int j = jb + ni * 8 + e;
                                lr += pfun(q2r[2 * mi + h], s2[j], c[mi][ni][2 * h + e]);
                            }
                        }
                        lrow[2 * mi + h] += lr;
                        atomicAdd(&sacc[r * 65 + c0], lr);
                    } else {
                        float lr = 0.f, acc = 0.f;
                        int cc = -1;
#pragma unroll
                        for (int ni = 0; ni < 8; ni++) {
#pragma unroll
                            for (int e = 0; e < 2; e++) {
                                int j = jb + ni * 8 + e;
                                float pv = pfun(q2r[2 * mi + h], s2[j], c[mi][ni][2 * h + e]);
                                lr += pv;
                                int cj = cl[j];
                                if (cj == cc) {
                                    acc += pv;
                                } else {
                                    if (cc >= 0) atomicAdd(&sacc[r * 65 + cc], acc);
                                    cc = cj; acc = pv;
                                }
                            }
                        }
                        atomicAdd(&sacc[r * 65 + cc], acc);
                        lrow[2 * mi + h] += lr;
                    }
                }
#pragma unroll
                for (int ni = 0; ni < 8; ni++)
#pragma unroll
                    for (int k = 0; k < 4; k++) c[mi][ni][k] = 0.f;
            }
            if (t + 1 < 8 && tid < 256) {
                int sc = s0 + (t + 1) * 256 + tid, o = g_inv[sc];
                s2s[((t + 1) & 1) * 256 + tid] =
                    g_n2p[o] + g_n2p[NR + o] + g_n2p[2 * NR + o] + g_n2p[3 * NR + o];
                clss[((t + 1) & 1) * 256 + tid] = g_clsS[sc];
            }
        }
    }
#pragma unroll
    for (int i = 0; i < 4; i++) {
        float v = lrow[i];
        v += __shfl_xor_sync(~0u, v, 1);
        v += __shfl_xor_sync(~0u, v, 2);
        if ((lane & 3) == 0)
            atomicAdd(&lsums[wm * 32 + (i >> 1) * 16 + (lane >> 2) + (i & 1) * 8], v);
    }
    __syncthreads();
    for (int i = tid; i < 128 * 64; i += 512) {
        int r = i >> 6, cc = i & 63;
        g_pnum[(size_t)half * NQ * NC + (size_t)(m0 + r) * NC + cc] = sacc[r * 65 + cc];
    }
    if (tid < 128) g_pden[half * NQ + m0 + tid] = lsums[tid];
#undef LOADG
}

// =============================================================================
// Finalize
// =============================================================================
__global__ void fin_kernel(float* __restrict__ out) {
    int i = blockIdx.x * blockDim.x + threadIdx.x;
    if (i >= NQ * NC) return;
    int q = i >> 6;
    out[i] = (g_pnum[i] + g_pnum[(size_t)NQ * NC + i]) / (g_pden[q] + g_pden[NQ + q]);
}

// =============================================================================
// Launch: prep(0), clsrank(1), enc(2), dist(3), fin(4)
// =============================================================================
extern "C" void kernel_launch(void* const* d_in, const int* in_sizes, int n_in,
                              void* d_out, int out_size) {
    const float* support = (const float*)d_in[0];
    const float* query   = (const float*)d_in[1];
    const float* labels  = (const float*)d_in[2];
    const float* W       = (const float*)d_in[3];
    const float* b       = (const float*)d_in[4];
    float* out = (float*)d_out;

    cudaFuncSetAttribute(enc_kernel,  cudaFuncAttributeMaxDynamicSharedMemorySize, SMEM_ENC);
    cudaFuncSetAttribute(dist_kernel, cudaFuncAttributeMaxDynamicSharedMemorySize, SMEM_DIST);

    prep_kernel<<<NR + EMB, 128>>>(support, query, W);
    clsrank_kernel<<<NC, 256>>>(labels);
    enc_kernel<<<dim3(NR / 128, EMB / 128), 256, SMEM_ENC>>>(b);
    dist_kernel<<<dim3(NQ / 128, 2), 512, SMEM_DIST>>>();
    fin_kernel<<<(NQ * NC + 255) / 256, 256>>>(out);
}

// round 13
// speedup vs baseline: 5.0332x; 1.3323x over previous
#include <cuda_runtime.h>
#include <cuda_fp16.h>
#include <cstdint>

#define NS 4096
#define NQ 8192
#define NR 12288
#define IND 784
#define EMB 512
#define NC 64
#define KE 832           // 784 padded to 64-multiple (1-term fp16 encoder)
#define LOG2E 1.4426950408889634f

// ------------------------- device scratch -----------------------------------
__device__ __align__(128) __half g_X[(size_t)NR * KE];      // xh
__device__ __align__(128) __half g_W[(size_t)EMB * KE];     // wh (W^T rows)
__device__ __align__(128) __half g_Q[(size_t)NQ * 512];     // qh (1024 B/row)
__device__ __align__(128) __half g_S[(size_t)NS * 512];     // sh, class-sorted rows
__device__ float g_n2p[4 * NR];
__device__ int   g_cls[NS];      // original idx -> class
__device__ int   g_rank[NS];     // original idx -> sorted pos
__device__ int   g_inv[NS];      // sorted pos -> original idx
__device__ int   g_clsS[NS];     // class at sorted pos
__device__ float g_pnum[2 * (size_t)NQ * NC];
__device__ float g_pden[2 * NQ];

// ------------------------- helpers ------------------------------------------
__device__ __forceinline__ uint32_t smem_u32(const void* p) {
    uint32_t a;
    asm("{ .reg .u64 t; cvta.to.shared.u64 t, %1; cvt.u32.u64 %0, t; }" : "=r"(a) : "l"(p));
    return a;
}
#define CP_COMMIT() asm volatile("cp.async.commit_group;" ::: "memory")
#define CP_WAIT1()  asm volatile("cp.async.wait_group 1;" ::: "memory")

__device__ __forceinline__ void ldm4(uint32_t r[4], uint32_t addr) {
    asm volatile("ldmatrix.sync.aligned.m8n8.x4.shared.b16 {%0,%1,%2,%3}, [%4];"
                 : "=r"(r[0]), "=r"(r[1]), "=r"(r[2]), "=r"(r[3]) : "r"(addr));
}
__device__ __forceinline__ void mma16816(float c[4], uint32_t a0, uint32_t a1, uint32_t a2,
                                         uint32_t a3, uint32_t b0, uint32_t b1) {
    asm volatile(
        "mma.sync.aligned.m16n8k16.row.col.f32.f16.f16.f32 "
        "{%0,%1,%2,%3}, {%4,%5,%6,%7}, {%8,%9}, {%0,%1,%2,%3};"
        : "+f"(c[0]), "+f"(c[1]), "+f"(c[2]), "+f"(c[3])
        : "r"(a0), "r"(a1), "r"(a2), "r"(a3), "r"(b0), "r"(b1));
}

// ROWS x 64 halfs (128B) global -> smem (stride 144B); THREADS-thread CTA
template <int ROWS, int THREADS>
__device__ __forceinline__ void loadT(uint32_t sdst, const char* gbase, uint32_t goff,
                                      uint32_t rs, int tid) {
#pragma unroll
    for (int i = 0; i < ROWS * 8 / THREADS; i++) {
        int u = tid + i * THREADS, r = u >> 3, j = u & 7;
        asm volatile("cp.async.cg.shared.global [%0], [%1], 16;"
                     :: "r"(sdst + r * 144 + j * 16),
                        "l"(gbase + goff + (uint32_t)r * rs + j * 16) : "memory");
    }
}

// BK=64 chunk, warp tile 32x64 (dist): A tile 128 rows, B tile 256 rows. 16 warps (4x4).
__device__ __forceinline__ void compute_d(uint32_t smA, uint32_t smB, int wm, int wn, int lane,
                                          float c[2][8][4]) {
    uint32_t aRow = smA + (uint32_t)((wm * 32 + (lane & 15)) * 144 + (lane >> 4) * 16);
    uint32_t bRow = smB + (uint32_t)((wn * 64 + (lane >> 4) * 8 + (lane & 7)) * 144
                                     + ((lane >> 3) & 1) * 16);
#pragma unroll
    for (int ks = 0; ks < 4; ks++) {
        uint32_t ko = (uint32_t)ks * 32;
        uint32_t a[2][4], b[4][4];
#pragma unroll
        for (int mi = 0; mi < 2; mi++) ldm4(a[mi], aRow + mi * 2304 + ko);
#pragma unroll
        for (int q = 0; q < 4; q++) ldm4(b[q], bRow + q * 2304 + ko);
#pragma unroll
        for (int mi = 0; mi < 2; mi++)
#pragma unroll
            for (int ni = 0; ni < 8; ni++)
                mma16816(c[mi][ni], a[mi][0], a[mi][1], a[mi][2], a[mi][3],
                         b[ni >> 1][(ni & 1) * 2], b[ni >> 1][(ni & 1) * 2 + 1]);
    }
}

// BK=64 chunk, warp tile 64x32 (enc): A tile 128 rows, B tile 128 rows. 8 warps (2x4).
__device__ __forceinline__ void compute_e(uint32_t smA, uint32_t smB, int wm, int wn, int lane,
                                          float c[4][4][4]) {
    uint32_t aRow = smA + (uint32_t)((wm * 64 + (lane & 15)) * 144 + (lane >> 4) * 16);
    uint32_t bRow = smB + (uint32_t)((wn * 32 + (lane >> 4) * 8 + (lane & 7)) * 144
                                     + ((lane >> 3) & 1) * 16);
#pragma unroll
    for (int ks = 0; ks < 4; ks++) {
        uint32_t ko = (uint32_t)ks * 32;
        uint32_t a[4][4], b[2][4];
#pragma unroll
        for (int mi = 0; mi < 4; mi++) ldm4(a[mi], aRow + mi * 2304 + ko);
#pragma unroll
        for (int q = 0; q < 2; q++) ldm4(b[q], bRow + q * 2304 + ko);
#pragma unroll
        for (int mi = 0; mi < 4; mi++)
#pragma unroll
            for (int ni = 0; ni < 4; ni++)
                mma16816(c[mi][ni], a[mi][0], a[mi][1], a[mi][2], a[mi][3],
                         b[ni >> 1][(ni & 1) * 2], b[ni >> 1][(ni & 1) * 2 + 1]);
    }
}

// ------------------------- smem layouts -------------------------------------
// enc: stage = A(128x144) + B(128x144) = 36864; 3 stages; 2 CTAs/SM
#define ESTG 36864
#define E_BIAS 110592
#define E_N2   111104
#define SMEM_ENC 111616
// dist: stage = A(128x144=18432) + B(256x144=36864) = 55296; 3 stages
#define DSTG 55296
#define D_SACC 165888              // 128*65 f32 = 33280
#define D_S2   199168              // 2*256 f32
#define D_CLS  201216              // 2*256 int
#define D_Q2   203264              // 128 f32
#define D_LS   203776              // 128 f32
#define SMEM_DIST 204288

// =============================================================================
// Prep: fp16 rounding of X (NR rows), W^T (EMB rows), AND class extraction
// (last 32 blocks: one support row per thread, labels read exactly once).
// =============================================================================
__global__ void prep_kernel(const float* __restrict__ sup, const float* __restrict__ qry,
                            const float* __restrict__ W,
                            const float* __restrict__ labels) {
    int bid = blockIdx.x;
    if (bid < NR) {
        const float* src = bid < NS ? sup + (size_t)bid * IND : qry + (size_t)(bid - NS) * IND;
        __half* dst = g_X + (size_t)bid * KE;
        for (int c = threadIdx.x; c < IND; c += 128)
            dst[c] = __float2half_rn(src[c]);
        if (threadIdx.x < KE - IND) dst[IND + threadIdx.x] = __ushort_as_half(0);
    } else if (bid < NR + EMB) {
        int n = bid - NR;
        __half* dst = g_W + (size_t)n * KE;
        for (int k = threadIdx.x; k < IND; k += 128)
            dst[k] = __float2half_rn(W[(size_t)k * EMB + n]);
        if (threadIdx.x < KE - IND) dst[IND + threadIdx.x] = __ushort_as_half(0);
    } else {
        int row = (bid - NR - EMB) * 128 + threadIdx.x;   // 32 blocks x 128 = 4096
        const float* lr = labels + (size_t)row * NC;
        int c = 0;
#pragma unroll
        for (int j = 0; j < NC; j++)
            if (lr[j] > 0.5f) c = j;
        g_cls[row] = c;
    }
}

// =============================================================================
// Deterministic stable counting sort from g_cls (16 KB, L2-resident).
// Block b handles class b: rank[j] = #{cls<b} + #{j'<j : cls_j'==b}.
// =============================================================================
__global__ __launch_bounds__(256) void rank_kernel() {
    __shared__ int cl[NS];
    __shared__ int eqs[256], lts[256];
    const int b = blockIdx.x, tid = threadIdx.x;
    for (int idx = tid; idx < NS; idx += 256) cl[idx] = g_cls[idx];
    __syncthreads();
    int e0 = 0, l0 = 0;
    const int j0 = tid * 16;
#pragma unroll
    for (int e = 0; e < 16; e++) {
        int c = cl[j0 + e];
        e0 += (c == b);
        l0 += (c < b);
    }
    eqs[tid] = e0; lts[tid] = l0;
    __syncthreads();
    for (int off = 1; off < 256; off <<= 1) {
        int ve = (tid >= off) ? eqs[tid - off] : 0;
        int vl = (tid >= off) ? lts[tid - off] : 0;
        __syncthreads();
        eqs[tid] += ve; lts[tid] += vl;
        __syncthreads();
    }
    int r = lts[255] + eqs[tid] - e0;
    for (int e = 0; e < 16; e++) {
        int j = j0 + e;
        if (cl[j] == b) {
            g_rank[j] = r;
            g_inv[r] = j;
            g_clsS[r] = b;
            r++;
        }
    }
}

// =============================================================================
// Encoder: D[128x128] = X * W^T, K=832 (pure fp16).
// 8 warps (2x4), warp tile 64x32, single-barrier 3-stage pipeline, 2 CTAs/SM.
// =============================================================================
__global__ __launch_bounds__(256, 2) void enc_kernel(const float* __restrict__ bias) {
    extern __shared__ char sm[];
    uint32_t smb = smem_u32(sm);
    const int tid = threadIdx.x, lane = tid & 31, w = tid >> 5, wm = w >> 2, wn = w & 3;
    const int m0 = blockIdx.x * 128, n0 = blockIdx.y * 128;
    float* biasS = (float*)(sm + E_BIAS);
    float* n2s = (float*)(sm + E_N2);
    if (tid < 128) { biasS[tid] = bias[n0 + tid]; n2s[tid] = 0.f; }

    const char* A = (const char*)g_X + (size_t)m0 * (KE * 2);
    const char* B = (const char*)g_W + (size_t)n0 * (KE * 2);
    const int G = KE / 64;  // 13
    loadT<128, 256>(smb, A, 0, KE * 2, tid);
    loadT<128, 256>(smb + 18432, B, 0, KE * 2, tid); CP_COMMIT();
    loadT<128, 256>(smb + ESTG, A, 128, KE * 2, tid);
    loadT<128, 256>(smb + ESTG + 18432, B, 128, KE * 2, tid); CP_COMMIT();

    float c[4][4][4];
#pragma unroll
    for (int i = 0; i < 4; i++)
#pragma unroll
        for (int j = 0; j < 4; j++)
#pragma unroll
            for (int k = 0; k < 4; k++) c[i][j][k] = 0.f;

    for (int g = 0; g < G; g++) {
        CP_WAIT1(); __syncthreads();
        int s = (g % 3) * ESTG;
        compute_e(smb + s, smb + s + 18432, wm, wn, lane, c);
        if (g + 2 < G) {
            int s2 = ((g + 2) % 3) * ESTG;
            loadT<128, 256>(smb + s2, A, (uint32_t)(g + 2) * 128, KE * 2, tid);
            loadT<128, 256>(smb + s2 + 18432, B, (uint32_t)(g + 2) * 128, KE * 2, tid);
        }
        CP_COMMIT();
    }

    float vsq[8];
#pragma unroll
    for (int i = 0; i < 8; i++) vsq[i] = 0.f;
#pragma unroll
    for (int mi = 0; mi < 4; mi++) {
        int r0 = wm * 64 + mi * 16 + (lane >> 2);
#pragma unroll
        for (int ni = 0; ni < 4; ni++) {
            int cn = wn * 32 + ni * 8 + (lane & 3) * 2;
            float b0 = biasS[cn], b1 = biasS[cn + 1];
            float v0 = c[mi][ni][0] + b0, v1 = c[mi][ni][1] + b1;
            float v2 = c[mi][ni][2] + b0, v3 = c[mi][ni][3] + b1;
            vsq[2 * mi] += v0 * v0 + v1 * v1;
            vsq[2 * mi + 1] += v2 * v2 + v3 * v3;
#pragma unroll
            for (int h = 0; h < 2; h++) {
                float x0 = h ? v2 : v0, x1 = h ? v3 : v1;
                int rg = m0 + r0 + h * 8, col = n0 + cn;
                __half h0 = __float2half_rn(x0), h1 = __float2half_rn(x1);
                uint32_t hp = ((uint32_t)__half_as_ushort(h1) << 16) | __half_as_ushort(h0);
                if (rg < NS) {
                    int sr = g_rank[rg];
                    ((uint32_t*)(g_S + (size_t)sr * 512))[col >> 1] = hp;
                } else {
                    ((uint32_t*)(g_Q + (size_t)(rg - NS) * 512))[col >> 1] = hp;
                }
            }
        }
    }
#pragma unroll
    for (int i = 0; i < 8; i++) {
        float v = vsq[i];
        v += __shfl_xor_sync(~0u, v, 1);
        v += __shfl_xor_sync(~0u, v, 2);
        if ((lane & 3) == 0)
            atomicAdd(&n2s[wm * 64 + (i >> 1) * 16 + (lane >> 2) + (i & 1) * 8], v);
    }
    __syncthreads();
    if (tid < 128) g_n2p[blockIdx.y * NR + m0 + tid] = n2s[tid];
}

__device__ __forceinline__ float pfun(float q2, float s2, float qs) {
    float d2 = fmaxf(q2 + s2 - 2.f * qs, 0.f);
    float d, p;
    asm("sqrt.approx.f32 %0, %1;" : "=f"(d) : "f"(d2));
    asm("ex2.approx.f32 %0, %1;" : "=f"(p) : "f"((32.f - d) * LOG2E));
    return p;
}

// =============================================================================
// Fused distance/softmax/aggregate. CTA: 128 queries x 2048 supports (sorted).
// 8 tiles of 256 supports x 8 K-chunks = 64 iterations. 16 warps, tile 32x64.
// =============================================================================
__global__ __launch_bounds__(512, 1) void dist_kernel() {
    extern __shared__ char sm[];
    uint32_t smb = smem_u32(sm);
    const int tid = threadIdx.x, lane = tid & 31, w = tid >> 5, wm = w >> 2, wn = w & 3;
    const int m0 = blockIdx.x * 128, half = blockIdx.y, s0 = half * 2048;
    float* sacc  = (float*)(sm + D_SACC);
    float* s2s   = (float*)(sm + D_S2);
    int*   clss  = (int*)(sm + D_CLS);
    float* q2s   = (float*)(sm + D_Q2);
    float* lsums = (float*)(sm + D_LS);

    for (int i = tid; i < 128 * 65; i += 512) sacc[i] = 0.f;
    if (tid < 128) {
        int qr = NS + m0 + tid;
        q2s[tid] = g_n2p[qr] + g_n2p[NR + qr] + g_n2p[2 * NR + qr] + g_n2p[3 * NR + qr];
        lsums[tid] = 0.f;
    }
    if (tid < 256) {
        int sc = s0 + tid, o = g_inv[sc];
        s2s[tid] = g_n2p[o] + g_n2p[NR + o] + g_n2p[2 * NR + o] + g_n2p[3 * NR + o];
        clss[tid] = g_clsS[sc];
    }
    const char* A  = (const char*)g_Q + (size_t)m0 * 1024;
    const char* Sb = (const char*)g_S + (size_t)s0 * 1024;

#define LOADG(gg) do { \
        int _s = ((gg) % 3) * DSTG; \
        uint32_t _t = (uint32_t)(gg) >> 3, _kc = (uint32_t)(gg) & 7; \
        loadT<128, 512>(smb + _s, A, _kc * 128, 1024, tid); \
        loadT<256, 512>(smb + _s + 18432, Sb, _t * 262144 + _kc * 128, 1024, tid); \
    } while (0)

    LOADG(0); CP_COMMIT();
    LOADG(1); CP_COMMIT();

    float c[2][8][4];
#pragma unroll
    for (int i = 0; i < 2; i++)
#pragma unroll
        for (int j = 0; j < 8; j++)
#pragma unroll
            for (int k = 0; k < 4; k++) c[i][j][k] = 0.f;
    float lrow[4];
#pragma unroll
    for (int i = 0; i < 4; i++) lrow[i] = 0.f;
    __syncthreads();
    float q2r[4];
#pragma unroll
    for (int i = 0; i < 4; i++)
        q2r[i] = q2s[wm * 32 + (i >> 1) * 16 + (lane >> 2) + (i & 1) * 8];

    const int jb = wn * 64 + (lane & 3) * 2;

    for (int g = 0; g < 64; g++) {
        CP_WAIT1(); __syncthreads();
        int s = (g % 3) * DSTG;
        compute_d(smb + s, smb + s + 18432, wm, wn, lane, c);
        if (g + 2 < 64) LOADG(g + 2);
        CP_COMMIT();
        if ((g & 7) == 7) {
            int t = g >> 3, slot = t & 1;
            const float* s2 = s2s + slot * 256;
            const int* cl = clss + slot * 256;
            const bool fast = (cl[jb] == cl[jb + 57]);
            const int c0 = cl[jb];
#pragma unroll
            for (int mi = 0; mi < 2; mi++) {
#pragma unroll
                for (int h = 0; h < 2; h++) {
                    int r = wm * 32 + mi * 16 + (lane >> 2) + h * 8;
                    if (fast) {
                        float lr = 0.f;
#pragma unroll
                        for (int ni = 0; ni < 8; ni++) {
#pragma unroll
                            for (int e = 0; e < 2; e++) {
                                int j = jb + ni * 8 + e;
                                lr += pfun(q2r[2 * mi + h], s2[j], c[mi][ni][2 * h + e]);
                            }
                        }
                        lrow[2 * mi + h] += lr;
                        atomicAdd(&sacc[r * 65 + c0], lr);
                    } else {
                        float lr = 0.f, acc = 0.f;
                        int cc = -1;
#pragma unroll
                        for (int ni = 0; ni < 8; ni++) {
#pragma unroll
                            for (int e = 0; e < 2; e++) {
                                int j = jb + ni * 8 + e;
                                float pv = pfun(q2r[2 * mi + h], s2[j], c[mi][ni][2 * h + e]);
                                lr += pv;
                                int cj = cl[j];
                                if (cj == cc) {
                                    acc += pv;
                                } else {
                                    if (cc >= 0) atomicAdd(&sacc[r * 65 + cc], acc);
                                    cc = cj; acc = pv;
                                }
                            }
                        }
                        atomicAdd(&sacc[r * 65 + cc], acc);
                        lrow[2 * mi + h] += lr;
                    }
                }
#pragma unroll
                for (int ni = 0; ni < 8; ni++)
#pragma unroll
                    for (int k = 0; k < 4; k++) c[mi][ni][k] = 0.f;
            }
            if (t + 1 < 8 && tid < 256) {
                int sc = s0 + (t + 1) * 256 + tid, o = g_inv[sc];
                s2s[((t + 1) & 1) * 256 + tid] =
                    g_n2p[o] + g_n2p[NR + o] + g_n2p[2 * NR + o] + g_n2p[3 * NR + o];
                clss[((t + 1) & 1) * 256 + tid] = g_clsS[sc];
            }
        }
    }
#pragma unroll
    for (int i = 0; i < 4; i++) {
        float v = lrow[i];
        v += __shfl_xor_sync(~0u, v, 1);
        v += __shfl_xor_sync(~0u, v, 2);
        if ((lane & 3) == 0)
            atomicAdd(&lsums[wm * 32 + (i >> 1) * 16 + (lane >> 2) + (i & 1) * 8], v);
    }
    __syncthreads();
    for (int i = tid; i < 128 * 64; i += 512) {
        int r = i >> 6, cc = i & 63;
        g_pnum[(size_t)half * NQ * NC + (size_t)(m0 + r) * NC + cc] = sacc[r * 65 + cc];
    }
    if (tid < 128) g_pden[half * NQ + m0 + tid] = lsums[tid];
#undef LOADG
}

// =============================================================================
// Finalize
// =============================================================================
__global__ void fin_kernel(float* __restrict__ out) {
    int i = blockIdx.x * blockDim.x + threadIdx.x;
    if (i >= NQ * NC) return;
    int q = i >> 6;
    out[i] = (g_pnum[i] + g_pnum[(size_t)NQ * NC + i]) / (g_pden[q] + g_pden[NQ + q]);
}

// =============================================================================
// Launch: prep(0), rank(1), enc(2), dist(3), fin(4)
// =============================================================================
extern "C" void kernel_launch(void* const* d_in, const int* in_sizes, int n_in,
                              void* d_out, int out_size) {
    const float* support = (const float*)d_in[0];
    const float* query   = (const float*)d_in[1];
    const float* labels  = (const float*)d_in[2];
    const float* W       = (const float*)d_in[3];
    const float* b       = (const float*)d_in[4];
    float* out = (float*)d_out;

    cudaFuncSetAttribute(enc_kernel,  cudaFuncAttributeMaxDynamicSharedMemorySize, SMEM_ENC);
    cudaFuncSetAttribute(dist_kernel, cudaFuncAttributeMaxDynamicSharedMemorySize, SMEM_DIST);

    prep_kernel<<<NR + EMB + 32, 128>>>(support, query, W, labels);
    rank_kernel<<<NC, 256>>>();
    enc_kernel<<<dim3(NR / 128, EMB / 128), 256, SMEM_ENC>>>(b);
    dist_kernel<<<dim3(NQ / 128, 2), 512, SMEM_DIST>>>();
    fin_kernel<<<(NQ * NC + 255) / 256, 256>>>(out);
}